// round 2
// baseline (speedup 1.0000x reference)
#include <cuda_runtime.h>
#include <math.h>

#define B_  32
#define N_  512
#define F_  512
#define H_  8
#define DL_ 64
#define DA_ 64
#define NB_ 128
#define G_  2048   // 2*H*DL + 2*H*DA
#define NP1 513    // N+1

// ---------------- scratch (static device globals; allocation-free) -------------
__device__ float g_normed[(size_t)B_ * N_ * F_];     // 33.5 MB
__device__ float g_g[(size_t)B_ * N_ * G_];          // 134 MB
__device__ float g_attn[(size_t)B_ * N_ * H_ * DL_]; // 33.5 MB
__device__ float g_oin[(size_t)B_ * N_ * H_ * DL_];  // 33.5 MB
__device__ int   g_ts32[B_ * NP1];

// ---------------- timestamp canonicalization ----------------------------------
// Reference declares unix_ts as int64 but JAX (x64 disabled) downcasts to int32.
// Handle both layouts: int64 little-endian has zero high words at odd int32
// indices (values < 1e6); sorted positive int32 data cannot have 8 zero odd
// entries. Deterministic per input.
__global__ void ts_fix_kernel(const int* __restrict__ tsraw)
{
    __shared__ int is64;
    if (threadIdx.x == 0) {
        int z = 0;
        #pragma unroll
        for (int i = 1; i < 16; i += 2) z |= tsraw[i];
        is64 = (z == 0) ? 1 : 0;
    }
    __syncthreads();
    int i = blockIdx.x * blockDim.x + threadIdx.x;
    if (i < B_ * NP1) g_ts32[i] = is64 ? tsraw[2 * i] : tsraw[i];
}

// ---------------- LayerNorm over F=512, one block (256 thr) per row ------------
__global__ void ln1_kernel(const float* __restrict__ x,
                           const float* __restrict__ tl)
{
    int row = blockIdx.x;
    int tid = threadIdx.x;
    const float* xr = x + (size_t)row * F_;
    float v0 = xr[tid], v1 = xr[tid + 256];
    float s = v0 + v1, sq = v0 * v0 + v1 * v1;
    #pragma unroll
    for (int o = 16; o; o >>= 1) {
        s  += __shfl_down_sync(0xffffffffu, s,  o);
        sq += __shfl_down_sync(0xffffffffu, sq, o);
    }
    __shared__ float red[16];
    __shared__ float mean_s, rstd_s;
    int w = tid >> 5, l = tid & 31;
    if (l == 0) { red[w] = s; red[w + 8] = sq; }
    __syncthreads();
    if (tid == 0) {
        float ts = 0.f, tq = 0.f;
        #pragma unroll
        for (int i = 0; i < 8; i++) { ts += red[i]; tq += red[i + 8]; }
        float m = ts * (1.0f / F_);
        float var = tq * (1.0f / F_) - m * m;
        mean_s = m;
        rstd_s = 1.0f / sqrtf(var + 1e-6f);
    }
    __syncthreads();
    float t = tl[row];
    float m = mean_s, rs = rstd_s;
    g_normed[(size_t)row * F_ + tid]       = (v0 - m) * rs * t;
    g_normed[(size_t)row * F_ + tid + 256] = (v1 - m) * rs * t;
}

// o_input = u * LN(attn_out) * tl
__global__ void ln2_kernel(const float* __restrict__ tl)
{
    int row = blockIdx.x;
    int tid = threadIdx.x;
    const float* ar = g_attn + (size_t)row * 512;
    float v0 = ar[tid], v1 = ar[tid + 256];
    float s = v0 + v1, sq = v0 * v0 + v1 * v1;
    #pragma unroll
    for (int o = 16; o; o >>= 1) {
        s  += __shfl_down_sync(0xffffffffu, s,  o);
        sq += __shfl_down_sync(0xffffffffu, sq, o);
    }
    __shared__ float red[16];
    __shared__ float mean_s, rstd_s;
    int w = tid >> 5, l = tid & 31;
    if (l == 0) { red[w] = s; red[w + 8] = sq; }
    __syncthreads();
    if (tid == 0) {
        float ts = 0.f, tq = 0.f;
        #pragma unroll
        for (int i = 0; i < 8; i++) { ts += red[i]; tq += red[i + 8]; }
        float m = ts * (1.0f / 512.0f);
        float var = tq * (1.0f / 512.0f) - m * m;
        mean_s = m;
        rstd_s = 1.0f / sqrtf(var + 1e-6f);
    }
    __syncthreads();
    float t = tl[row];
    float m = mean_s, rs = rstd_s;
    float u0 = g_g[(size_t)row * G_ + tid];
    float u1 = g_g[(size_t)row * G_ + tid + 256];
    g_oin[(size_t)row * 512 + tid]       = u0 * (v0 - m) * rs * t;
    g_oin[(size_t)row * 512 + tid + 256] = u1 * (v1 - m) * rs * t;
}

// ---------------- SGEMM 128x128x8, 256 threads, 8x8 regs ----------------------
// MODE 1: C = silu(g_normed @ Bw) * tl[row]   (NC = 2048, C = g_g)
// MODE 2: C = (g_oin @ Bw) + bias[c] + x[r,c] (NC = 512,  C = dout)
template <int MODE>
__global__ void __launch_bounds__(256)
sgemm_kernel(const float* __restrict__ Bw,
             const float* __restrict__ tl,
             const float* __restrict__ bias,
             const float* __restrict__ xres,
             float* __restrict__ dout)
{
    constexpr int NC = (MODE == 1) ? 2048 : 512;
    constexpr int K  = 512;
    const float* A = (MODE == 1) ? g_normed : g_oin;
    float*       C = (MODE == 1) ? g_g      : dout;

    __shared__ __align__(16) float As[8][128];
    __shared__ __align__(16) float Bs[8][128];

    int tid  = threadIdx.x;
    int row0 = blockIdx.y * 128, col0 = blockIdx.x * 128;
    int tx = tid & 15, ty = tid >> 4;
    int arow = tid >> 1, acol = (tid & 1) * 4;
    int brow = tid >> 5, bcol = (tid & 31) * 4;

    float acc[8][8] = {};
    const float* Aptr = A + (size_t)(row0 + arow) * K + acol;
    const float* Bptr = Bw + (size_t)brow * NC + col0 + bcol;

    for (int k0 = 0; k0 < K; k0 += 8) {
        float4 av = *(const float4*)(Aptr + k0);
        As[acol + 0][arow] = av.x;
        As[acol + 1][arow] = av.y;
        As[acol + 2][arow] = av.z;
        As[acol + 3][arow] = av.w;
        float4 bv = *(const float4*)(Bptr + (size_t)k0 * NC);
        *(float4*)&Bs[brow][bcol] = bv;
        __syncthreads();
        #pragma unroll
        for (int kk = 0; kk < 8; kk++) {
            float4 a0 = *(const float4*)&As[kk][ty * 8];
            float4 a1 = *(const float4*)&As[kk][ty * 8 + 4];
            float4 b0 = *(const float4*)&Bs[kk][tx * 8];
            float4 b1 = *(const float4*)&Bs[kk][tx * 8 + 4];
            float af[8] = {a0.x, a0.y, a0.z, a0.w, a1.x, a1.y, a1.z, a1.w};
            float bf[8] = {b0.x, b0.y, b0.z, b0.w, b1.x, b1.y, b1.z, b1.w};
            #pragma unroll
            for (int i = 0; i < 8; i++)
                #pragma unroll
                for (int j = 0; j < 8; j++)
                    acc[i][j] += af[i] * bf[j];
        }
        __syncthreads();
    }

    #pragma unroll
    for (int i = 0; i < 8; i++) {
        int r = row0 + ty * 8 + i;
        float tlv = (MODE == 1) ? tl[r] : 0.0f;
        #pragma unroll
        for (int j = 0; j < 8; j++) {
            int c = col0 + tx * 8 + j;
            float v = acc[i][j];
            if (MODE == 1) {
                v = (v / (1.0f + expf(-v))) * tlv;
            } else {
                v = v + bias[c] + xres[(size_t)r * NC + c];
            }
            C[(size_t)r * NC + c] = v;
        }
    }
}

// ---------------- attention: per (b,h), 32 q-rows per block --------------------
// s = silu(q k^T + time_bias + pos_bias)/N * attn_mask * tl_m * tl_n ; out = s @ v
__global__ void __launch_bounds__(256)
attn_kernel(const float* __restrict__ tw,
            const float* __restrict__ pw,
            const float* __restrict__ amask,
            const float* __restrict__ tl)
{
    const int n0 = blockIdx.x * 32;
    const int h  = blockIdx.y;
    const int b  = blockIdx.z;

    __shared__ __align__(16) float qs[32][64];
    __shared__ float kvs[64][65];
    __shared__ float ss[32][64];
    __shared__ int tsn[32];
    __shared__ float tln[32];
    __shared__ int tsm[64];
    __shared__ float tlm[64];

    int tid = threadIdx.x;
    int tx = tid & 15, ty = tid >> 4;
    const int r0 = ty * 2, r1 = ty * 2 + 1;

    // load q tile (rows n0..n0+31, d=64) from g (offset 1024 + h*64)
    #pragma unroll
    for (int it = 0; it < 2; it++) {
        int idx = tid * 2 + it;          // float4 index 0..511
        int rr = idx >> 4, cc = (idx & 15) * 4;
        float4 vq = *(const float4*)(g_g + ((size_t)(b * N_ + n0 + rr)) * G_ + 1024 + h * 64 + cc);
        *(float4*)&qs[rr][cc] = vq;
    }
    if (tid < 32) {
        tsn[tid] = g_ts32[b * NP1 + n0 + tid + 1];
        tln[tid] = tl[b * N_ + n0 + tid];
    }

    float oacc[2][4] = {};

    for (int m0 = 0; m0 < N_; m0 += 64) {
        __syncthreads();   // protect kvs reuse from previous iteration
        // load k tile (rows m0..m0+63) into kvs, offset 1536 + h*64
        #pragma unroll
        for (int it = 0; it < 4; it++) {
            int idx = tid * 4 + it;
            int rr = idx >> 4, cc = (idx & 15) * 4;
            float4 vk = *(const float4*)(g_g + ((size_t)(b * N_ + m0 + rr)) * G_ + 1536 + h * 64 + cc);
            kvs[rr][cc + 0] = vk.x; kvs[rr][cc + 1] = vk.y;
            kvs[rr][cc + 2] = vk.z; kvs[rr][cc + 3] = vk.w;
        }
        if (tid < 64) {
            tsm[tid] = g_ts32[b * NP1 + m0 + tid];
            tlm[tid] = tl[b * N_ + m0 + tid];
        }
        __syncthreads();

        // phase A: s(32x64) = q k^T, thread tile 2x4
        float sa[2][4] = {};
        #pragma unroll 8
        for (int kk = 0; kk < 64; kk++) {
            float a0 = qs[r0][kk], a1 = qs[r1][kk];
            #pragma unroll
            for (int j = 0; j < 4; j++) {
                float bb = kvs[tx * 4 + j][kk];
                sa[0][j] += a0 * bb;
                sa[1][j] += a1 * bb;
            }
        }

        // epilogue: rel bias + silu + masks -> ss
        #pragma unroll
        for (int i = 0; i < 2; i++) {
            int nl = ty * 2 + i;
            int n  = n0 + nl;
            int tn = tsn[nl];
            float tlnv = tln[nl];
            #pragma unroll
            for (int j = 0; j < 4; j++) {
                int ml = tx * 4 + j;
                int m  = m0 + ml;
                int dt = tn - tsm[ml];
                float ad = fabsf((float)dt);
                ad = fmaxf(ad, 1.0f);
                int buck = (int)(logf(ad) / 0.301f);
                buck = min(max(buck, 0), NB_);
                float rel = tw[buck] + pw[N_ - 1 + m - n];
                float sv = sa[i][j] + rel;
                sv = sv / (1.0f + expf(-sv)) * (1.0f / (float)N_);
                sv *= amask[(size_t)n * N_ + m] * tlm[ml] * tlnv;
                ss[nl][ml] = sv;
            }
        }
        __syncthreads();

        // load v tile into kvs (offset 512 + h*64)
        #pragma unroll
        for (int it = 0; it < 4; it++) {
            int idx = tid * 4 + it;
            int rr = idx >> 4, cc = (idx & 15) * 4;
            float4 vv = *(const float4*)(g_g + ((size_t)(b * N_ + m0 + rr)) * G_ + 512 + h * 64 + cc);
            kvs[rr][cc + 0] = vv.x; kvs[rr][cc + 1] = vv.y;
            kvs[rr][cc + 2] = vv.z; kvs[rr][cc + 3] = vv.w;
        }
        __syncthreads();

        // phase B: out(32x64) += ss @ v, thread tile 2 rows x 4 d-cols
        #pragma unroll 8
        for (int mm = 0; mm < 64; mm++) {
            float a0 = ss[r0][mm], a1 = ss[r1][mm];
            #pragma unroll
            for (int j = 0; j < 4; j++) {
                float bb = kvs[mm][tx * 4 + j];
                oacc[0][j] += a0 * bb;
                oacc[1][j] += a1 * bb;
            }
        }
    }

    // write attn_out (B,N,H*DL)
    #pragma unroll
    for (int i = 0; i < 2; i++) {
        int n = n0 + ty * 2 + i;
        #pragma unroll
        for (int j = 0; j < 4; j++) {
            g_attn[((size_t)(b * N_ + n)) * 512 + h * 64 + tx * 4 + j] = oacc[i][j];
        }
    }
}

// ---------------- launch -------------------------------------------------------
extern "C" void kernel_launch(void* const* d_in, const int* in_sizes, int n_in,
                              void* d_out, int out_size)
{
    const float* x      = (const float*)d_in[0];
    const float* tlmask = (const float*)d_in[1];
    const float* amask  = (const float*)d_in[2];
    const float* uvqk   = (const float*)d_in[3];
    const float* out_w  = (const float*)d_in[4];
    const float* out_b  = (const float*)d_in[5];
    const float* tw     = (const float*)d_in[6];
    const float* pw     = (const float*)d_in[7];
    const int*   tsraw  = (const int*)d_in[8];
    float*       out    = (float*)d_out;

    const int rows = B_ * N_;   // 16384

    ts_fix_kernel<<<(B_ * NP1 + 255) / 256, 256>>>(tsraw);

    ln1_kernel<<<rows, 256>>>(x, tlmask);

    dim3 g1(G_ / 128, rows / 128);        // (16, 128)
    sgemm_kernel<1><<<g1, 256>>>(uvqk, tlmask, nullptr, nullptr, nullptr);

    dim3 ga(N_ / 32, H_, B_);             // (16, 8, 32)
    attn_kernel<<<ga, 256>>>(tw, pw, amask, tlmask);

    ln2_kernel<<<rows, 256>>>(tlmask);

    dim3 g2(512 / 128, rows / 128);       // (4, 128)
    sgemm_kernel<2><<<g2, 256>>>(out_w, nullptr, out_b, x, out);
}

// round 3
// speedup vs baseline: 1.5894x; 1.5894x over previous
#include <cuda_runtime.h>
#include <math.h>

#define B_  32
#define N_  512
#define F_  512
#define H_  8
#define DL_ 64
#define DA_ 64
#define NB_ 128
#define G_  2048   // 2*H*DL + 2*H*DA
#define NP1 513    // N+1

// ---------------- scratch (static device globals; allocation-free) -------------
__device__ float g_normed[(size_t)B_ * N_ * F_];
__device__ float g_g[(size_t)B_ * N_ * G_];
__device__ float g_attn[(size_t)B_ * N_ * H_ * DL_];
__device__ float g_oin[(size_t)B_ * N_ * H_ * DL_];
__device__ int   g_ts32[B_ * NP1];
__device__ int   g_tflag[64];          // 8x8 tile flags (64x64 tiles of attn_mask)

// ---------------- timestamp canonicalization ----------------------------------
// Reference declares unix_ts int64 but JAX (x64 off) downcasts to int32.
// Detect layout: int64-LE has zero high words at odd int32 indices.
__global__ void ts_fix_kernel(const int* __restrict__ tsraw)
{
    __shared__ int is64;
    if (threadIdx.x == 0) {
        int z = 0;
        #pragma unroll
        for (int i = 1; i < 16; i += 2) z |= tsraw[i];
        is64 = (z == 0) ? 1 : 0;
    }
    __syncthreads();
    int i = blockIdx.x * blockDim.x + threadIdx.x;
    if (i < B_ * NP1) g_ts32[i] = is64 ? tsraw[2 * i] : tsraw[i];
}

// ---------------- per-tile mask flags (exact: skip only all-zero tiles) --------
__global__ void tileflag_kernel(const float* __restrict__ amask)
{
    int t = blockIdx.x;            // 0..63
    int ti = t >> 3, tj = t & 7;
    int any = 0;
    for (int k = threadIdx.x; k < 1024; k += 256) {   // float4 granules
        int r = k >> 4, c = (k & 15) * 4;
        float4 v = *(const float4*)(amask + (size_t)(ti * 64 + r) * N_ + tj * 64 + c);
        any |= (v.x != 0.f) | (v.y != 0.f) | (v.z != 0.f) | (v.w != 0.f);
    }
    any = __syncthreads_or(any);
    if (threadIdx.x == 0) g_tflag[t] = any;
}

// ---------------- LayerNorm over F=512, one block (256 thr) per row ------------
__global__ void ln1_kernel(const float* __restrict__ x,
                           const float* __restrict__ tl)
{
    int row = blockIdx.x;
    int tid = threadIdx.x;
    const float* xr = x + (size_t)row * F_;
    float v0 = xr[tid], v1 = xr[tid + 256];
    float s = v0 + v1, sq = v0 * v0 + v1 * v1;
    #pragma unroll
    for (int o = 16; o; o >>= 1) {
        s  += __shfl_down_sync(0xffffffffu, s,  o);
        sq += __shfl_down_sync(0xffffffffu, sq, o);
    }
    __shared__ float red[16];
    __shared__ float mean_s, rstd_s;
    int w = tid >> 5, l = tid & 31;
    if (l == 0) { red[w] = s; red[w + 8] = sq; }
    __syncthreads();
    if (tid == 0) {
        float ts = 0.f, tq = 0.f;
        #pragma unroll
        for (int i = 0; i < 8; i++) { ts += red[i]; tq += red[i + 8]; }
        float m = ts * (1.0f / F_);
        float var = tq * (1.0f / F_) - m * m;
        mean_s = m;
        rstd_s = rsqrtf(var + 1e-6f);
    }
    __syncthreads();
    float t = tl[row];
    float m = mean_s, rs = rstd_s;
    g_normed[(size_t)row * F_ + tid]       = (v0 - m) * rs * t;
    g_normed[(size_t)row * F_ + tid + 256] = (v1 - m) * rs * t;
}

// o_input = u * LN(attn_out) * tl
__global__ void ln2_kernel(const float* __restrict__ tl)
{
    int row = blockIdx.x;
    int tid = threadIdx.x;
    const float* ar = g_attn + (size_t)row * 512;
    float v0 = ar[tid], v1 = ar[tid + 256];
    float s = v0 + v1, sq = v0 * v0 + v1 * v1;
    #pragma unroll
    for (int o = 16; o; o >>= 1) {
        s  += __shfl_down_sync(0xffffffffu, s,  o);
        sq += __shfl_down_sync(0xffffffffu, sq, o);
    }
    __shared__ float red[16];
    __shared__ float mean_s, rstd_s;
    int w = tid >> 5, l = tid & 31;
    if (l == 0) { red[w] = s; red[w + 8] = sq; }
    __syncthreads();
    if (tid == 0) {
        float ts = 0.f, tq = 0.f;
        #pragma unroll
        for (int i = 0; i < 8; i++) { ts += red[i]; tq += red[i + 8]; }
        float m = ts * (1.0f / 512.0f);
        float var = tq * (1.0f / 512.0f) - m * m;
        mean_s = m;
        rstd_s = rsqrtf(var + 1e-6f);
    }
    __syncthreads();
    float t = tl[row];
    float m = mean_s, rs = rstd_s;
    float u0 = g_g[(size_t)row * G_ + tid];
    float u1 = g_g[(size_t)row * G_ + tid + 256];
    g_oin[(size_t)row * 512 + tid]       = u0 * (v0 - m) * rs * t;
    g_oin[(size_t)row * 512 + tid + 256] = u1 * (v1 - m) * rs * t;
}

// ---------------- SGEMM 128x128x8, 256 threads, 8x8 regs, reg-prefetch ---------
template <int MODE>
__global__ void __launch_bounds__(256)
sgemm_kernel(const float* __restrict__ Bw,
             const float* __restrict__ tl,
             const float* __restrict__ bias,
             const float* __restrict__ xres,
             float* __restrict__ dout)
{
    constexpr int NC = (MODE == 1) ? 2048 : 512;
    constexpr int K  = 512;
    const float* A = (MODE == 1) ? g_normed : g_oin;
    float*       C = (MODE == 1) ? g_g      : dout;

    __shared__ __align__(16) float As[8][128];
    __shared__ __align__(16) float Bs[8][128];

    int tid  = threadIdx.x;
    int row0 = blockIdx.y * 128, col0 = blockIdx.x * 128;
    int tx = tid & 15, ty = tid >> 4;
    int arow = tid >> 1, acol = (tid & 1) * 4;
    int brow = tid >> 5, bcol = (tid & 31) * 4;

    float acc[8][8] = {};
    const float* Aptr = A + (size_t)(row0 + arow) * K + acol;
    const float* Bptr = Bw + (size_t)brow * NC + col0 + bcol;

    float4 av = *(const float4*)(Aptr);
    float4 bv = *(const float4*)(Bptr);

    for (int k0 = 0; k0 < K; k0 += 8) {
        As[acol + 0][arow] = av.x;
        As[acol + 1][arow] = av.y;
        As[acol + 2][arow] = av.z;
        As[acol + 3][arow] = av.w;
        *(float4*)&Bs[brow][bcol] = bv;
        __syncthreads();
        if (k0 + 8 < K) {
            av = *(const float4*)(Aptr + k0 + 8);
            bv = *(const float4*)(Bptr + (size_t)(k0 + 8) * NC);
        }
        #pragma unroll
        for (int kk = 0; kk < 8; kk++) {
            float4 a0 = *(const float4*)&As[kk][ty * 8];
            float4 a1 = *(const float4*)&As[kk][ty * 8 + 4];
            float4 b0 = *(const float4*)&Bs[kk][tx * 8];
            float4 b1 = *(const float4*)&Bs[kk][tx * 8 + 4];
            float af[8] = {a0.x, a0.y, a0.z, a0.w, a1.x, a1.y, a1.z, a1.w};
            float bf[8] = {b0.x, b0.y, b0.z, b0.w, b1.x, b1.y, b1.z, b1.w};
            #pragma unroll
            for (int i = 0; i < 8; i++)
                #pragma unroll
                for (int j = 0; j < 8; j++)
                    acc[i][j] += af[i] * bf[j];
        }
        __syncthreads();
    }

    #pragma unroll
    for (int i = 0; i < 8; i++) {
        int r = row0 + ty * 8 + i;
        float tlv = (MODE == 1) ? tl[r] : 0.0f;
        #pragma unroll
        for (int j = 0; j < 8; j++) {
            int c = col0 + tx * 8 + j;
            float v = acc[i][j];
            if (MODE == 1) {
                v = __fdividef(v, 1.0f + __expf(-v)) * tlv;
            } else {
                v = v + bias[c] + xres[(size_t)r * NC + c];
            }
            C[(size_t)r * NC + c] = v;
        }
    }
}

// ---------------- attention: 64 q-rows per block, 4x4 reg tiles ----------------
// smem: qsT/ksT transposed ([d][n]) with XOR swizzle, ssT transposed ([m][n]).
// swizzled linear index for (row=reduction idx, col=packed idx):
__device__ __forceinline__ int SWZ(int row, int col) {
    return row * 64 + ((((col) >> 2) ^ (row & 15)) << 2) + (col & 3);
}

__global__ void __launch_bounds__(256)
attn_kernel(const float* __restrict__ tw,
            const float* __restrict__ pw,
            const float* __restrict__ amask,
            const float* __restrict__ tl)
{
    const int n0 = blockIdx.x * 64;
    const int h  = blockIdx.y;
    const int b  = blockIdx.z;

    __shared__ float qsT[4096];   // [d][n] swizzled
    __shared__ float kvs[4096];   // K: [d][m] swizzled; V: [m][d] linear
    __shared__ float ssT[4096];   // [m][n] swizzled

    const int tid = threadIdx.x;
    const int tx = tid & 15, ty = tid >> 4;

    // ---- load q tile transposed: rows n0..n0+63, d = 0..63 ----
    #pragma unroll
    for (int it = 0; it < 4; it++) {
        int idx = tid + it * 256;          // float4 granule 0..1023
        int rr = idx >> 4;                 // n-local
        int cc = (idx & 15) * 4;           // d
        float4 v = *(const float4*)(g_g + ((size_t)(b * N_ + n0 + rr)) * G_ + 1024 + h * 64 + cc);
        qsT[SWZ(cc + 0, rr)] = v.x;
        qsT[SWZ(cc + 1, rr)] = v.y;
        qsT[SWZ(cc + 2, rr)] = v.z;
        qsT[SWZ(cc + 3, rr)] = v.w;
    }

    // per-thread n-side constants (n = n0 + ty*4 + i)
    int   tn_r[4];
    float tln_r[4];
    #pragma unroll
    for (int i = 0; i < 4; i++) {
        int n = n0 + ty * 4 + i;
        tn_r[i]  = g_ts32[b * NP1 + n + 1];
        tln_r[i] = tl[b * N_ + n];
    }

    float oacc[4][4] = {};
    const int tn0 = n0 >> 6;

    for (int m0 = 0; m0 < N_; m0 += 64) {
        if (!g_tflag[tn0 * 8 + (m0 >> 6)]) continue;

        __syncthreads();   // previous phase B done (kvs, ssT free)

        // ---- load k tile transposed ----
        #pragma unroll
        for (int it = 0; it < 4; it++) {
            int idx = tid + it * 256;
            int rr = idx >> 4;             // m-local
            int cc = (idx & 15) * 4;       // d
            float4 v = *(const float4*)(g_g + ((size_t)(b * N_ + m0 + rr)) * G_ + 1536 + h * 64 + cc);
            kvs[SWZ(cc + 0, rr)] = v.x;
            kvs[SWZ(cc + 1, rr)] = v.y;
            kvs[SWZ(cc + 2, rr)] = v.z;
            kvs[SWZ(cc + 3, rr)] = v.w;
        }
        // m-side constants (m = m0 + tx*4 + j)
        int   tm_r[4];
        float tlm_r[4];
        #pragma unroll
        for (int j = 0; j < 4; j++) {
            int m = m0 + tx * 4 + j;
            tm_r[j]  = g_ts32[b * NP1 + m];
            tlm_r[j] = tl[b * N_ + m];
        }
        __syncthreads();

        // ---- phase A: s(64x64) = q k^T ----
        float acc[4][4] = {};
        #pragma unroll 16
        for (int kk = 0; kk < 64; kk++) {
            float4 a  = *(const float4*)&qsT[kk * 64 + ((ty ^ (kk & 15)) << 2)];
            float4 bb = *(const float4*)&kvs[kk * 64 + ((tx ^ (kk & 15)) << 2)];
            float af[4] = {a.x, a.y, a.z, a.w};
            float bf[4] = {bb.x, bb.y, bb.z, bb.w};
            #pragma unroll
            for (int i = 0; i < 4; i++)
                #pragma unroll
                for (int j = 0; j < 4; j++)
                    acc[i][j] += af[i] * bf[j];
        }

        // ---- epilogue: rel bias + silu + masks; write ssT[m][n] ----
        #pragma unroll
        for (int i = 0; i < 4; i++) {
            int n = n0 + ty * 4 + i;
            #pragma unroll
            for (int j = 0; j < 4; j++) {
                int m  = m0 + tx * 4 + j;
                int dt = tn_r[i] - tm_r[j];
                float ad = fmaxf(fabsf((float)dt), 1.0f);
                int buck = (int)(__logf(ad) * (1.0f / 0.301f));
                buck = min(max(buck, 0), NB_);
                float rel = tw[buck] + pw[N_ - 1 + m - n];
                float sv = acc[i][j] + rel;
                sv = __fdividef(sv, 1.0f + __expf(-sv)) * (1.0f / (float)N_);
                sv *= amask[(size_t)n * N_ + m] * tlm_r[j] * tln_r[i];
                // ssT[m_local][n_local], swizzled
                int ml = tx * 4 + j;
                ssT[ml * 64 + ((ty ^ (ml & 15)) << 2) + i] = sv;
            }
        }
        __syncthreads();   // ssT visible; phase A reads of kvs done

        // ---- load v tile (linear [m][d]) ----
        #pragma unroll
        for (int it = 0; it < 4; it++) {
            int idx = tid + it * 256;
            int rr = idx >> 4;             // m-local
            int cc = (idx & 15) * 4;       // d
            float4 v = *(const float4*)(g_g + ((size_t)(b * N_ + m0 + rr)) * G_ + 512 + h * 64 + cc);
            *(float4*)&kvs[rr * 64 + cc] = v;
        }
        __syncthreads();

        // ---- phase B: out(64x64) += ssT^T @ v ----
        #pragma unroll 16
        for (int mm = 0; mm < 64; mm++) {
            float4 a  = *(const float4*)&ssT[mm * 64 + ((ty ^ (mm & 15)) << 2)];
            float4 bb = *(const float4*)&kvs[mm * 64 + tx * 4];
            float af[4] = {a.x, a.y, a.z, a.w};
            float bf[4] = {bb.x, bb.y, bb.z, bb.w};
            #pragma unroll
            for (int i = 0; i < 4; i++)
                #pragma unroll
                for (int j = 0; j < 4; j++)
                    oacc[i][j] += af[i] * bf[j];
        }
    }

    // ---- write attn_out (B,N,H*DL) ----
    #pragma unroll
    for (int i = 0; i < 4; i++) {
        int n = n0 + ty * 4 + i;
        float4 o = make_float4(oacc[i][0], oacc[i][1], oacc[i][2], oacc[i][3]);
        *(float4*)(g_attn + ((size_t)(b * N_ + n)) * 512 + h * 64 + tx * 4) = o;
    }
}

// ---------------- launch -------------------------------------------------------
extern "C" void kernel_launch(void* const* d_in, const int* in_sizes, int n_in,
                              void* d_out, int out_size)
{
    const float* x      = (const float*)d_in[0];
    const float* tlmask = (const float*)d_in[1];
    const float* amask  = (const float*)d_in[2];
    const float* uvqk   = (const float*)d_in[3];
    const float* out_w  = (const float*)d_in[4];
    const float* out_b  = (const float*)d_in[5];
    const float* tw     = (const float*)d_in[6];
    const float* pw     = (const float*)d_in[7];
    const int*   tsraw  = (const int*)d_in[8];
    float*       out    = (float*)d_out;

    const int rows = B_ * N_;   // 16384

    ts_fix_kernel<<<(B_ * NP1 + 255) / 256, 256>>>(tsraw);
    tileflag_kernel<<<64, 256>>>(amask);

    ln1_kernel<<<rows, 256>>>(x, tlmask);

    dim3 g1(G_ / 128, rows / 128);        // (16, 128)
    sgemm_kernel<1><<<g1, 256>>>(uvqk, tlmask, nullptr, nullptr, nullptr);

    dim3 ga(N_ / 64, H_, B_);             // (8, 8, 32)
    attn_kernel<<<ga, 256>>>(tw, pw, amask, tlmask);

    ln2_kernel<<<rows, 256>>>(tlmask);

    dim3 g2(512 / 128, rows / 128);       // (4, 128)
    sgemm_kernel<2><<<g2, 256>>>(out_w, nullptr, out_b, x, out);
}

// round 6
// speedup vs baseline: 2.6058x; 1.6395x over previous
#include <cuda_runtime.h>
#include <cuda_bf16.h>
#include <math.h>
#include <stdint.h>

#define B_  32
#define N_  512
#define F_  512
#define H_  8
#define NB_ 128
#define G_  2048
#define NP1 513

// ---------------- scratch ------------------------------------------------------
__device__ __align__(16) float g_g[(size_t)B_ * N_ * G_];
__device__ __align__(16) float g_attn[(size_t)B_ * N_ * 512];
__device__ int   g_ts32[B_ * NP1];
__device__ int   g_tflag[64];
__device__ __align__(16) __nv_bfloat16 g_Ahi[(size_t)B_ * N_ * F_];
__device__ __align__(16) __nv_bfloat16 g_Alo[(size_t)B_ * N_ * F_];
__device__ __align__(16) __nv_bfloat16 g_Whi[(size_t)G_ * F_];    // [n][k]
__device__ __align__(16) __nv_bfloat16 g_Wlo[(size_t)G_ * F_];
__device__ __align__(16) __nv_bfloat16 g_O2hi[(size_t)B_ * N_ * 512];
__device__ __align__(16) __nv_bfloat16 g_O2lo[(size_t)B_ * N_ * 512];
__device__ __align__(16) __nv_bfloat16 g_W2hi[(size_t)512 * 512]; // [n][k]
__device__ __align__(16) __nv_bfloat16 g_W2lo[(size_t)512 * 512];

// ---------------- helpers ------------------------------------------------------
__device__ __forceinline__ uint32_t smem_u32(const void* p) {
    uint32_t a;
    asm("{ .reg .u64 t; cvta.to.shared.u64 t, %1; cvt.u32.u64 %0, t; }" : "=r"(a) : "l"(p));
    return a;
}
__device__ __forceinline__ void ldsm_x4(uint32_t* r, uint32_t a) {
    asm volatile("ldmatrix.sync.aligned.m8n8.x4.shared.b16 {%0,%1,%2,%3}, [%4];"
        : "=r"(r[0]), "=r"(r[1]), "=r"(r[2]), "=r"(r[3]) : "r"(a));
}
__device__ __forceinline__ void ldsm_x2(uint32_t* r, uint32_t a) {
    asm volatile("ldmatrix.sync.aligned.m8n8.x2.shared.b16 {%0,%1}, [%2];"
        : "=r"(r[0]), "=r"(r[1]) : "r"(a));
}
__device__ __forceinline__ void mma16816(float* d, const uint32_t* a, const uint32_t* b) {
    asm volatile("mma.sync.aligned.m16n8k16.row.col.f32.bf16.bf16.f32 "
        "{%0,%1,%2,%3}, {%4,%5,%6,%7}, {%8,%9}, {%0,%1,%2,%3};"
        : "+f"(d[0]), "+f"(d[1]), "+f"(d[2]), "+f"(d[3])
        : "r"(a[0]), "r"(a[1]), "r"(a[2]), "r"(a[3]), "r"(b[0]), "r"(b[1]));
}

// ---------------- timestamp canonicalization ----------------------------------
// Reference declares unix_ts int64 but JAX (x64 off) downcasts to int32.
__global__ void ts_fix_kernel(const int* __restrict__ tsraw)
{
    __shared__ int is64;
    if (threadIdx.x == 0) {
        int z = 0;
        #pragma unroll
        for (int i = 1; i < 16; i += 2) z |= tsraw[i];
        is64 = (z == 0) ? 1 : 0;
    }
    __syncthreads();
    int i = blockIdx.x * blockDim.x + threadIdx.x;
    if (i < B_ * NP1) g_ts32[i] = is64 ? tsraw[2 * i] : tsraw[i];
}

// ---------------- per-tile mask flags ------------------------------------------
__global__ void tileflag_kernel(const float* __restrict__ amask)
{
    int t = blockIdx.x;
    int ti = t >> 3, tj = t & 7;
    int any = 0;
    for (int k = threadIdx.x; k < 1024; k += 256) {
        int r = k >> 4, c = (k & 15) * 4;
        float4 v = *(const float4*)(amask + (size_t)(ti * 64 + r) * N_ + tj * 64 + c);
        any |= (v.x != 0.f) | (v.y != 0.f) | (v.z != 0.f) | (v.w != 0.f);
    }
    any = __syncthreads_or(any);
    if (threadIdx.x == 0) g_tflag[t] = any;
}

// ---------------- W transpose + bf16 hi/lo split (generic) ---------------------
__global__ void wprep_kernel(const float* __restrict__ W,
                             __nv_bfloat16* __restrict__ hi,
                             __nv_bfloat16* __restrict__ lo,
                             int ncols)
{
    __shared__ float t[32][33];
    int n0 = blockIdx.x * 32, k0 = blockIdx.y * 32;
    int tx = threadIdx.x, ty = threadIdx.y;   // 32 x 8
    #pragma unroll
    for (int j = 0; j < 4; j++)
        t[ty + j * 8][tx] = W[(size_t)(k0 + ty + j * 8) * ncols + n0 + tx];
    __syncthreads();
    #pragma unroll
    for (int j = 0; j < 4; j++) {
        int row = ty + j * 8;                 // local n
        float v = t[tx][row];
        __nv_bfloat16 h = __float2bfloat16(v);
        float l = v - __bfloat162float(h);
        size_t o = (size_t)(n0 + row) * F_ + k0 + tx;
        hi[o] = h;
        lo[o] = __float2bfloat16(l);
    }
}

// ---------------- ln1: LayerNorm -> bf16 hi/lo ---------------------------------
__global__ void ln1_kernel(const float* __restrict__ x,
                           const float* __restrict__ tl)
{
    int row = blockIdx.x;
    int tid = threadIdx.x;
    const float* xr = x + (size_t)row * F_;
    float v0 = xr[tid], v1 = xr[tid + 256];
    float s = v0 + v1, sq = v0 * v0 + v1 * v1;
    #pragma unroll
    for (int o = 16; o; o >>= 1) {
        s  += __shfl_down_sync(0xffffffffu, s,  o);
        sq += __shfl_down_sync(0xffffffffu, sq, o);
    }
    __shared__ float red[16];
    __shared__ float mean_s, rstd_s;
    int w = tid >> 5, l = tid & 31;
    if (l == 0) { red[w] = s; red[w + 8] = sq; }
    __syncthreads();
    if (tid == 0) {
        float ts = 0.f, tq = 0.f;
        #pragma unroll
        for (int i = 0; i < 8; i++) { ts += red[i]; tq += red[i + 8]; }
        float m = ts * (1.0f / F_);
        float var = tq * (1.0f / F_) - m * m;
        mean_s = m;
        rstd_s = rsqrtf(var + 1e-6f);
    }
    __syncthreads();
    float t = tl[row];
    float m = mean_s, rs = rstd_s;
    float n0v = (v0 - m) * rs * t;
    float n1v = (v1 - m) * rs * t;
    __nv_bfloat16 h0 = __float2bfloat16(n0v);
    __nv_bfloat16 h1 = __float2bfloat16(n1v);
    size_t o0 = (size_t)row * F_ + tid;
    g_Ahi[o0]       = h0;
    g_Alo[o0]       = __float2bfloat16(n0v - __bfloat162float(h0));
    g_Ahi[o0 + 256] = h1;
    g_Alo[o0 + 256] = __float2bfloat16(n1v - __bfloat162float(h1));
}

// ---------------- ln2: o_input = u*LN(attn)*tl -> bf16 hi/lo -------------------
__global__ void ln2_kernel(const float* __restrict__ tl)
{
    int row = blockIdx.x;
    int tid = threadIdx.x;
    const float* ar = g_attn + (size_t)row * 512;
    float v0 = ar[tid], v1 = ar[tid + 256];
    float s = v0 + v1, sq = v0 * v0 + v1 * v1;
    #pragma unroll
    for (int o = 16; o; o >>= 1) {
        s  += __shfl_down_sync(0xffffffffu, s,  o);
        sq += __shfl_down_sync(0xffffffffu, sq, o);
    }
    __shared__ float red[16];
    __shared__ float mean_s, rstd_s;
    int w = tid >> 5, l = tid & 31;
    if (l == 0) { red[w] = s; red[w + 8] = sq; }
    __syncthreads();
    if (tid == 0) {
        float ts = 0.f, tq = 0.f;
        #pragma unroll
        for (int i = 0; i < 8; i++) { ts += red[i]; tq += red[i + 8]; }
        float m = ts * (1.0f / 512.0f);
        float var = tq * (1.0f / 512.0f) - m * m;
        mean_s = m;
        rstd_s = rsqrtf(var + 1e-6f);
    }
    __syncthreads();
    float t = tl[row];
    float m = mean_s, rs = rstd_s;
    float u0 = g_g[(size_t)row * G_ + tid];
    float u1 = g_g[(size_t)row * G_ + tid + 256];
    float o0 = u0 * (v0 - m) * rs * t;
    float o1 = u1 * (v1 - m) * rs * t;
    __nv_bfloat16 h0 = __float2bfloat16(o0);
    __nv_bfloat16 h1 = __float2bfloat16(o1);
    size_t off = (size_t)row * 512 + tid;
    g_O2hi[off]       = h0;
    g_O2lo[off]       = __float2bfloat16(o0 - __bfloat162float(h0));
    g_O2hi[off + 256] = h1;
    g_O2lo[off + 256] = __float2bfloat16(o1 - __bfloat162float(h1));
}

// ---------------- GEMM via mma.sync bf16, 3-term split -------------------------
// 128x128 block tile, 8 warps (4x2), warp tile 32x64. A:[m][k], B:[n][k] (=B^T).
// MODE 1: C = silu(acc)*tl[row] -> g_g (NC=2048)
// MODE 2: C = acc + bias[col] + xres      (NC=512)
template <int MODE>
__global__ void __launch_bounds__(256)
gemm_mma(const __nv_bfloat16* __restrict__ Ahi, const __nv_bfloat16* __restrict__ Alo,
         const __nv_bfloat16* __restrict__ Bhi, const __nv_bfloat16* __restrict__ Blo,
         const float* __restrict__ tl, const float* __restrict__ bias,
         const float* __restrict__ xres, float* __restrict__ Cout)
{
    constexpr int NC  = (MODE == 1) ? G_ : 512;
    constexpr int LDS = 40;   // bf16 elements per smem row (5 coprime 8 -> no LDSM conflicts)

    __shared__ __align__(16) __nv_bfloat16 sAhi[128 * LDS];
    __shared__ __align__(16) __nv_bfloat16 sAlo[128 * LDS];
    __shared__ __align__(16) __nv_bfloat16 sBhi[128 * LDS];
    __shared__ __align__(16) __nv_bfloat16 sBlo[128 * LDS];

    const int tid = threadIdx.x, lane = tid & 31, wid = tid >> 5;
    const int wr = wid & 3, wc = wid >> 2;          // warp grid 4(m) x 2(n)
    const int m0 = blockIdx.y * 128, n0 = blockIdx.x * 128;

    const uint32_t bAhi = smem_u32(sAhi), bAlo = smem_u32(sAlo);
    const uint32_t bBhi = smem_u32(sBhi), bBlo = smem_u32(sBlo);

    float d[2][8][4] = {};

    for (int kc = 0; kc < 16; kc++) {
        const int k0 = kc * 32;
        __syncthreads();
        #pragma unroll
        for (int it = 0; it < 2; it++) {
            int idx = tid + it * 256;
            int r = idx >> 2, c = (idx & 3) * 8;
            size_t asrc = (size_t)(m0 + r) * F_ + k0 + c;
            size_t bsrc = (size_t)(n0 + r) * F_ + k0 + c;
            *(float4*)&sAhi[r * LDS + c] = *(const float4*)(Ahi + asrc);
            *(float4*)&sAlo[r * LDS + c] = *(const float4*)(Alo + asrc);
            *(float4*)&sBhi[r * LDS + c] = *(const float4*)(Bhi + bsrc);
            *(float4*)&sBlo[r * LDS + c] = *(const float4*)(Blo + bsrc);
        }
        __syncthreads();

        #pragma unroll
        for (int ks = 0; ks < 2; ks++) {
            uint32_t ahi[2][4], alo[2][4], bhi[8][2], blo[8][2];
            #pragma unroll
            for (int mi = 0; mi < 2; mi++) {
                int row = wr * 32 + mi * 16 + (lane & 15);
                uint32_t off = (uint32_t)(row * LDS + ks * 16 + (lane >> 4) * 8) * 2;
                ldsm_x4(ahi[mi], bAhi + off);
                ldsm_x4(alo[mi], bAlo + off);
            }
            #pragma unroll
            for (int ni = 0; ni < 8; ni++) {
                int row = wc * 64 + ni * 8 + (lane & 7);
                uint32_t off = (uint32_t)(row * LDS + ks * 16 + ((lane >> 3) & 1) * 8) * 2;
                ldsm_x2(bhi[ni], bBhi + off);
                ldsm_x2(blo[ni], bBlo + off);
            }
            #pragma unroll
            for (int mi = 0; mi < 2; mi++)
                #pragma unroll
                for (int ni = 0; ni < 8; ni++) {
                    mma16816(d[mi][ni], ahi[mi], bhi[ni]);
                    mma16816(d[mi][ni], ahi[mi], blo[ni]);
                    mma16816(d[mi][ni], alo[mi], bhi[ni]);
                }
        }
    }

    // epilogue: d0,d1 -> row (lane>>2), cols (lane&3)*2,+1 ; d2,d3 -> row+8
    #pragma unroll
    for (int mi = 0; mi < 2; mi++) {
        int rbase = m0 + wr * 32 + mi * 16 + (lane >> 2);
        #pragma unroll
        for (int half = 0; half < 2; half++) {
            int row = rbase + half * 8;
            float tlv = (MODE == 1) ? tl[row] : 0.0f;
            #pragma unroll
            for (int ni = 0; ni < 8; ni++) {
                int col = n0 + wc * 64 + ni * 8 + (lane & 3) * 2;
                float v0 = d[mi][ni][half * 2 + 0];
                float v1 = d[mi][ni][half * 2 + 1];
                if (MODE == 1) {
                    v0 = __fdividef(v0, 1.0f + __expf(-v0)) * tlv;
                    v1 = __fdividef(v1, 1.0f + __expf(-v1)) * tlv;
                } else {
                    v0 += bias[col]     + xres[(size_t)row * NC + col];
                    v1 += bias[col + 1] + xres[(size_t)row * NC + col + 1];
                }
                *(float2*)(Cout + (size_t)row * NC + col) = make_float2(v0, v1);
            }
        }
    }
}

// ---------------- attention (R3 design, fp32) ----------------------------------
__device__ __forceinline__ int SWZ(int row, int col) {
    return row * 64 + ((((col) >> 2) ^ (row & 15)) << 2) + (col & 3);
}

__global__ void __launch_bounds__(256)
attn_kernel(const float* __restrict__ tw,
            const float* __restrict__ pw,
            const float* __restrict__ amask,
            const float* __restrict__ tl)
{
    const int n0 = blockIdx.x * 64;
    const int h  = blockIdx.y;
    const int b  = blockIdx.z;

    __shared__ float qsT[4096];
    __shared__ float kvs[4096];
    __shared__ float ssT[4096];

    const int tid = threadIdx.x;
    const int tx = tid & 15, ty = tid >> 4;

    #pragma unroll
    for (int it = 0; it < 4; it++) {
        int idx = tid + it * 256;
        int rr = idx >> 4;
        int cc = (idx & 15) * 4;
        float4 v = *(const float4*)(g_g + ((size_t)(b * N_ + n0 + rr)) * G_ + 1024 + h * 64 + cc);
        qsT[SWZ(cc + 0, rr)] = v.x;
        qsT[SWZ(cc + 1, rr)] = v.y;
        qsT[SWZ(cc + 2, rr)] = v.z;
        qsT[SWZ(cc + 3, rr)] = v.w;
    }

    int   tn_r[4];
    float tln_r[4];
    #pragma unroll
    for (int i = 0; i < 4; i++) {
        int n = n0 + ty * 4 + i;
        tn_r[i]  = g_ts32[b * NP1 + n + 1];
        tln_r[i] = tl[b * N_ + n];
    }

    float oacc[4][4] = {};
    const int tn0 = n0 >> 6;

    for (int m0 = 0; m0 < N_; m0 += 64) {
        if (!g_tflag[tn0 * 8 + (m0 >> 6)]) continue;

        __syncthreads();

        #pragma unroll
        for (int it = 0; it < 4; it++) {
            int idx = tid + it * 256;
            int rr = idx >> 4;
            int cc = (idx & 15) * 4;
            float4 v = *(const float4*)(g_g + ((size_t)(b * N_ + m0 + rr)) * G_ + 1536 + h * 64 + cc);
            kvs[SWZ(cc + 0, rr)] = v.x;
            kvs[SWZ(cc + 1, rr)] = v.y;
            kvs[SWZ(cc + 2, rr)] = v.z;
            kvs[SWZ(cc + 3, rr)] = v.w;
        }
        int   tm_r[4];
        float tlm_r[4];
        #pragma unroll
        for (int j = 0; j < 4; j++) {
            int m = m0 + tx * 4 + j;
            tm_r[j]  = g_ts32[b * NP1 + m];
            tlm_r[j] = tl[b * N_ + m];
        }
        __syncthreads();

        float acc[4][4] = {};
        #pragma unroll 16
        for (int kk = 0; kk < 64; kk++) {
            float4 a  = *(const float4*)&qsT[kk * 64 + ((ty ^ (kk & 15)) << 2)];
            float4 bb = *(const float4*)&kvs[kk * 64 + ((tx ^ (kk & 15)) << 2)];
            float af[4] = {a.x, a.y, a.z, a.w};
            float bf[4] = {bb.x, bb.y, bb.z, bb.w};
            #pragma unroll
            for (int i = 0; i < 4; i++)
                #pragma unroll
                for (int j = 0; j < 4; j++)
                    acc[i][j] += af[i] * bf[j];
        }

        #pragma unroll
        for (int i = 0; i < 4; i++) {
            int n = n0 + ty * 4 + i;
            #pragma unroll
            for (int j = 0; j < 4; j++) {
                int m  = m0 + tx * 4 + j;
                int dt = tn_r[i] - tm_r[j];
                float ad = fmaxf(fabsf((float)dt), 1.0f);
                int buck = (int)(__logf(ad) * (1.0f / 0.301f));
                buck = min(max(buck, 0), NB_);
                float rel = tw[buck] + pw[N_ - 1 + m - n];
                float sv = acc[i][j] + rel;
                sv = __fdividef(sv, 1.0f + __expf(-sv)) * (1.0f / (float)N_);
                sv *= amask[(size_t)n * N_ + m] * tlm_r[j] * tln_r[i];
                int ml = tx * 4 + j;
                ssT[ml * 64 + ((ty ^ (ml & 15)) << 2) + i] = sv;
            }
        }
        __syncthreads();

        #pragma unroll
        for (int it = 0; it < 4; it++) {
            int idx = tid + it * 256;
            int rr = idx >> 4;
            int cc = (idx & 15) * 4;
            float4 v = *(const float4*)(g_g + ((size_t)(b * N_ + m0 + rr)) * G_ + 512 + h * 64 + cc);
            *(float4*)&kvs[rr * 64 + cc] = v;
        }
        __syncthreads();

        #pragma unroll 16
        for (int mm = 0; mm < 64; mm++) {
            float4 a  = *(const float4*)&ssT[mm * 64 + ((ty ^ (mm & 15)) << 2)];
            float4 bb = *(const float4*)&kvs[mm * 64 + tx * 4];
            float af[4] = {a.x, a.y, a.z, a.w};
            float bf[4] = {bb.x, bb.y, bb.z, bb.w};
            #pragma unroll
            for (int i = 0; i < 4; i++)
                #pragma unroll
                for (int j = 0; j < 4; j++)
                    oacc[i][j] += af[i] * bf[j];
        }
    }

    #pragma unroll
    for (int i = 0; i < 4; i++) {
        int n = n0 + ty * 4 + i;
        float4 o = make_float4(oacc[i][0], oacc[i][1], oacc[i][2], oacc[i][3]);
        *(float4*)(g_attn + ((size_t)(b * N_ + n)) * 512 + h * 64 + tx * 4) = o;
    }
}

// ---------------- launch -------------------------------------------------------
extern "C" void kernel_launch(void* const* d_in, const int* in_sizes, int n_in,
                              void* d_out, int out_size)
{
    const float* x      = (const float*)d_in[0];
    const float* tlmask = (const float*)d_in[1];
    const float* amask  = (const float*)d_in[2];
    const float* uvqk   = (const float*)d_in[3];
    const float* out_w  = (const float*)d_in[4];
    const float* out_b  = (const float*)d_in[5];
    const float* tw     = (const float*)d_in[6];
    const float* pw     = (const float*)d_in[7];
    const int*   tsraw  = (const int*)d_in[8];
    float*       out    = (float*)d_out;

    const int rows = B_ * N_;   // 16384

    ts_fix_kernel<<<(B_ * NP1 + 255) / 256, 256>>>(tsraw);
    tileflag_kernel<<<64, 256>>>(amask);

    __nv_bfloat16 *whi, *wlo, *w2hi, *w2lo;
    cudaGetSymbolAddress((void**)&whi,  g_Whi);
    cudaGetSymbolAddress((void**)&wlo,  g_Wlo);
    cudaGetSymbolAddress((void**)&w2hi, g_W2hi);
    cudaGetSymbolAddress((void**)&w2lo, g_W2lo);

    wprep_kernel<<<dim3(G_ / 32, F_ / 32), dim3(32, 8)>>>(uvqk, whi, wlo, G_);
    wprep_kernel<<<dim3(512 / 32, F_ / 32), dim3(32, 8)>>>(out_w, w2hi, w2lo, 512);

    ln1_kernel<<<rows, 256>>>(x, tlmask);

    __nv_bfloat16 *ahi, *alo, *o2hi, *o2lo;
    cudaGetSymbolAddress((void**)&ahi,  g_Ahi);
    cudaGetSymbolAddress((void**)&alo,  g_Alo);
    cudaGetSymbolAddress((void**)&o2hi, g_O2hi);
    cudaGetSymbolAddress((void**)&o2lo, g_O2lo);
    float* gg;
    cudaGetSymbolAddress((void**)&gg, g_g);

    dim3 g1(G_ / 128, rows / 128);        // (16, 128)
    gemm_mma<1><<<g1, 256>>>(ahi, alo, whi, wlo, tlmask, nullptr, nullptr, gg);

    dim3 ga(N_ / 64, H_, B_);             // (8, 8, 32)
    attn_kernel<<<ga, 256>>>(tw, pw, amask, tlmask);

    ln2_kernel<<<rows, 256>>>(tlmask);

    dim3 g2(512 / 128, rows / 128);       // (4, 128)
    gemm_mma<2><<<g2, 256>>>(o2hi, o2lo, w2hi, w2lo, nullptr, out_b, x, out);
}

// round 8
// speedup vs baseline: 3.2327x; 1.2405x over previous
#include <cuda_runtime.h>
#include <cuda_bf16.h>
#include <math.h>
#include <stdint.h>

#define B_  32
#define N_  512
#define F_  512
#define H_  8
#define NB_ 128
#define G_  2048
#define NP1 513

// ---------------- scratch ------------------------------------------------------
__device__ __align__(16) float g_g[(size_t)B_ * N_ * 512];        // u (gated path)
__device__ __align__(16) float g_attn[(size_t)B_ * N_ * 512];
__device__ int   g_ts32[B_ * NP1];
__device__ int   g_tflag[64];
__device__ __align__(16) __nv_bfloat16 g_Ahi[(size_t)B_ * N_ * F_];
__device__ __align__(16) __nv_bfloat16 g_Alo[(size_t)B_ * N_ * F_];
__device__ __align__(16) __nv_bfloat16 g_Whi[(size_t)G_ * F_];    // [n][k]
__device__ __align__(16) __nv_bfloat16 g_Wlo[(size_t)G_ * F_];
__device__ __align__(16) __nv_bfloat16 g_O2hi[(size_t)B_ * N_ * 512];
__device__ __align__(16) __nv_bfloat16 g_O2lo[(size_t)B_ * N_ * 512];
__device__ __align__(16) __nv_bfloat16 g_W2hi[(size_t)512 * 512]; // [n][k]
__device__ __align__(16) __nv_bfloat16 g_W2lo[(size_t)512 * 512];
// head-major qkv, layout [b*H+h][n][64]
__device__ __align__(16) __nv_bfloat16 g_Qhi[(size_t)B_ * H_ * N_ * 64];
__device__ __align__(16) __nv_bfloat16 g_Qlo[(size_t)B_ * H_ * N_ * 64];
__device__ __align__(16) __nv_bfloat16 g_Khi[(size_t)B_ * H_ * N_ * 64];
__device__ __align__(16) __nv_bfloat16 g_Klo[(size_t)B_ * H_ * N_ * 64];
__device__ __align__(16) __nv_bfloat16 g_Vhi[(size_t)B_ * H_ * N_ * 64];
__device__ __align__(16) __nv_bfloat16 g_Vlo[(size_t)B_ * H_ * N_ * 64];

// ---------------- helpers ------------------------------------------------------
__device__ __forceinline__ uint32_t smem_u32(const void* p) {
    uint32_t a;
    asm("{ .reg .u64 t; cvta.to.shared.u64 t, %1; cvt.u32.u64 %0, t; }" : "=r"(a) : "l"(p));
    return a;
}
__device__ __forceinline__ void ldsm_x4(uint32_t* r, uint32_t a) {
    asm volatile("ldmatrix.sync.aligned.m8n8.x4.shared.b16 {%0,%1,%2,%3}, [%4];"
        : "=r"(r[0]), "=r"(r[1]), "=r"(r[2]), "=r"(r[3]) : "r"(a));
}
__device__ __forceinline__ void ldsm_x2(uint32_t* r, uint32_t a) {
    asm volatile("ldmatrix.sync.aligned.m8n8.x2.shared.b16 {%0,%1}, [%2];"
        : "=r"(r[0]), "=r"(r[1]) : "r"(a));
}
__device__ __forceinline__ void ldsm_x2_t(uint32_t* r, uint32_t a) {
    asm volatile("ldmatrix.sync.aligned.m8n8.x2.trans.shared.b16 {%0,%1}, [%2];"
        : "=r"(r[0]), "=r"(r[1]) : "r"(a));
}
__device__ __forceinline__ void mma16816(float* d, const uint32_t* a, const uint32_t* b) {
    asm volatile("mma.sync.aligned.m16n8k16.row.col.f32.bf16.bf16.f32 "
        "{%0,%1,%2,%3}, {%4,%5,%6,%7}, {%8,%9}, {%0,%1,%2,%3};"
        : "+f"(d[0]), "+f"(d[1]), "+f"(d[2]), "+f"(d[3])
        : "r"(a[0]), "r"(a[1]), "r"(a[2]), "r"(a[3]), "r"(b[0]), "r"(b[1]));
}

// ---------------- timestamp canonicalization ----------------------------------
__global__ void ts_fix_kernel(const int* __restrict__ tsraw)
{
    __shared__ int is64;
    if (threadIdx.x == 0) {
        int z = 0;
        #pragma unroll
        for (int i = 1; i < 16; i += 2) z |= tsraw[i];
        is64 = (z == 0) ? 1 : 0;
    }
    __syncthreads();
    int i = blockIdx.x * blockDim.x + threadIdx.x;
    if (i < B_ * NP1) g_ts32[i] = is64 ? tsraw[2 * i] : tsraw[i];
}

// ---------------- per-tile mask flags ------------------------------------------
__global__ void tileflag_kernel(const float* __restrict__ amask)
{
    int t = blockIdx.x;
    int ti = t >> 3, tj = t & 7;
    int any = 0;
    for (int k = threadIdx.x; k < 1024; k += 256) {
        int r = k >> 4, c = (k & 15) * 4;
        float4 v = *(const float4*)(amask + (size_t)(ti * 64 + r) * N_ + tj * 64 + c);
        any |= (v.x != 0.f) | (v.y != 0.f) | (v.z != 0.f) | (v.w != 0.f);
    }
    any = __syncthreads_or(any);
    if (threadIdx.x == 0) g_tflag[t] = any;
}

// ---------------- W transpose + bf16 hi/lo split (generic) ---------------------
__global__ void wprep_kernel(const float* __restrict__ W,
                             __nv_bfloat16* __restrict__ hi,
                             __nv_bfloat16* __restrict__ lo,
                             int ncols)
{
    __shared__ float t[32][33];
    int n0 = blockIdx.x * 32, k0 = blockIdx.y * 32;
    int tx = threadIdx.x, ty = threadIdx.y;   // 32 x 8
    #pragma unroll
    for (int j = 0; j < 4; j++)
        t[ty + j * 8][tx] = W[(size_t)(k0 + ty + j * 8) * ncols + n0 + tx];
    __syncthreads();
    #pragma unroll
    for (int j = 0; j < 4; j++) {
        int row = ty + j * 8;
        float v = t[tx][row];
        __nv_bfloat16 h = __float2bfloat16(v);
        float l = v - __bfloat162float(h);
        size_t o = (size_t)(n0 + row) * F_ + k0 + tx;
        hi[o] = h;
        lo[o] = __float2bfloat16(l);
    }
}

// ---------------- ln1: LayerNorm -> bf16 hi/lo ---------------------------------
__global__ void ln1_kernel(const float* __restrict__ x,
                           const float* __restrict__ tl)
{
    int row = blockIdx.x;
    int tid = threadIdx.x;
    const float* xr = x + (size_t)row * F_;
    float v0 = xr[tid], v1 = xr[tid + 256];
    float s = v0 + v1, sq = v0 * v0 + v1 * v1;
    #pragma unroll
    for (int o = 16; o; o >>= 1) {
        s  += __shfl_down_sync(0xffffffffu, s,  o);
        sq += __shfl_down_sync(0xffffffffu, sq, o);
    }
    __shared__ float red[16];
    __shared__ float mean_s, rstd_s;
    int w = tid >> 5, l = tid & 31;
    if (l == 0) { red[w] = s; red[w + 8] = sq; }
    __syncthreads();
    if (tid == 0) {
        float ts = 0.f, tq = 0.f;
        #pragma unroll
        for (int i = 0; i < 8; i++) { ts += red[i]; tq += red[i + 8]; }
        float m = ts * (1.0f / F_);
        float var = tq * (1.0f / F_) - m * m;
        mean_s = m;
        rstd_s = rsqrtf(var + 1e-6f);
    }
    __syncthreads();
    float t = tl[row];
    float m = mean_s, rs = rstd_s;
    float n0v = (v0 - m) * rs * t;
    float n1v = (v1 - m) * rs * t;
    __nv_bfloat16 h0 = __float2bfloat16(n0v);
    __nv_bfloat16 h1 = __float2bfloat16(n1v);
    size_t o0 = (size_t)row * F_ + tid;
    g_Ahi[o0]       = h0;
    g_Alo[o0]       = __float2bfloat16(n0v - __bfloat162float(h0));
    g_Ahi[o0 + 256] = h1;
    g_Alo[o0 + 256] = __float2bfloat16(n1v - __bfloat162float(h1));
}

// ---------------- ln2: o_input = u*LN(attn)*tl -> bf16 hi/lo -------------------
__global__ void ln2_kernel(const float* __restrict__ tl)
{
    int row = blockIdx.x;
    int tid = threadIdx.x;
    const float* ar = g_attn + (size_t)row * 512;
    float v0 = ar[tid], v1 = ar[tid + 256];
    float s = v0 + v1, sq = v0 * v0 + v1 * v1;
    #pragma unroll
    for (int o = 16; o; o >>= 1) {
        s  += __shfl_down_sync(0xffffffffu, s,  o);
        sq += __shfl_down_sync(0xffffffffu, sq, o);
    }
    __shared__ float red[16];
    __shared__ float mean_s, rstd_s;
    int w = tid >> 5, l = tid & 31;
    if (l == 0) { red[w] = s; red[w + 8] = sq; }
    __syncthreads();
    if (tid == 0) {
        float ts = 0.f, tq = 0.f;
        #pragma unroll
        for (int i = 0; i < 8; i++) { ts += red[i]; tq += red[i + 8]; }
        float m = ts * (1.0f / 512.0f);
        float var = tq * (1.0f / 512.0f) - m * m;
        mean_s = m;
        rstd_s = rsqrtf(var + 1e-6f);
    }
    __syncthreads();
    float t = tl[row];
    float m = mean_s, rs = rstd_s;
    float u0 = g_g[(size_t)row * 512 + tid];
    float u1 = g_g[(size_t)row * 512 + tid + 256];
    float o0 = u0 * (v0 - m) * rs * t;
    float o1 = u1 * (v1 - m) * rs * t;
    __nv_bfloat16 h0 = __float2bfloat16(o0);
    __nv_bfloat16 h1 = __float2bfloat16(o1);
    size_t off = (size_t)row * 512 + tid;
    g_O2hi[off]       = h0;
    g_O2lo[off]       = __float2bfloat16(o0 - __bfloat162float(h0));
    g_O2hi[off + 256] = h1;
    g_O2lo[off + 256] = __float2bfloat16(o1 - __bfloat162float(h1));
}

// ---------------- GEMM via mma.sync bf16, 3-term split -------------------------
// MODE 1: silu(acc)*tl -> u fp32 (cols<512) / qkv bf16 hi/lo head-major (cols>=512)
// MODE 2: acc + bias + xres -> dout (NC=512)
template <int MODE>
__global__ void __launch_bounds__(256)
gemm_mma(const __nv_bfloat16* __restrict__ Ahi, const __nv_bfloat16* __restrict__ Alo,
         const __nv_bfloat16* __restrict__ Bhi, const __nv_bfloat16* __restrict__ Blo,
         const float* __restrict__ tl, const float* __restrict__ bias,
         const float* __restrict__ xres, float* __restrict__ Cout)
{
    constexpr int LDS = 40;

    __shared__ __align__(16) __nv_bfloat16 sAhi[128 * LDS];
    __shared__ __align__(16) __nv_bfloat16 sAlo[128 * LDS];
    __shared__ __align__(16) __nv_bfloat16 sBhi[128 * LDS];
    __shared__ __align__(16) __nv_bfloat16 sBlo[128 * LDS];

    const int tid = threadIdx.x, lane = tid & 31, wid = tid >> 5;
    const int wr = wid & 3, wc = wid >> 2;
    const int m0 = blockIdx.y * 128, n0 = blockIdx.x * 128;

    const uint32_t bAhi = smem_u32(sAhi), bAlo = smem_u32(sAlo);
    const uint32_t bBhi = smem_u32(sBhi), bBlo = smem_u32(sBlo);

    float d[2][8][4] = {};

    for (int kc = 0; kc < 16; kc++) {
        const int k0 = kc * 32;
        __syncthreads();
        #pragma unroll
        for (int it = 0; it < 2; it++) {
            int idx = tid + it * 256;
            int r = idx >> 2, c = (idx & 3) * 8;
            size_t asrc = (size_t)(m0 + r) * F_ + k0 + c;
            size_t bsrc = (size_t)(n0 + r) * F_ + k0 + c;
            *(float4*)&sAhi[r * LDS + c] = *(const float4*)(Ahi + asrc);
            *(float4*)&sAlo[r * LDS + c] = *(const float4*)(Alo + asrc);
            *(float4*)&sBhi[r * LDS + c] = *(const float4*)(Bhi + bsrc);
            *(float4*)&sBlo[r * LDS + c] = *(const float4*)(Blo + bsrc);
        }
        __syncthreads();

        #pragma unroll
        for (int ks = 0; ks < 2; ks++) {
            uint32_t ahi[2][4], alo[2][4], bhi[8][2], blo[8][2];
            #pragma unroll
            for (int mi = 0; mi < 2; mi++) {
                int row = wr * 32 + mi * 16 + (lane & 15);
                uint32_t off = (uint32_t)(row * LDS + ks * 16 + (lane >> 4) * 8) * 2;
                ldsm_x4(ahi[mi], bAhi + off);
                ldsm_x4(alo[mi], bAlo + off);
            }
            #pragma unroll
            for (int ni = 0; ni < 8; ni++) {
                int row = wc * 64 + ni * 8 + (lane & 7);
                uint32_t off = (uint32_t)(row * LDS + ks * 16 + ((lane >> 3) & 1) * 8) * 2;
                ldsm_x2(bhi[ni], bBhi + off);
                ldsm_x2(blo[ni], bBlo + off);
            }
            #pragma unroll
            for (int mi = 0; mi < 2; mi++)
                #pragma unroll
                for (int ni = 0; ni < 8; ni++) {
                    mma16816(d[mi][ni], ahi[mi], bhi[ni]);
                    mma16816(d[mi][ni], ahi[mi], blo[ni]);
                    mma16816(d[mi][ni], alo[mi], bhi[ni]);
                }
        }
    }

    #pragma unroll
    for (int mi = 0; mi < 2; mi++) {
        int rbase = m0 + wr * 32 + mi * 16 + (lane >> 2);
        #pragma unroll
        for (int half = 0; half < 2; half++) {
            int row = rbase + half * 8;
            float tlv = (MODE == 1) ? tl[row] : 0.0f;
            #pragma unroll
            for (int ni = 0; ni < 8; ni++) {
                int col = n0 + wc * 64 + ni * 8 + (lane & 3) * 2;
                float v0 = d[mi][ni][half * 2 + 0];
                float v1 = d[mi][ni][half * 2 + 1];
                if (MODE == 1) {
                    v0 = __fdividef(v0, 1.0f + __expf(-v0)) * tlv;
                    v1 = __fdividef(v1, 1.0f + __expf(-v1)) * tlv;
                    if (col < 512) {
                        *(float2*)(g_g + (size_t)row * 512 + col) = make_float2(v0, v1);
                    } else {
                        __nv_bfloat16 h0 = __float2bfloat16(v0);
                        __nv_bfloat16 h1 = __float2bfloat16(v1);
                        __nv_bfloat162 hp, lp;
                        hp.x = h0; hp.y = h1;
                        lp.x = __float2bfloat16(v0 - __bfloat162float(h0));
                        lp.y = __float2bfloat16(v1 - __bfloat162float(h1));
                        int hh = (col >> 6) & 7;
                        int dd = col & 63;
                        size_t off = (((size_t)(row >> 9) * H_ + hh) * N_ + (row & 511)) * 64 + dd;
                        if (col < 1024) {
                            *(__nv_bfloat162*)(g_Vhi + off) = hp;
                            *(__nv_bfloat162*)(g_Vlo + off) = lp;
                        } else if (col < 1536) {
                            *(__nv_bfloat162*)(g_Qhi + off) = hp;
                            *(__nv_bfloat162*)(g_Qlo + off) = lp;
                        } else {
                            *(__nv_bfloat162*)(g_Khi + off) = hp;
                            *(__nv_bfloat162*)(g_Klo + off) = lp;
                        }
                    }
                } else {
                    v0 += bias[col]     + xres[(size_t)row * 512 + col];
                    v1 += bias[col + 1] + xres[(size_t)row * 512 + col + 1];
                    *(float2*)(Cout + (size_t)row * 512 + col) = make_float2(v0, v1);
                }
            }
        }
    }
}

// ---------------- tensor-core attention ----------------------------------------
#define DS    72
#define SQHI  0
#define SQLO  9216
#define SKHI  18432
#define SKLO  27648
#define SVHI  36864
#define SVLO  46080
#define SPHI  55296
#define SPLO  64512
#define STSN  73728
#define STLN  73984
#define STSM  74240
#define STLM  74496
#define ATT_SMEM 74752

__global__ void __launch_bounds__(128)
attn_tc(const float* __restrict__ tw, const float* __restrict__ pw,
        const float* __restrict__ amask, const float* __restrict__ tl)
{
    extern __shared__ __align__(16) char sm[];
    const uint32_t sb = smem_u32(sm);
    const int tid = threadIdx.x, lane = tid & 31, w = tid >> 5;
    const int n0 = blockIdx.x * 64, h = blockIdx.y, b = blockIdx.z;
    const int bh = b * H_ + h;

    // Q hi/lo -> smem
    #pragma unroll
    for (int it = 0; it < 4; it++) {
        int idx = tid + it * 128;          // 0..511 float4 granules
        int r = idx >> 3, c = (idx & 7) * 8;
        size_t src = ((size_t)bh * N_ + n0 + r) * 64 + c;
        *(float4*)(sm + SQHI + (r * DS + c) * 2) = *(const float4*)(g_Qhi + src);
        *(float4*)(sm + SQLO + (r * DS + c) * 2) = *(const float4*)(g_Qlo + src);
    }
    if (tid < 64) {
        *(int*)(sm + STSN + tid * 4)   = g_ts32[b * NP1 + n0 + tid + 1];
        *(float*)(sm + STLN + tid * 4) = tl[b * N_ + n0 + tid];
    }

    float o[8][4] = {};
    const int tr = n0 >> 6;

    for (int m0 = 0; m0 < N_; m0 += 64) {
        if (!g_tflag[tr * 8 + (m0 >> 6)]) continue;
        __syncthreads();
        #pragma unroll
        for (int it = 0; it < 4; it++) {
            int idx = tid + it * 128;
            int r = idx >> 3, c = (idx & 7) * 8;
            size_t src = ((size_t)bh * N_ + m0 + r) * 64 + c;
            *(float4*)(sm + SKHI + (r * DS + c) * 2) = *(const float4*)(g_Khi + src);
            *(float4*)(sm + SKLO + (r * DS + c) * 2) = *(const float4*)(g_Klo + src);
            *(float4*)(sm + SVHI + (r * DS + c) * 2) = *(const float4*)(g_Vhi + src);
            *(float4*)(sm + SVLO + (r * DS + c) * 2) = *(const float4*)(g_Vlo + src);
        }
        if (tid < 64) {
            *(int*)(sm + STSM + tid * 4)   = g_ts32[b * NP1 + m0 + tid];
            *(float*)(sm + STLM + tid * 4) = tl[b * N_ + m0 + tid];
        }
        __syncthreads();

        // phase A: S = Q K^T (3-term split)
        float s[8][4] = {};
        #pragma unroll
        for (int ks = 0; ks < 4; ks++) {
            uint32_t qhi[4], qlo[4];
            int arow = w * 16 + (lane & 15);
            uint32_t aoff = (uint32_t)(arow * DS + ks * 16 + (lane >> 4) * 8) * 2;
            ldsm_x4(qhi, sb + SQHI + aoff);
            ldsm_x4(qlo, sb + SQLO + aoff);
            #pragma unroll
            for (int ni = 0; ni < 8; ni++) {
                uint32_t khi[2], klo[2];
                int brow = ni * 8 + (lane & 7);
                uint32_t boff = (uint32_t)(brow * DS + ks * 16 + ((lane >> 3) & 1) * 8) * 2;
                ldsm_x2(khi, sb + SKHI + boff);
                ldsm_x2(klo, sb + SKLO + boff);
                mma16816(s[ni], qhi, khi);
                mma16816(s[ni], qhi, klo);
                mma16816(s[ni], qlo, khi);
            }
        }

        // epilogue -> P hi/lo (warp-private rows)
        #pragma unroll
        for (int half = 0; half < 2; half++) {
            int r = w * 16 + (lane >> 2) + half * 8;
            int n = n0 + r;
            int tn = *(const int*)(sm + STSN + r * 4);
            float tlnv = *(const float*)(sm + STLN + r * 4);
            #pragma unroll
            for (int ni = 0; ni < 8; ni++) {
                int c = ni * 8 + (lane & 3) * 2;
                int m = m0 + c;
                float2 am = *(const float2*)(amask + (size_t)n * N_ + m);
                int dt0 = tn - *(const int*)(sm + STSM + c * 4);
                int dt1 = tn - *(const int*)(sm + STSM + c * 4 + 4);
                float ad0 = fmaxf(fabsf((float)dt0), 1.0f);
                float ad1 = fmaxf(fabsf((float)dt1), 1.0f);
                int bk0 = min(max((int)(__logf(ad0) * (1.0f / 0.301f)), 0), NB_);
                int bk1 = min(max((int)(__logf(ad1) * (1.0f / 0.301f)), 0), NB_);
                float x0 = s[ni][half * 2 + 0] + tw[bk0] + pw[N_ - 1 + m - n];
                float x1 = s[ni][half * 2 + 1] + tw[bk1] + pw[N_ + m - n];
                x0 = __fdividef(x0, 1.0f + __expf(-x0)) * (1.0f / (float)N_);
                x1 = __fdividef(x1, 1.0f + __expf(-x1)) * (1.0f / (float)N_);
                x0 *= am.x * *(const float*)(sm + STLM + c * 4)     * tlnv;
                x1 *= am.y * *(const float*)(sm + STLM + c * 4 + 4) * tlnv;
                __nv_bfloat16 h0 = __float2bfloat16(x0);
                __nv_bfloat16 h1 = __float2bfloat16(x1);
                __nv_bfloat162 hp, lp;
                hp.x = h0; hp.y = h1;
                lp.x = __float2bfloat16(x0 - __bfloat162float(h0));
                lp.y = __float2bfloat16(x1 - __bfloat162float(h1));
                *(uint32_t*)(sm + SPHI + (r * DS + c) * 2) = *(uint32_t*)&hp;
                *(uint32_t*)(sm + SPLO + (r * DS + c) * 2) = *(uint32_t*)&lp;
            }
        }
        __syncwarp();

        // PV: O += P V (3-term split); V via ldmatrix.trans
        #pragma unroll
        for (int ks = 0; ks < 4; ks++) {
            uint32_t phi[4], plo[4];
            int arow = w * 16 + (lane & 15);
            uint32_t aoff = (uint32_t)(arow * DS + ks * 16 + (lane >> 4) * 8) * 2;
            ldsm_x4(phi, sb + SPHI + aoff);
            ldsm_x4(plo, sb + SPLO + aoff);
            #pragma unroll
            for (int ni = 0; ni < 8; ni++) {
                uint32_t vhi[2], vlo[2];
                int vrow = ks * 16 + (lane & 15);
                uint32_t voff = (uint32_t)(vrow * DS + ni * 8) * 2;
                ldsm_x2_t(vhi, sb + SVHI + voff);
                ldsm_x2_t(vlo, sb + SVLO + voff);
                mma16816(o[ni], phi, vhi);
                mma16816(o[ni], phi, vlo);
                mma16816(o[ni], plo, vhi);
            }
        }
    }

    #pragma unroll
    for (int half = 0; half < 2; half++) {
        int r = w * 16 + (lane >> 2) + half * 8;
        int n = n0 + r;
        #pragma unroll
        for (int ni = 0; ni < 8; ni++) {
            int c = ni * 8 + (lane & 3) * 2;
            *(float2*)(g_attn + ((size_t)(b * N_ + n)) * 512 + h * 64 + c) =
                make_float2(o[ni][half * 2], o[ni][half * 2 + 1]);
        }
    }
}

// ---------------- launch -------------------------------------------------------
extern "C" void kernel_launch(void* const* d_in, const int* in_sizes, int n_in,
                              void* d_out, int out_size)
{
    const float* x      = (const float*)d_in[0];
    const float* tlmask = (const float*)d_in[1];
    const float* amask  = (const float*)d_in[2];
    const float* uvqk   = (const float*)d_in[3];
    const float* out_w  = (const float*)d_in[4];
    const float* out_b  = (const float*)d_in[5];
    const float* tw     = (const float*)d_in[6];
    const float* pw     = (const float*)d_in[7];
    const int*   tsraw  = (const int*)d_in[8];
    float*       out    = (float*)d_out;

    const int rows = B_ * N_;   // 16384

    ts_fix_kernel<<<(B_ * NP1 + 255) / 256, 256>>>(tsraw);
    tileflag_kernel<<<64, 256>>>(amask);

    __nv_bfloat16 *whi, *wlo, *w2hi, *w2lo;
    cudaGetSymbolAddress((void**)&whi,  g_Whi);
    cudaGetSymbolAddress((void**)&wlo,  g_Wlo);
    cudaGetSymbolAddress((void**)&w2hi, g_W2hi);
    cudaGetSymbolAddress((void**)&w2lo, g_W2lo);

    wprep_kernel<<<dim3(G_ / 32, F_ / 32), dim3(32, 8)>>>(uvqk, whi, wlo, G_);
    wprep_kernel<<<dim3(512 / 32, F_ / 32), dim3(32, 8)>>>(out_w, w2hi, w2lo, 512);

    ln1_kernel<<<rows, 256>>>(x, tlmask);

    __nv_bfloat16 *ahi, *alo, *o2hi, *o2lo;
    cudaGetSymbolAddress((void**)&ahi,  g_Ahi);
    cudaGetSymbolAddress((void**)&alo,  g_Alo);
    cudaGetSymbolAddress((void**)&o2hi, g_O2hi);
    cudaGetSymbolAddress((void**)&o2lo, g_O2lo);

    dim3 g1(G_ / 128, rows / 128);        // (16, 128)
    gemm_mma<1><<<g1, 256>>>(ahi, alo, whi, wlo, tlmask, nullptr, nullptr, nullptr);

    cudaFuncSetAttribute(attn_tc, cudaFuncAttributeMaxDynamicSharedMemorySize, ATT_SMEM);
    dim3 ga(N_ / 64, H_, B_);             // (8, 8, 32)
    attn_tc<<<ga, 128, ATT_SMEM>>>(tw, pw, amask, tlmask);

    ln2_kernel<<<rows, 256>>>(tlmask);

    dim3 g2(512 / 128, rows / 128);       // (4, 128)
    gemm_mma<2><<<g2, 256>>>(o2hi, o2lo, w2hi, w2lo, nullptr, out_b, x, out);
}

// round 9
// speedup vs baseline: 3.2336x; 1.0003x over previous
#include <cuda_runtime.h>
#include <cuda_bf16.h>
#include <math.h>
#include <stdint.h>

#define B_  32
#define N_  512
#define F_  512
#define H_  8
#define NB_ 128
#define G_  2048
#define NP1 513

// ---------------- scratch ------------------------------------------------------
__device__ __align__(16) float g_g[(size_t)B_ * N_ * 512];        // u (gated path)
__device__ __align__(16) float g_attn[(size_t)B_ * N_ * 512];
__device__ int   g_ts32[B_ * NP1];
__device__ int   g_tflag[64];
__device__ __align__(16) __nv_bfloat16 g_Ahi[(size_t)B_ * N_ * F_];
__device__ __align__(16) __nv_bfloat16 g_Alo[(size_t)B_ * N_ * F_];
__device__ __align__(16) __nv_bfloat16 g_Whi[(size_t)G_ * F_];    // [n][k]
__device__ __align__(16) __nv_bfloat16 g_Wlo[(size_t)G_ * F_];
__device__ __align__(16) __nv_bfloat16 g_O2hi[(size_t)B_ * N_ * 512];
__device__ __align__(16) __nv_bfloat16 g_O2lo[(size_t)B_ * N_ * 512];
__device__ __align__(16) __nv_bfloat16 g_W2hi[(size_t)512 * 512]; // [n][k]
__device__ __align__(16) __nv_bfloat16 g_W2lo[(size_t)512 * 512];
// head-major qkv, layout [b*H+h][n][64]
__device__ __align__(16) __nv_bfloat16 g_Qhi[(size_t)B_ * H_ * N_ * 64];
__device__ __align__(16) __nv_bfloat16 g_Qlo[(size_t)B_ * H_ * N_ * 64];
__device__ __align__(16) __nv_bfloat16 g_Khi[(size_t)B_ * H_ * N_ * 64];
__device__ __align__(16) __nv_bfloat16 g_Klo[(size_t)B_ * H_ * N_ * 64];
__device__ __align__(16) __nv_bfloat16 g_Vhi[(size_t)B_ * H_ * N_ * 64];
__device__ __align__(16) __nv_bfloat16 g_Vlo[(size_t)B_ * H_ * N_ * 64];

// ---------------- helpers ------------------------------------------------------
__device__ __forceinline__ uint32_t smem_u32(const void* p) {
    uint32_t a;
    asm("{ .reg .u64 t; cvta.to.shared.u64 t, %1; cvt.u32.u64 %0, t; }" : "=r"(a) : "l"(p));
    return a;
}
__device__ __forceinline__ void cpa16(uint32_t dst, const void* src) {
    asm volatile("cp.async.cg.shared.global [%0], [%1], 16;" :: "r"(dst), "l"(src));
}
__device__ __forceinline__ void cpa_commit() { asm volatile("cp.async.commit_group;" ::: "memory"); }
__device__ __forceinline__ void cpa_wait1()  { asm volatile("cp.async.wait_group 1;" ::: "memory"); }
__device__ __forceinline__ void cpa_wait0()  { asm volatile("cp.async.wait_group 0;" ::: "memory"); }
__device__ __forceinline__ void ldsm_x4(uint32_t* r, uint32_t a) {
    asm volatile("ldmatrix.sync.aligned.m8n8.x4.shared.b16 {%0,%1,%2,%3}, [%4];"
        : "=r"(r[0]), "=r"(r[1]), "=r"(r[2]), "=r"(r[3]) : "r"(a));
}
__device__ __forceinline__ void ldsm_x2(uint32_t* r, uint32_t a) {
    asm volatile("ldmatrix.sync.aligned.m8n8.x2.shared.b16 {%0,%1}, [%2];"
        : "=r"(r[0]), "=r"(r[1]) : "r"(a));
}
__device__ __forceinline__ void ldsm_x2_t(uint32_t* r, uint32_t a) {
    asm volatile("ldmatrix.sync.aligned.m8n8.x2.trans.shared.b16 {%0,%1}, [%2];"
        : "=r"(r[0]), "=r"(r[1]) : "r"(a));
}
__device__ __forceinline__ void mma16816(float* d, const uint32_t* a, const uint32_t* b) {
    asm volatile("mma.sync.aligned.m16n8k16.row.col.f32.bf16.bf16.f32 "
        "{%0,%1,%2,%3}, {%4,%5,%6,%7}, {%8,%9}, {%0,%1,%2,%3};"
        : "+f"(d[0]), "+f"(d[1]), "+f"(d[2]), "+f"(d[3])
        : "r"(a[0]), "r"(a[1]), "r"(a[2]), "r"(a[3]), "r"(b[0]), "r"(b[1]));
}

// ---------------- timestamp canonicalization ----------------------------------
__global__ void ts_fix_kernel(const int* __restrict__ tsraw)
{
    __shared__ int is64;
    if (threadIdx.x == 0) {
        int z = 0;
        #pragma unroll
        for (int i = 1; i < 16; i += 2) z |= tsraw[i];
        is64 = (z == 0) ? 1 : 0;
    }
    __syncthreads();
    int i = blockIdx.x * blockDim.x + threadIdx.x;
    if (i < B_ * NP1) g_ts32[i] = is64 ? tsraw[2 * i] : tsraw[i];
}

// ---------------- per-tile mask flags ------------------------------------------
__global__ void tileflag_kernel(const float* __restrict__ amask)
{
    int t = blockIdx.x;
    int ti = t >> 3, tj = t & 7;
    int any = 0;
    for (int k = threadIdx.x; k < 1024; k += 256) {
        int r = k >> 4, c = (k & 15) * 4;
        float4 v = *(const float4*)(amask + (size_t)(ti * 64 + r) * N_ + tj * 64 + c);
        any |= (v.x != 0.f) | (v.y != 0.f) | (v.z != 0.f) | (v.w != 0.f);
    }
    any = __syncthreads_or(any);
    if (threadIdx.x == 0) g_tflag[t] = any;
}

// ---------------- W transpose + bf16 hi/lo split -------------------------------
__global__ void wprep_kernel(const float* __restrict__ W,
                             __nv_bfloat16* __restrict__ hi,
                             __nv_bfloat16* __restrict__ lo,
                             int ncols)
{
    __shared__ float t[32][33];
    int n0 = blockIdx.x * 32, k0 = blockIdx.y * 32;
    int tx = threadIdx.x, ty = threadIdx.y;   // 32 x 8
    #pragma unroll
    for (int j = 0; j < 4; j++)
        t[ty + j * 8][tx] = W[(size_t)(k0 + ty + j * 8) * ncols + n0 + tx];
    __syncthreads();
    #pragma unroll
    for (int j = 0; j < 4; j++) {
        int row = ty + j * 8;
        float v = t[tx][row];
        __nv_bfloat16 h = __float2bfloat16(v);
        float l = v - __bfloat162float(h);
        size_t o = (size_t)(n0 + row) * F_ + k0 + tx;
        hi[o] = h;
        lo[o] = __float2bfloat16(l);
    }
}

// ---------------- ln1: LayerNorm -> bf16 hi/lo ---------------------------------
__global__ void ln1_kernel(const float* __restrict__ x,
                           const float* __restrict__ tl)
{
    int row = blockIdx.x;
    int tid = threadIdx.x;
    const float* xr = x + (size_t)row * F_;
    float v0 = xr[tid], v1 = xr[tid + 256];
    float s = v0 + v1, sq = v0 * v0 + v1 * v1;
    #pragma unroll
    for (int o = 16; o; o >>= 1) {
        s  += __shfl_down_sync(0xffffffffu, s,  o);
        sq += __shfl_down_sync(0xffffffffu, sq, o);
    }
    __shared__ float red[16];
    __shared__ float mean_s, rstd_s;
    int w = tid >> 5, l = tid & 31;
    if (l == 0) { red[w] = s; red[w + 8] = sq; }
    __syncthreads();
    if (tid == 0) {
        float ts = 0.f, tq = 0.f;
        #pragma unroll
        for (int i = 0; i < 8; i++) { ts += red[i]; tq += red[i + 8]; }
        float m = ts * (1.0f / F_);
        float var = tq * (1.0f / F_) - m * m;
        mean_s = m;
        rstd_s = rsqrtf(var + 1e-6f);
    }
    __syncthreads();
    float t = tl[row];
    float m = mean_s, rs = rstd_s;
    float n0v = (v0 - m) * rs * t;
    float n1v = (v1 - m) * rs * t;
    __nv_bfloat16 h0 = __float2bfloat16(n0v);
    __nv_bfloat16 h1 = __float2bfloat16(n1v);
    size_t o0 = (size_t)row * F_ + tid;
    g_Ahi[o0]       = h0;
    g_Alo[o0]       = __float2bfloat16(n0v - __bfloat162float(h0));
    g_Ahi[o0 + 256] = h1;
    g_Alo[o0 + 256] = __float2bfloat16(n1v - __bfloat162float(h1));
}

// ---------------- ln2: o_input = u*LN(attn)*tl -> bf16 hi/lo -------------------
__global__ void ln2_kernel(const float* __restrict__ tl)
{
    int row = blockIdx.x;
    int tid = threadIdx.x;
    const float* ar = g_attn + (size_t)row * 512;
    float v0 = ar[tid], v1 = ar[tid + 256];
    float s = v0 + v1, sq = v0 * v0 + v1 * v1;
    #pragma unroll
    for (int o = 16; o; o >>= 1) {
        s  += __shfl_down_sync(0xffffffffu, s,  o);
        sq += __shfl_down_sync(0xffffffffu, sq, o);
    }
    __shared__ float red[16];
    __shared__ float mean_s, rstd_s;
    int w = tid >> 5, l = tid & 31;
    if (l == 0) { red[w] = s; red[w + 8] = sq; }
    __syncthreads();
    if (tid == 0) {
        float ts = 0.f, tq = 0.f;
        #pragma unroll
        for (int i = 0; i < 8; i++) { ts += red[i]; tq += red[i + 8]; }
        float m = ts * (1.0f / 512.0f);
        float var = tq * (1.0f / 512.0f) - m * m;
        mean_s = m;
        rstd_s = rsqrtf(var + 1e-6f);
    }
    __syncthreads();
    float t = tl[row];
    float m = mean_s, rs = rstd_s;
    float u0 = g_g[(size_t)row * 512 + tid];
    float u1 = g_g[(size_t)row * 512 + tid + 256];
    float o0 = u0 * (v0 - m) * rs * t;
    float o1 = u1 * (v1 - m) * rs * t;
    __nv_bfloat16 h0 = __float2bfloat16(o0);
    __nv_bfloat16 h1 = __float2bfloat16(o1);
    size_t off = (size_t)row * 512 + tid;
    g_O2hi[off]       = h0;
    g_O2lo[off]       = __float2bfloat16(o0 - __bfloat162float(h0));
    g_O2hi[off + 256] = h1;
    g_O2lo[off + 256] = __float2bfloat16(o1 - __bfloat162float(h1));
}

// ---------------- GEMM via mma.sync bf16, 3-term split, cp.async 2-stage -------
// smem stage layout (per stage 40960 B): Ahi +0, Alo +10240, Bhi +20480, Blo +30720
#define GST 40960
#define GEMM_SMEM (2 * GST)

template <int MODE>
__global__ void __launch_bounds__(256)
gemm_mma(const __nv_bfloat16* __restrict__ Ahi, const __nv_bfloat16* __restrict__ Alo,
         const __nv_bfloat16* __restrict__ Bhi, const __nv_bfloat16* __restrict__ Blo,
         const float* __restrict__ tl, const float* __restrict__ bias,
         const float* __restrict__ xres, float* __restrict__ Cout)
{
    constexpr int LDS = 40;
    extern __shared__ __align__(16) char dsm[];
    const uint32_t sb = smem_u32(dsm);

    const int tid = threadIdx.x, lane = tid & 31, wid = tid >> 5;
    const int wr = wid & 3, wc = wid >> 2;
    const int m0 = blockIdx.y * 128, n0 = blockIdx.x * 128;

    float d[2][8][4] = {};

    // stage loader: 128x32 bf16 of each of 4 arrays
    auto load_stage = [&](int kc, int st) {
        const int k0 = kc * 32;
        const uint32_t base = sb + st * GST;
        #pragma unroll
        for (int it = 0; it < 2; it++) {
            int idx = tid + it * 256;
            int r = idx >> 2, c = (idx & 3) * 8;
            uint32_t doff = (uint32_t)(r * LDS + c) * 2;
            size_t asrc = (size_t)(m0 + r) * F_ + k0 + c;
            size_t bsrc = (size_t)(n0 + r) * F_ + k0 + c;
            cpa16(base + doff,         Ahi + asrc);
            cpa16(base + 10240 + doff, Alo + asrc);
            cpa16(base + 20480 + doff, Bhi + bsrc);
            cpa16(base + 30720 + doff, Blo + bsrc);
        }
        cpa_commit();
    };

    load_stage(0, 0);

    for (int kc = 0; kc < 16; kc++) {
        if (kc < 15) { load_stage(kc + 1, (kc + 1) & 1); cpa_wait1(); }
        else         { cpa_wait0(); }
        __syncthreads();

        const uint32_t base = sb + (kc & 1) * GST;
        #pragma unroll
        for (int ks = 0; ks < 2; ks++) {
            uint32_t ahi[2][4], alo[2][4], bhi[8][2], blo[8][2];
            #pragma unroll
            for (int mi = 0; mi < 2; mi++) {
                int row = wr * 32 + mi * 16 + (lane & 15);
                uint32_t off = (uint32_t)(row * LDS + ks * 16 + (lane >> 4) * 8) * 2;
                ldsm_x4(ahi[mi], base + off);
                ldsm_x4(alo[mi], base + 10240 + off);
            }
            #pragma unroll
            for (int ni = 0; ni < 8; ni++) {
                int row = wc * 64 + ni * 8 + (lane & 7);
                uint32_t off = (uint32_t)(row * LDS + ks * 16 + ((lane >> 3) & 1) * 8) * 2;
                ldsm_x2(bhi[ni], base + 20480 + off);
                ldsm_x2(blo[ni], base + 30720 + off);
            }
            #pragma unroll
            for (int mi = 0; mi < 2; mi++)
                #pragma unroll
                for (int ni = 0; ni < 8; ni++) {
                    mma16816(d[mi][ni], ahi[mi], bhi[ni]);
                    mma16816(d[mi][ni], ahi[mi], blo[ni]);
                    mma16816(d[mi][ni], alo[mi], bhi[ni]);
                }
        }
        __syncthreads();   // stage (kc&1) free for reuse by load at kc+1's issue of kc+2
    }

    #pragma unroll
    for (int mi = 0; mi < 2; mi++) {
        int rbase = m0 + wr * 32 + mi * 16 + (lane >> 2);
        #pragma unroll
        for (int half = 0; half < 2; half++) {
            int row = rbase + half * 8;
            float tlv = (MODE == 1) ? tl[row] : 0.0f;
            #pragma unroll
            for (int ni = 0; ni < 8; ni++) {
                int col = n0 + wc * 64 + ni * 8 + (lane & 3) * 2;
                float v0 = d[mi][ni][half * 2 + 0];
                float v1 = d[mi][ni][half * 2 + 1];
                if (MODE == 1) {
                    v0 = __fdividef(v0, 1.0f + __expf(-v0)) * tlv;
                    v1 = __fdividef(v1, 1.0f + __expf(-v1)) * tlv;
                    if (col < 512) {
                        *(float2*)(g_g + (size_t)row * 512 + col) = make_float2(v0, v1);
                    } else {
                        __nv_bfloat16 h0 = __float2bfloat16(v0);
                        __nv_bfloat16 h1 = __float2bfloat16(v1);
                        __nv_bfloat162 hp, lp;
                        hp.x = h0; hp.y = h1;
                        lp.x = __float2bfloat16(v0 - __bfloat162float(h0));
                        lp.y = __float2bfloat16(v1 - __bfloat162float(h1));
                        int hh = (col >> 6) & 7;
                        int dd = col & 63;
                        size_t off = (((size_t)(row >> 9) * H_ + hh) * N_ + (row & 511)) * 64 + dd;
                        if (col < 1024) {
                            *(__nv_bfloat162*)(g_Vhi + off) = hp;
                            *(__nv_bfloat162*)(g_Vlo + off) = lp;
                        } else if (col < 1536) {
                            *(__nv_bfloat162*)(g_Qhi + off) = hp;
                            *(__nv_bfloat162*)(g_Qlo + off) = lp;
                        } else {
                            *(__nv_bfloat162*)(g_Khi + off) = hp;
                            *(__nv_bfloat162*)(g_Klo + off) = lp;
                        }
                    }
                } else {
                    v0 += bias[col]     + xres[(size_t)row * 512 + col];
                    v1 += bias[col + 1] + xres[(size_t)row * 512 + col + 1];
                    *(float2*)(Cout + (size_t)row * 512 + col) = make_float2(v0, v1);
                }
            }
        }
    }
}

// ---------------- tensor-core attention, cp.async 2-stage KV -------------------
#define DS    72
// dynamic smem layout:
#define SQHI  0
#define SQLO  9216
#define SKV0  18432          // stage base; per stage: Khi+0, Klo+9216, Vhi+18432, Vlo+27648
#define KVST  36864
#define SPHI  (SKV0 + 2 * KVST)          // 92160
#define SPLO  (SPHI + 9216)              // 101376
#define ATT_SMEM (SPLO + 9216)           // 110592

__global__ void __launch_bounds__(128)
attn_tc(const float* __restrict__ tw, const float* __restrict__ pw,
        const float* __restrict__ amask, const float* __restrict__ tl)
{
    extern __shared__ __align__(16) char sm[];
    const uint32_t sb = smem_u32(sm);
    const int tid = threadIdx.x, lane = tid & 31, w = tid >> 5;
    const int n0 = blockIdx.x * 64, h = blockIdx.y, b = blockIdx.z;
    const int bh = b * H_ + h;

    // Q hi/lo -> smem (plain stores; first pipeline barrier covers visibility)
    #pragma unroll
    for (int it = 0; it < 4; it++) {
        int idx = tid + it * 128;
        int r = idx >> 3, c = (idx & 7) * 8;
        size_t src = ((size_t)bh * N_ + n0 + r) * 64 + c;
        *(float4*)(sm + SQHI + (r * DS + c) * 2) = *(const float4*)(g_Qhi + src);
        *(float4*)(sm + SQLO + (r * DS + c) * 2) = *(const float4*)(g_Qlo + src);
    }

    // active tile list (uniform across block)
    int mlist[8];
    int nact = 0;
    const int tr = n0 >> 6;
    #pragma unroll
    for (int t = 0; t < 8; t++)
        if (g_tflag[tr * 8 + t]) mlist[nact++] = t * 64;

    auto load_kv = [&](int m0, int st) {
        const uint32_t base = sb + SKV0 + st * KVST;
        #pragma unroll
        for (int it = 0; it < 4; it++) {
            int idx = tid + it * 128;
            int r = idx >> 3, c = (idx & 7) * 8;
            uint32_t doff = (uint32_t)(r * DS + c) * 2;
            size_t src = ((size_t)bh * N_ + m0 + r) * 64 + c;
            cpa16(base + doff,         g_Khi + src);
            cpa16(base + 9216  + doff, g_Klo + src);
            cpa16(base + 18432 + doff, g_Vhi + src);
            cpa16(base + 27648 + doff, g_Vlo + src);
        }
        cpa_commit();
    };

    float o[8][4] = {};

    if (nact > 0) load_kv(mlist[0], 0);

    for (int i = 0; i < nact; i++) {
        if (i + 1 < nact) { load_kv(mlist[i + 1], (i + 1) & 1); cpa_wait1(); }
        else              { cpa_wait0(); }
        __syncthreads();

        const int m0 = mlist[i];
        const uint32_t kb = sb + SKV0 + (i & 1) * KVST;

        // phase A: S = Q K^T (3-term split)
        float s[8][4] = {};
        #pragma unroll
        for (int ks = 0; ks < 4; ks++) {
            uint32_t qhi[4], qlo[4];
            int arow = w * 16 + (lane & 15);
            uint32_t aoff = (uint32_t)(arow * DS + ks * 16 + (lane >> 4) * 8) * 2;
            ldsm_x4(qhi, sb + SQHI + aoff);
            ldsm_x4(qlo, sb + SQLO + aoff);
            #pragma unroll
            for (int ni = 0; ni < 8; ni++) {
                uint32_t khi[2], klo[2];
                int brow = ni * 8 + (lane & 7);
                uint32_t boff = (uint32_t)(brow * DS + ks * 16 + ((lane >> 3) & 1) * 8) * 2;
                ldsm_x2(khi, kb + boff);
                ldsm_x2(klo, kb + 9216 + boff);
                mma16816(s[ni], qhi, khi);
                mma16816(s[ni], qhi, klo);
                mma16816(s[ni], qlo, khi);
            }
        }

        // epilogue -> P hi/lo (warp-private rows); ts/tl/amask direct from global (L1/L2 cached)
        #pragma unroll
        for (int half = 0; half < 2; half++) {
            int r = w * 16 + (lane >> 2) + half * 8;
            int n = n0 + r;
            int tn = g_ts32[b * NP1 + n + 1];
            float tlnv = tl[b * N_ + n];
            #pragma unroll
            for (int ni = 0; ni < 8; ni++) {
                int c = ni * 8 + (lane & 3) * 2;
                int m = m0 + c;
                float2 am = *(const float2*)(amask + (size_t)n * N_ + m);
                int dt0 = tn - g_ts32[b * NP1 + m];
                int dt1 = tn - g_ts32[b * NP1 + m + 1];
                float ad0 = fmaxf(fabsf((float)dt0), 1.0f);
                float ad1 = fmaxf(fabsf((float)dt1), 1.0f);
                int bk0 = min(max((int)(__logf(ad0) * (1.0f / 0.301f)), 0), NB_);
                int bk1 = min(max((int)(__logf(ad1) * (1.0f / 0.301f)), 0), NB_);
                float x0 = s[ni][half * 2 + 0] + tw[bk0] + pw[N_ - 1 + m - n];
                float x1 = s[ni][half * 2 + 1] + tw[bk1] + pw[N_ + m - n];
                x0 = __fdividef(x0, 1.0f + __expf(-x0)) * (1.0f / (float)N_);
                x1 = __fdividef(x1, 1.0f + __expf(-x1)) * (1.0f / (float)N_);
                x0 *= am.x * tl[b * N_ + m]     * tlnv;
                x1 *= am.y * tl[b * N_ + m + 1] * tlnv;
                __nv_bfloat16 h0 = __float2bfloat16(x0);
                __nv_bfloat16 h1 = __float2bfloat16(x1);
                __nv_bfloat162 hp, lp;
                hp.x = h0; hp.y = h1;
                lp.x = __float2bfloat16(x0 - __bfloat162float(h0));
                lp.y = __float2bfloat16(x1 - __bfloat162float(h1));
                *(uint32_t*)(sm + SPHI + (r * DS + c) * 2) = *(uint32_t*)&hp;
                *(uint32_t*)(sm + SPLO + (r * DS + c) * 2) = *(uint32_t*)&lp;
            }
        }
        __syncwarp();

        // PV: O += P V (3-term split); V via ldmatrix.trans
        #pragma unroll
        for (int ks = 0; ks < 4; ks++) {
            uint32_t phi[4], plo[4];
            int arow = w * 16 + (lane & 15);
            uint32_t aoff = (uint32_t)(arow * DS + ks * 16 + (lane >> 4) * 8) * 2;
            ldsm_x4(phi, sb + SPHI + aoff);
            ldsm_x4(plo, sb + SPLO + aoff);
            #pragma unroll
            for (int ni = 0; ni < 8; ni++) {
                uint32_t vhi[2], vlo[2];
                int vrow = ks * 16 + (lane & 15);
                uint32_t voff = (uint32_t)(vrow * DS + ni * 8) * 2;
                ldsm_x2_t(vhi, kb + 18432 + voff);
                ldsm_x2_t(vlo, kb + 27648 + voff);
                mma16816(o[ni], phi, vhi);
                mma16816(o[ni], phi, vlo);
                mma16816(o[ni], plo, vhi);
            }
        }
        __syncthreads();   // stage (i&1) free before load of tile i+2
    }

    #pragma unroll
    for (int half = 0; half < 2; half++) {
        int r = w * 16 + (lane >> 2) + half * 8;
        int n = n0 + r;
        #pragma unroll
        for (int ni = 0; ni < 8; ni++) {
            int c = ni * 8 + (lane & 3) * 2;
            *(float2*)(g_attn + ((size_t)(b * N_ + n)) * 512 + h * 64 + c) =
                make_float2(o[ni][half * 2], o[ni][half * 2 + 1]);
        }
    }
}

// ---------------- launch -------------------------------------------------------
extern "C" void kernel_launch(void* const* d_in, const int* in_sizes, int n_in,
                              void* d_out, int out_size)
{
    const float* x      = (const float*)d_in[0];
    const float* tlmask = (const float*)d_in[1];
    const float* amask  = (const float*)d_in[2];
    const float* uvqk   = (const float*)d_in[3];
    const float* out_w  = (const float*)d_in[4];
    const float* out_b  = (const float*)d_in[5];
    const float* tw     = (const float*)d_in[6];
    const float* pw     = (const float*)d_in[7];
    const int*   tsraw  = (const int*)d_in[8];
    float*       out    = (float*)d_out;

    const int rows = B_ * N_;   // 16384

    ts_fix_kernel<<<(B_ * NP1 + 255) / 256, 256>>>(tsraw);
    tileflag_kernel<<<64, 256>>>(amask);

    __nv_bfloat16 *whi, *wlo, *w2hi, *w2lo;
    cudaGetSymbolAddress((void**)&whi,  g_Whi);
    cudaGetSymbolAddress((void**)&wlo,  g_Wlo);
    cudaGetSymbolAddress((void**)&w2hi, g_W2hi);
    cudaGetSymbolAddress((void**)&w2lo, g_W2lo);

    wprep_kernel<<<dim3(G_ / 32, F_ / 32), dim3(32, 8)>>>(uvqk, whi, wlo, G_);
    wprep_kernel<<<dim3(512 / 32, F_ / 32), dim3(32, 8)>>>(out_w, w2hi, w2lo, 512);

    ln1_kernel<<<rows, 256>>>(x, tlmask);

    __nv_bfloat16 *ahi, *alo, *o2hi, *o2lo;
    cudaGetSymbolAddress((void**)&ahi,  g_Ahi);
    cudaGetSymbolAddress((void**)&alo,  g_Alo);
    cudaGetSymbolAddress((void**)&o2hi, g_O2hi);
    cudaGetSymbolAddress((void**)&o2lo, g_O2lo);

    cudaFuncSetAttribute(gemm_mma<1>, cudaFuncAttributeMaxDynamicSharedMemorySize, GEMM_SMEM);
    cudaFuncSetAttribute(gemm_mma<2>, cudaFuncAttributeMaxDynamicSharedMemorySize, GEMM_SMEM);
    cudaFuncSetAttribute(attn_tc, cudaFuncAttributeMaxDynamicSharedMemorySize, ATT_SMEM);

    dim3 g1(G_ / 128, rows / 128);        // (16, 128)
    gemm_mma<1><<<g1, 256, GEMM_SMEM>>>(ahi, alo, whi, wlo, tlmask, nullptr, nullptr, nullptr);

    dim3 ga(N_ / 64, H_, B_);             // (8, 8, 32)
    attn_tc<<<ga, 128, ATT_SMEM>>>(tw, pw, amask, tlmask);

    ln2_kernel<<<rows, 256>>>(tlmask);

    dim3 g2(512 / 128, rows / 128);       // (4, 128)
    gemm_mma<2><<<g2, 256, GEMM_SMEM>>>(o2hi, o2lo, w2hi, w2lo, nullptr, out_b, x, out);
}

// round 11
// speedup vs baseline: 6.5294x; 2.0192x over previous
#include <cuda_runtime.h>
#include <cuda_fp16.h>
#include <math.h>
#include <stdint.h>

#define B_  32
#define N_  512
#define F_  512
#define H_  8
#define NB_ 128
#define G_  2048
#define NP1 513

// ---------------- scratch ------------------------------------------------------
__device__ __align__(16) float g_g[(size_t)B_ * N_ * 512];        // u (gated path)
__device__ __align__(16) float g_attn[(size_t)B_ * N_ * 512];
__device__ __align__(16) float g_relb[(size_t)B_ * N_ * N_];      // shared rel bias
__device__ int   g_ts32[B_ * NP1];
__device__ int   g_tflag[64];
__device__ __align__(16) __half g_Ah[(size_t)B_ * N_ * F_];
__device__ __align__(16) __half g_Wh[(size_t)G_ * F_];            // [n][k]
__device__ __align__(16) __half g_O2h[(size_t)B_ * N_ * 512];
__device__ __align__(16) __half g_W2h[(size_t)512 * 512];         // [n][k]
// head-major qkv, layout [b*H+h][n][64]
__device__ __align__(16) __half g_Qh[(size_t)B_ * H_ * N_ * 64];
__device__ __align__(16) __half g_Kh[(size_t)B_ * H_ * N_ * 64];
__device__ __align__(16) __half g_Vh[(size_t)B_ * H_ * N_ * 64];

// ---------------- helpers ------------------------------------------------------
__device__ __forceinline__ uint32_t smem_u32(const void* p) {
    uint32_t a;
    asm("{ .reg .u64 t; cvta.to.shared.u64 t, %1; cvt.u32.u64 %0, t; }" : "=r"(a) : "l"(p));
    return a;
}
__device__ __forceinline__ void cpa16(uint32_t dst, const void* src) {
    asm volatile("cp.async.cg.shared.global [%0], [%1], 16;" :: "r"(dst), "l"(src));
}
__device__ __forceinline__ void cpa_commit() { asm volatile("cp.async.commit_group;" ::: "memory"); }
__device__ __forceinline__ void cpa_wait1()  { asm volatile("cp.async.wait_group 1;" ::: "memory"); }
__device__ __forceinline__ void cpa_wait0()  { asm volatile("cp.async.wait_group 0;" ::: "memory"); }
__device__ __forceinline__ void ldsm_x4(uint32_t* r, uint32_t a) {
    asm volatile("ldmatrix.sync.aligned.m8n8.x4.shared.b16 {%0,%1,%2,%3}, [%4];"
        : "=r"(r[0]), "=r"(r[1]), "=r"(r[2]), "=r"(r[3]) : "r"(a));
}
__device__ __forceinline__ void ldsm_x2(uint32_t* r, uint32_t a) {
    asm volatile("ldmatrix.sync.aligned.m8n8.x2.shared.b16 {%0,%1}, [%2];"
        : "=r"(r[0]), "=r"(r[1]) : "r"(a));
}
__device__ __forceinline__ void ldsm_x2_t(uint32_t* r, uint32_t a) {
    asm volatile("ldmatrix.sync.aligned.m8n8.x2.trans.shared.b16 {%0,%1}, [%2];"
        : "=r"(r[0]), "=r"(r[1]) : "r"(a));
}
__device__ __forceinline__ void mma_f16(float* d, const uint32_t* a, const uint32_t* b) {
    asm volatile("mma.sync.aligned.m16n8k16.row.col.f32.f16.f16.f32 "
        "{%0,%1,%2,%3}, {%4,%5,%6,%7}, {%8,%9}, {%0,%1,%2,%3};"
        : "+f"(d[0]), "+f"(d[1]), "+f"(d[2]), "+f"(d[3])
        : "r"(a[0]), "r"(a[1]), "r"(a[2]), "r"(a[3]), "r"(b[0]), "r"(b[1]));
}

// ---------------- timestamp canonicalization ----------------------------------
__global__ void ts_fix_kernel(const int* __restrict__ tsraw)
{
    __shared__ int is64;
    if (threadIdx.x == 0) {
        int z = 0;
        #pragma unroll
        for (int i = 1; i < 16; i += 2) z |= tsraw[i];
        is64 = (z == 0) ? 1 : 0;
    }
    __syncthreads();
    int i = blockIdx.x * blockDim.x + threadIdx.x;
    if (i < B_ * NP1) g_ts32[i] = is64 ? tsraw[2 * i] : tsraw[i];
}

// ---------------- per-tile mask flags ------------------------------------------
__global__ void tileflag_kernel(const float* __restrict__ amask)
{
    int t = blockIdx.x;
    int ti = t >> 3, tj = t & 7;
    int any = 0;
    for (int k = threadIdx.x; k < 1024; k += 256) {
        int r = k >> 4, c = (k & 15) * 4;
        float4 v = *(const float4*)(amask + (size_t)(ti * 64 + r) * N_ + tj * 64 + c);
        any |= (v.x != 0.f) | (v.y != 0.f) | (v.z != 0.f) | (v.w != 0.f);
    }
    any = __syncthreads_or(any);
    if (threadIdx.x == 0) g_tflag[t] = any;
}

// ---------------- rel bias precompute (shared across heads) --------------------
// rel[b][n][m] = tw[clip(log(|ts[n+1]-ts[m]| max 1)/0.301)] + pw[N-1+m-n]
// quads per batch = N*N/4 = 65536 = 2^16  ->  b = idx>>16 (R10 bug: was >>15)
__global__ void relprep_kernel(const float* __restrict__ tw,
                               const float* __restrict__ pw)
{
    int idx = blockIdx.x * 256 + threadIdx.x;          // quad index
    int b = idx >> 16;
    int q = idx & 0xFFFF;
    int n = q >> 7;                                    // 128 quads per row
    int mq = (q & 127) * 4;
    int tn = g_ts32[b * NP1 + n + 1];
    float4 r;
    float* rr = &r.x;
    #pragma unroll
    for (int j = 0; j < 4; j++) {
        int m = mq + j;
        int dt = tn - g_ts32[b * NP1 + m];
        float ad = fmaxf(fabsf((float)dt), 1.0f);
        int bk = min(max((int)(__logf(ad) * (1.0f / 0.301f)), 0), NB_);
        rr[j] = tw[bk] + pw[N_ - 1 + m - n];
    }
    *(float4*)(g_relb + ((size_t)(b * N_ + n)) * N_ + mq) = r;
}

// ---------------- W transpose + fp16 -------------------------------------------
__global__ void wprep_kernel(const float* __restrict__ W,
                             __half* __restrict__ hp, int ncols)
{
    __shared__ float t[32][33];
    int n0 = blockIdx.x * 32, k0 = blockIdx.y * 32;
    int tx = threadIdx.x, ty = threadIdx.y;   // 32 x 8
    #pragma unroll
    for (int j = 0; j < 4; j++)
        t[ty + j * 8][tx] = W[(size_t)(k0 + ty + j * 8) * ncols + n0 + tx];
    __syncthreads();
    #pragma unroll
    for (int j = 0; j < 4; j++) {
        int row = ty + j * 8;
        hp[(size_t)(n0 + row) * F_ + k0 + tx] = __float2half_rn(t[tx][row]);
    }
}

// ---------------- ln1: LayerNorm -> fp16 ---------------------------------------
__global__ void ln1_kernel(const float* __restrict__ x,
                           const float* __restrict__ tl)
{
    int row = blockIdx.x;
    int tid = threadIdx.x;
    const float* xr = x + (size_t)row * F_;
    float v0 = xr[tid], v1 = xr[tid + 256];
    float s = v0 + v1, sq = v0 * v0 + v1 * v1;
    #pragma unroll
    for (int o = 16; o; o >>= 1) {
        s  += __shfl_down_sync(0xffffffffu, s,  o);
        sq += __shfl_down_sync(0xffffffffu, sq, o);
    }
    __shared__ float red[16];
    __shared__ float mean_s, rstd_s;
    int w = tid >> 5, l = tid & 31;
    if (l == 0) { red[w] = s; red[w + 8] = sq; }
    __syncthreads();
    if (tid == 0) {
        float ts = 0.f, tq = 0.f;
        #pragma unroll
        for (int i = 0; i < 8; i++) { ts += red[i]; tq += red[i + 8]; }
        float m = ts * (1.0f / F_);
        float var = tq * (1.0f / F_) - m * m;
        mean_s = m;
        rstd_s = rsqrtf(var + 1e-6f);
    }
    __syncthreads();
    float t = tl[row];
    float m = mean_s, rs = rstd_s;
    size_t o0 = (size_t)row * F_ + tid;
    g_Ah[o0]       = __float2half_rn((v0 - m) * rs * t);
    g_Ah[o0 + 256] = __float2half_rn((v1 - m) * rs * t);
}

// ---------------- ln2: o_input = u*LN(attn)*tl -> fp16 -------------------------
__global__ void ln2_kernel(const float* __restrict__ tl)
{
    int row = blockIdx.x;
    int tid = threadIdx.x;
    const float* ar = g_attn + (size_t)row * 512;
    float v0 = ar[tid], v1 = ar[tid + 256];
    float s = v0 + v1, sq = v0 * v0 + v1 * v1;
    #pragma unroll
    for (int o = 16; o; o >>= 1) {
        s  += __shfl_down_sync(0xffffffffu, s,  o);
        sq += __shfl_down_sync(0xffffffffu, sq, o);
    }
    __shared__ float red[16];
    __shared__ float mean_s, rstd_s;
    int w = tid >> 5, l = tid & 31;
    if (l == 0) { red[w] = s; red[w + 8] = sq; }
    __syncthreads();
    if (tid == 0) {
        float ts = 0.f, tq = 0.f;
        #pragma unroll
        for (int i = 0; i < 8; i++) { ts += red[i]; tq += red[i + 8]; }
        float m = ts * (1.0f / 512.0f);
        float var = tq * (1.0f / 512.0f) - m * m;
        mean_s = m;
        rstd_s = rsqrtf(var + 1e-6f);
    }
    __syncthreads();
    float t = tl[row];
    float m = mean_s, rs = rstd_s;
    float u0 = g_g[(size_t)row * 512 + tid];
    float u1 = g_g[(size_t)row * 512 + tid + 256];
    size_t off = (size_t)row * 512 + tid;
    g_O2h[off]       = __float2half_rn(u0 * (v0 - m) * rs * t);
    g_O2h[off + 256] = __float2half_rn(u1 * (v1 - m) * rs * t);
}

// ---------------- GEMM via mma.sync fp16, cp.async 2-stage ---------------------
// per stage 20480 B: A +0, B +10240
#define GST 20480
#define GEMM_SMEM (2 * GST)

template <int MODE>
__global__ void __launch_bounds__(256)
gemm_mma(const __half* __restrict__ Ah, const __half* __restrict__ Bh,
         const float* __restrict__ tl, const float* __restrict__ bias,
         const float* __restrict__ xres, float* __restrict__ Cout)
{
    constexpr int LDS = 40;
    extern __shared__ __align__(16) char dsm[];
    const uint32_t sb = smem_u32(dsm);

    const int tid = threadIdx.x, lane = tid & 31, wid = tid >> 5;
    const int wr = wid & 3, wc = wid >> 2;
    const int m0 = blockIdx.y * 128, n0 = blockIdx.x * 128;

    float d[2][8][4] = {};

    auto load_stage = [&](int kc, int st) {
        const int k0 = kc * 32;
        const uint32_t base = sb + st * GST;
        #pragma unroll
        for (int it = 0; it < 2; it++) {
            int idx = tid + it * 256;
            int r = idx >> 2, c = (idx & 3) * 8;
            uint32_t doff = (uint32_t)(r * LDS + c) * 2;
            cpa16(base + doff,         Ah + (size_t)(m0 + r) * F_ + k0 + c);
            cpa16(base + 10240 + doff, Bh + (size_t)(n0 + r) * F_ + k0 + c);
        }
        cpa_commit();
    };

    load_stage(0, 0);

    for (int kc = 0; kc < 16; kc++) {
        if (kc < 15) { load_stage(kc + 1, (kc + 1) & 1); cpa_wait1(); }
        else         { cpa_wait0(); }
        __syncthreads();

        const uint32_t base = sb + (kc & 1) * GST;
        #pragma unroll
        for (int ks = 0; ks < 2; ks++) {
            uint32_t a[2][4], bb[8][2];
            #pragma unroll
            for (int mi = 0; mi < 2; mi++) {
                int row = wr * 32 + mi * 16 + (lane & 15);
                uint32_t off = (uint32_t)(row * LDS + ks * 16 + (lane >> 4) * 8) * 2;
                ldsm_x4(a[mi], base + off);
            }
            #pragma unroll
            for (int ni = 0; ni < 8; ni++) {
                int row = wc * 64 + ni * 8 + (lane & 7);
                uint32_t off = (uint32_t)(row * LDS + ks * 16 + ((lane >> 3) & 1) * 8) * 2;
                ldsm_x2(bb[ni], base + 10240 + off);
            }
            #pragma unroll
            for (int mi = 0; mi < 2; mi++)
                #pragma unroll
                for (int ni = 0; ni < 8; ni++)
                    mma_f16(d[mi][ni], a[mi], bb[ni]);
        }
        __syncthreads();
    }

    #pragma unroll
    for (int mi = 0; mi < 2; mi++) {
        int rbase = m0 + wr * 32 + mi * 16 + (lane >> 2);
        #pragma unroll
        for (int half = 0; half < 2; half++) {
            int row = rbase + half * 8;
            float tlv = (MODE == 1) ? tl[row] : 0.0f;
            #pragma unroll
            for (int ni = 0; ni < 8; ni++) {
                int col = n0 + wc * 64 + ni * 8 + (lane & 3) * 2;
                float v0 = d[mi][ni][half * 2 + 0];
                float v1 = d[mi][ni][half * 2 + 1];
                if (MODE == 1) {
                    v0 = __fdividef(v0, 1.0f + __expf(-v0)) * tlv;
                    v1 = __fdividef(v1, 1.0f + __expf(-v1)) * tlv;
                    if (col < 512) {
                        *(float2*)(g_g + (size_t)row * 512 + col) = make_float2(v0, v1);
                    } else {
                        __half2 hp;
                        hp.x = __float2half_rn(v0);
                        hp.y = __float2half_rn(v1);
                        int hh = (col >> 6) & 7;
                        int dd = col & 63;
                        size_t off = (((size_t)(row >> 9) * H_ + hh) * N_ + (row & 511)) * 64 + dd;
                        if (col < 1024)      *(__half2*)(g_Vh + off) = hp;
                        else if (col < 1536) *(__half2*)(g_Qh + off) = hp;
                        else                 *(__half2*)(g_Kh + off) = hp;
                    }
                } else {
                    v0 += bias[col]     + xres[(size_t)row * 512 + col];
                    v1 += bias[col + 1] + xres[(size_t)row * 512 + col + 1];
                    *(float2*)(Cout + (size_t)row * 512 + col) = make_float2(v0, v1);
                }
            }
        }
    }
}

// ---------------- tensor-core attention, fp16, cp.async 2-stage KV -------------
#define DS    72
#define SQ    0
#define SKV0  9216          // per stage: K +0, V +9216; stage size 18432
#define KVST  18432
#define SP    (SKV0 + 2 * KVST)          // 46080
#define ATT_SMEM (SP + 9216)             // 55296

__global__ void __launch_bounds__(128)
attn_tc(const float* __restrict__ amask, const float* __restrict__ tl)
{
    extern __shared__ __align__(16) char sm[];
    const uint32_t sb = smem_u32(sm);
    const int tid = threadIdx.x, lane = tid & 31, w = tid >> 5;
    const int n0 = blockIdx.x * 64, h = blockIdx.y, b = blockIdx.z;
    const int bh = b * H_ + h;

    // Q -> smem
    #pragma unroll
    for (int it = 0; it < 4; it++) {
        int idx = tid + it * 128;
        int r = idx >> 3, c = (idx & 7) * 8;
        *(float4*)(sm + SQ + (r * DS + c) * 2) =
            *(const float4*)(g_Qh + ((size_t)bh * N_ + n0 + r) * 64 + c);
    }

    int mlist[8];
    int nact = 0;
    const int tr = n0 >> 6;
    #pragma unroll
    for (int t = 0; t < 8; t++)
        if (g_tflag[tr * 8 + t]) mlist[nact++] = t * 64;

    auto load_kv = [&](int m0, int st) {
        const uint32_t base = sb + SKV0 + st * KVST;
        #pragma unroll
        for (int it = 0; it < 4; it++) {
            int idx = tid + it * 128;
            int r = idx >> 3, c = (idx & 7) * 8;
            uint32_t doff = (uint32_t)(r * DS + c) * 2;
            size_t src = ((size_t)bh * N_ + m0 + r) * 64 + c;
            cpa16(base + doff,        g_Kh + src);
            cpa16(base + 9216 + doff, g_Vh + src);
        }
        cpa_commit();
    };

    float o[8][4] = {};

    if (nact > 0) load_kv(mlist[0], 0);

    for (int i = 0; i < nact; i++) {
        if (i + 1 < nact) { load_kv(mlist[i + 1], (i + 1) & 1); cpa_wait1(); }
        else              { cpa_wait0(); }
        __syncthreads();

        const int m0 = mlist[i];
        const uint32_t kb = sb + SKV0 + (i & 1) * KVST;

        // S = Q K^T
        float s[8][4] = {};
        #pragma unroll
        for (int ks = 0; ks < 4; ks++) {
            uint32_t q[4];
            int arow = w * 16 + (lane & 15);
            uint32_t aoff = (uint32_t)(arow * DS + ks * 16 + (lane >> 4) * 8) * 2;
            ldsm_x4(q, sb + SQ + aoff);
            #pragma unroll
            for (int ni = 0; ni < 8; ni++) {
                uint32_t k[2];
                int brow = ni * 8 + (lane & 7);
                uint32_t boff = (uint32_t)(brow * DS + ks * 16 + ((lane >> 3) & 1) * 8) * 2;
                ldsm_x2(k, kb + boff);
                mma_f16(s[ni], q, k);
            }
        }

        // epilogue: rel from precomputed table; P unscaled by 1/N (folded into O)
        #pragma unroll
        for (int half = 0; half < 2; half++) {
            int r = w * 16 + (lane >> 2) + half * 8;
            int n = n0 + r;
            float tlnv = tl[b * N_ + n];
            const float* relrow = g_relb + ((size_t)(b * N_ + n)) * N_;
            #pragma unroll
            for (int ni = 0; ni < 8; ni++) {
                int c = ni * 8 + (lane & 3) * 2;
                int m = m0 + c;
                float2 am = *(const float2*)(amask + (size_t)n * N_ + m);
                float2 rl = *(const float2*)(relrow + m);
                float x0 = s[ni][half * 2 + 0] + rl.x;
                float x1 = s[ni][half * 2 + 1] + rl.y;
                x0 = __fdividef(x0, 1.0f + __expf(-x0));
                x1 = __fdividef(x1, 1.0f + __expf(-x1));
                x0 *= am.x * tl[b * N_ + m]     * tlnv;
                x1 *= am.y * tl[b * N_ + m + 1] * tlnv;
                __half2 hp;
                hp.x = __float2half_rn(x0);
                hp.y = __float2half_rn(x1);
                *(uint32_t*)(sm + SP + (r * DS + c) * 2) = *(uint32_t*)&hp;
            }
        }
        __syncwarp();

        // O += P V; V via ldmatrix.trans
        #pragma unroll
        for (int ks = 0; ks < 4; ks++) {
            uint32_t p[4];
            int arow = w * 16 + (lane & 15);
            uint32_t aoff = (uint32_t)(arow * DS + ks * 16 + (lane >> 4) * 8) * 2;
            ldsm_x4(p, sb + SP + aoff);
            #pragma unroll
            for (int ni = 0; ni < 8; ni++) {
                uint32_t v[2];
                int vrow = ks * 16 + (lane & 15);
                uint32_t voff = (uint32_t)(vrow * DS + ni * 8) * 2;
                ldsm_x2_t(v, kb + 9216 + voff);
                mma_f16(o[ni], p, v);
            }
        }
        __syncthreads();
    }

    #pragma unroll
    for (int half = 0; half < 2; half++) {
        int r = w * 16 + (lane >> 2) + half * 8;
        int n = n0 + r;
        #pragma unroll
        for (int ni = 0; ni < 8; ni++) {
            int c = ni * 8 + (lane & 3) * 2;
            *(float2*)(g_attn + ((size_t)(b * N_ + n)) * 512 + h * 64 + c) =
                make_float2(o[ni][half * 2] * (1.0f / N_), o[ni][half * 2 + 1] * (1.0f / N_));
        }
    }
}

// ---------------- launch -------------------------------------------------------
extern "C" void kernel_launch(void* const* d_in, const int* in_sizes, int n_in,
                              void* d_out, int out_size)
{
    const float* x      = (const float*)d_in[0];
    const float* tlmask = (const float*)d_in[1];
    const float* amask  = (const float*)d_in[2];
    const float* uvqk   = (const float*)d_in[3];
    const float* out_w  = (const float*)d_in[4];
    const float* out_b  = (const float*)d_in[5];
    const float* tw     = (const float*)d_in[6];
    const float* pw     = (const float*)d_in[7];
    const int*   tsraw  = (const int*)d_in[8];
    float*       out    = (float*)d_out;

    const int rows = B_ * N_;   // 16384

    ts_fix_kernel<<<(B_ * NP1 + 255) / 256, 256>>>(tsraw);
    tileflag_kernel<<<64, 256>>>(amask);
    relprep_kernel<<<B_ * N_ * N_ / 1024, 256>>>(tw, pw);

    __half *wh, *w2h;
    cudaGetSymbolAddress((void**)&wh,  g_Wh);
    cudaGetSymbolAddress((void**)&w2h, g_W2h);
    wprep_kernel<<<dim3(G_ / 32, F_ / 32), dim3(32, 8)>>>(uvqk, wh, G_);
    wprep_kernel<<<dim3(512 / 32, F_ / 32), dim3(32, 8)>>>(out_w, w2h, 512);

    ln1_kernel<<<rows, 256>>>(x, tlmask);

    __half *ah, *o2h;
    cudaGetSymbolAddress((void**)&ah,  g_Ah);
    cudaGetSymbolAddress((void**)&o2h, g_O2h);

    cudaFuncSetAttribute(gemm_mma<1>, cudaFuncAttributeMaxDynamicSharedMemorySize, GEMM_SMEM);
    cudaFuncSetAttribute(gemm_mma<2>, cudaFuncAttributeMaxDynamicSharedMemorySize, GEMM_SMEM);
    cudaFuncSetAttribute(attn_tc, cudaFuncAttributeMaxDynamicSharedMemorySize, ATT_SMEM);

    dim3 g1(G_ / 128, rows / 128);        // (16, 128)
    gemm_mma<1><<<g1, 256, GEMM_SMEM>>>(ah, wh, tlmask, nullptr, nullptr, nullptr);

    dim3 ga(N_ / 64, H_, B_);             // (8, 8, 32)
    attn_tc<<<ga, 128, ATT_SMEM>>>(amask, tlmask);

    ln2_kernel<<<rows, 256>>>(tlmask);

    dim3 g2(512 / 128, rows / 128);       // (4, 128)
    gemm_mma<2><<<g2, 256, GEMM_SMEM>>>(o2h, w2h, nullptr, out_b, x, out);
}

// round 12
// speedup vs baseline: 6.5349x; 1.0008x over previous
#include <cuda_runtime.h>
#include <cuda_fp16.h>
#include <math.h>
#include <stdint.h>

#define B_  32
#define N_  512
#define F_  512
#define H_  8
#define NB_ 128
#define G_  2048
#define NP1 513

// ---------------- scratch ------------------------------------------------------
__device__ __align__(16) __half g_uh[(size_t)B_ * N_ * 512];      // u (gated path)
__device__ __align__(16) __half g_attnh[(size_t)B_ * N_ * 512];
__device__ __align__(16) __half g_relh[(size_t)B_ * N_ * N_];     // shared rel bias
__device__ int   g_ts32[B_ * NP1];
__device__ int   g_tflag[64];
__device__ __align__(16) __half g_Ah[(size_t)B_ * N_ * F_];
__device__ __align__(16) __half g_Wh[(size_t)G_ * F_];            // [n][k]
__device__ __align__(16) __half g_O2h[(size_t)B_ * N_ * 512];
__device__ __align__(16) __half g_W2h[(size_t)512 * 512];         // [n][k]
// head-major qkv, layout [b*H+h][n][64]
__device__ __align__(16) __half g_Qh[(size_t)B_ * H_ * N_ * 64];
__device__ __align__(16) __half g_Kh[(size_t)B_ * H_ * N_ * 64];
__device__ __align__(16) __half g_Vh[(size_t)B_ * H_ * N_ * 64];

// ---------------- helpers ------------------------------------------------------
__device__ __forceinline__ uint32_t smem_u32(const void* p) {
    uint32_t a;
    asm("{ .reg .u64 t; cvta.to.shared.u64 t, %1; cvt.u32.u64 %0, t; }" : "=r"(a) : "l"(p));
    return a;
}
__device__ __forceinline__ void cpa16(uint32_t dst, const void* src) {
    asm volatile("cp.async.cg.shared.global [%0], [%1], 16;" :: "r"(dst), "l"(src));
}
__device__ __forceinline__ void cpa_commit() { asm volatile("cp.async.commit_group;" ::: "memory"); }
__device__ __forceinline__ void cpa_wait1()  { asm volatile("cp.async.wait_group 1;" ::: "memory"); }
__device__ __forceinline__ void cpa_wait0()  { asm volatile("cp.async.wait_group 0;" ::: "memory"); }
__device__ __forceinline__ void ldsm_x4(uint32_t* r, uint32_t a) {
    asm volatile("ldmatrix.sync.aligned.m8n8.x4.shared.b16 {%0,%1,%2,%3}, [%4];"
        : "=r"(r[0]), "=r"(r[1]), "=r"(r[2]), "=r"(r[3]) : "r"(a));
}
__device__ __forceinline__ void ldsm_x4_t(uint32_t* r, uint32_t a) {
    asm volatile("ldmatrix.sync.aligned.m8n8.x4.trans.shared.b16 {%0,%1,%2,%3}, [%4];"
        : "=r"(r[0]), "=r"(r[1]), "=r"(r[2]), "=r"(r[3]) : "r"(a));
}
__device__ __forceinline__ void mma_f16(float* d, const uint32_t* a, const uint32_t* b) {
    asm volatile("mma.sync.aligned.m16n8k16.row.col.f32.f16.f16.f32 "
        "{%0,%1,%2,%3}, {%4,%5,%6,%7}, {%8,%9}, {%0,%1,%2,%3};"
        : "+f"(d[0]), "+f"(d[1]), "+f"(d[2]), "+f"(d[3])
        : "r"(a[0]), "r"(a[1]), "r"(a[2]), "r"(a[3]), "r"(b[0]), "r"(b[1]));
}

// ---------------- timestamp canonicalization ----------------------------------
__global__ void ts_fix_kernel(const int* __restrict__ tsraw)
{
    __shared__ int is64;
    if (threadIdx.x == 0) {
        int z = 0;
        #pragma unroll
        for (int i = 1; i < 16; i += 2) z |= tsraw[i];
        is64 = (z == 0) ? 1 : 0;
    }
    __syncthreads();
    int i = blockIdx.x * blockDim.x + threadIdx.x;
    if (i < B_ * NP1) g_ts32[i] = is64 ? tsraw[2 * i] : tsraw[i];
}

// ---------------- per-tile mask flags ------------------------------------------
__global__ void tileflag_kernel(const float* __restrict__ amask)
{
    int t = blockIdx.x;
    int ti = t >> 3, tj = t & 7;
    int any = 0;
    for (int k = threadIdx.x; k < 1024; k += 256) {
        int r = k >> 4, c = (k & 15) * 4;
        float4 v = *(const float4*)(amask + (size_t)(ti * 64 + r) * N_ + tj * 64 + c);
        any |= (v.x != 0.f) | (v.y != 0.f) | (v.z != 0.f) | (v.w != 0.f);
    }
    any = __syncthreads_or(any);
    if (threadIdx.x == 0) g_tflag[t] = any;
}

// ---------------- rel bias precompute (shared across heads, fp16) --------------
// rel[b][n][m] = tw[clip(log(|ts[n+1]-ts[m]| max 1)/0.301)] + pw[N-1+m-n]
// quads per batch = N*N/4 = 65536 = 2^16
__global__ void relprep_kernel(const float* __restrict__ tw,
                               const float* __restrict__ pw)
{
    int idx = blockIdx.x * 256 + threadIdx.x;          // quad index
    int b = idx >> 16;
    int q = idx & 0xFFFF;
    int n = q >> 7;                                    // 128 quads per row
    int mq = (q & 127) * 4;
    int tn = g_ts32[b * NP1 + n + 1];
    float rr[4];
    #pragma unroll
    for (int j = 0; j < 4; j++) {
        int m = mq + j;
        int dt = tn - g_ts32[b * NP1 + m];
        float ad = fmaxf(fabsf((float)dt), 1.0f);
        int bk = min(max((int)(__logf(ad) * (1.0f / 0.301f)), 0), NB_);
        rr[j] = tw[bk] + pw[N_ - 1 + m - n];
    }
    __half2 p01 = __floats2half2_rn(rr[0], rr[1]);
    __half2 p23 = __floats2half2_rn(rr[2], rr[3]);
    uint2 pk;
    pk.x = *(uint32_t*)&p01;
    pk.y = *(uint32_t*)&p23;
    *(uint2*)(g_relh + ((size_t)(b * N_ + n)) * N_ + mq) = pk;
}

// ---------------- W transpose + fp16 -------------------------------------------
__global__ void wprep_kernel(const float* __restrict__ W,
                             __half* __restrict__ hp, int ncols)
{
    __shared__ float t[32][33];
    int n0 = blockIdx.x * 32, k0 = blockIdx.y * 32;
    int tx = threadIdx.x, ty = threadIdx.y;   // 32 x 8
    #pragma unroll
    for (int j = 0; j < 4; j++)
        t[ty + j * 8][tx] = W[(size_t)(k0 + ty + j * 8) * ncols + n0 + tx];
    __syncthreads();
    #pragma unroll
    for (int j = 0; j < 4; j++) {
        int row = ty + j * 8;
        hp[(size_t)(n0 + row) * F_ + k0 + tx] = __float2half_rn(t[tx][row]);
    }
}

// ---------------- ln1: LayerNorm -> fp16 ---------------------------------------
__global__ void ln1_kernel(const float* __restrict__ x,
                           const float* __restrict__ tl)
{
    int row = blockIdx.x;
    int tid = threadIdx.x;
    const float* xr = x + (size_t)row * F_;
    float v0 = xr[tid], v1 = xr[tid + 256];
    float s = v0 + v1, sq = v0 * v0 + v1 * v1;
    #pragma unroll
    for (int o = 16; o; o >>= 1) {
        s  += __shfl_down_sync(0xffffffffu, s,  o);
        sq += __shfl_down_sync(0xffffffffu, sq, o);
    }
    __shared__ float red[16];
    __shared__ float mean_s, rstd_s;
    int w = tid >> 5, l = tid & 31;
    if (l == 0) { red[w] = s; red[w + 8] = sq; }
    __syncthreads();
    if (tid == 0) {
        float ts = 0.f, tq = 0.f;
        #pragma unroll
        for (int i = 0; i < 8; i++) { ts += red[i]; tq += red[i + 8]; }
        float m = ts * (1.0f / F_);
        float var = tq * (1.0f / F_) - m * m;
        mean_s = m;
        rstd_s = rsqrtf(var + 1e-6f);
    }
    __syncthreads();
    float t = tl[row];
    float m = mean_s, rs = rstd_s;
    size_t o0 = (size_t)row * F_ + tid;
    g_Ah[o0]       = __float2half_rn((v0 - m) * rs * t);
    g_Ah[o0 + 256] = __float2half_rn((v1 - m) * rs * t);
}

// ---------------- ln2: o_input = u*LN(attn)*tl -> fp16 -------------------------
__global__ void ln2_kernel(const float* __restrict__ tl)
{
    int row = blockIdx.x;
    int tid = threadIdx.x;
    const __half* ar = g_attnh + (size_t)row * 512;
    float v0 = __half2float(ar[tid]);
    float v1 = __half2float(ar[tid + 256]);
    float s = v0 + v1, sq = v0 * v0 + v1 * v1;
    #pragma unroll
    for (int o = 16; o; o >>= 1) {
        s  += __shfl_down_sync(0xffffffffu, s,  o);
        sq += __shfl_down_sync(0xffffffffu, sq, o);
    }
    __shared__ float red[16];
    __shared__ float mean_s, rstd_s;
    int w = tid >> 5, l = tid & 31;
    if (l == 0) { red[w] = s; red[w + 8] = sq; }
    __syncthreads();
    if (tid == 0) {
        float ts = 0.f, tq = 0.f;
        #pragma unroll
        for (int i = 0; i < 8; i++) { ts += red[i]; tq += red[i + 8]; }
        float m = ts * (1.0f / 512.0f);
        float var = tq * (1.0f / 512.0f) - m * m;
        mean_s = m;
        rstd_s = rsqrtf(var + 1e-6f);
    }
    __syncthreads();
    float t = tl[row];
    float m = mean_s, rs = rstd_s;
    float u0 = __half2float(g_uh[(size_t)row * 512 + tid]);
    float u1 = __half2float(g_uh[(size_t)row * 512 + tid + 256]);
    size_t off = (size_t)row * 512 + tid;
    g_O2h[off]       = __float2half_rn(u0 * (v0 - m) * rs * t);
    g_O2h[off + 256] = __float2half_rn(u1 * (v1 - m) * rs * t);
}

// ---------------- GEMM via mma.sync fp16, cp.async 2-stage ---------------------
// per stage 20480 B: A +0, B +10240
#define GST 20480
#define GEMM_SMEM (2 * GST)

template <int MODE>
__global__ void __launch_bounds__(256)
gemm_mma(const __half* __restrict__ Ah, const __half* __restrict__ Bh,
         const float* __restrict__ tl, const float* __restrict__ bias,
         const float* __restrict__ xres, float* __restrict__ Cout)
{
    constexpr int LDS = 40;
    extern __shared__ __align__(16) char dsm[];
    const uint32_t sb = smem_u32(dsm);

    const int tid = threadIdx.x, lane = tid & 31, wid = tid >> 5;
    const int wr = wid & 3, wc = wid >> 2;
    const int m0 = blockIdx.y * 128, n0 = blockIdx.x * 128;

    float d[2][8][4] = {};

    auto load_stage = [&](int kc, int st) {
        const int k0 = kc * 32;
        const uint32_t base = sb + st * GST;
        #pragma unroll
        for (int it = 0; it < 2; it++) {
            int idx = tid + it * 256;
            int r = idx >> 2, c = (idx & 3) * 8;
            uint32_t doff = (uint32_t)(r * LDS + c) * 2;
            cpa16(base + doff,         Ah + (size_t)(m0 + r) * F_ + k0 + c);
            cpa16(base + 10240 + doff, Bh + (size_t)(n0 + r) * F_ + k0 + c);
        }
        cpa_commit();
    };

    load_stage(0, 0);

    for (int kc = 0; kc < 16; kc++) {
        if (kc < 15) { load_stage(kc + 1, (kc + 1) & 1); cpa_wait1(); }
        else         { cpa_wait0(); }
        __syncthreads();

        const uint32_t base = sb + (kc & 1) * GST;
        #pragma unroll
        for (int ks = 0; ks < 2; ks++) {
            uint32_t a[2][4], bb[4][4];
            const int g2 = lane >> 3;     // 0..3
            #pragma unroll
            for (int mi = 0; mi < 2; mi++) {
                int row = wr * 32 + mi * 16 + (lane & 15);
                uint32_t off = (uint32_t)(row * LDS + ks * 16 + (lane >> 4) * 8) * 2;
                ldsm_x4(a[mi], base + off);
            }
            #pragma unroll
            for (int nj = 0; nj < 4; nj++) {
                int row = wc * 64 + nj * 16 + (g2 >> 1) * 8 + (lane & 7);
                int col = ks * 16 + (g2 & 1) * 8;
                ldsm_x4(bb[nj], base + 10240 + (uint32_t)(row * LDS + col) * 2);
            }
            #pragma unroll
            for (int mi = 0; mi < 2; mi++)
                #pragma unroll
                for (int nj = 0; nj < 4; nj++) {
                    mma_f16(d[mi][2 * nj + 0], a[mi], &bb[nj][0]);
                    mma_f16(d[mi][2 * nj + 1], a[mi], &bb[nj][2]);
                }
        }
        __syncthreads();
    }

    #pragma unroll
    for (int mi = 0; mi < 2; mi++) {
        int rbase = m0 + wr * 32 + mi * 16 + (lane >> 2);
        #pragma unroll
        for (int half = 0; half < 2; half++) {
            int row = rbase + half * 8;
            float tlv = (MODE == 1) ? tl[row] : 0.0f;
            #pragma unroll
            for (int ni = 0; ni < 8; ni++) {
                int col = n0 + wc * 64 + ni * 8 + (lane & 3) * 2;
                float v0 = d[mi][ni][half * 2 + 0];
                float v1 = d[mi][ni][half * 2 + 1];
                if (MODE == 1) {
                    v0 = __fdividef(v0, 1.0f + __expf(-v0)) * tlv;
                    v1 = __fdividef(v1, 1.0f + __expf(-v1)) * tlv;
                    __half2 hp = __floats2half2_rn(v0, v1);
                    if (col < 512) {
                        *(__half2*)(g_uh + (size_t)row * 512 + col) = hp;
                    } else {
                        int hh = (col >> 6) & 7;
                        int dd = col & 63;
                        size_t off = (((size_t)(row >> 9) * H_ + hh) * N_ + (row & 511)) * 64 + dd;
                        if (col < 1024)      *(__half2*)(g_Vh + off) = hp;
                        else if (col < 1536) *(__half2*)(g_Qh + off) = hp;
                        else                 *(__half2*)(g_Kh + off) = hp;
                    }
                } else {
                    v0 += bias[col]     + xres[(size_t)row * 512 + col];
                    v1 += bias[col + 1] + xres[(size_t)row * 512 + col + 1];
                    *(float2*)(Cout + (size_t)row * 512 + col) = make_float2(v0, v1);
                }
            }
        }
    }
}

// ---------------- tensor-core attention: 128 q-rows, fp16, 2-stage KV ----------
#define DS    72
#define SQ    0
#define SKV0  18432         // per stage: K +0, V +9216; stage size 18432
#define KVST  18432
#define SP    (SKV0 + 2 * KVST)          // 55296
#define ATT_SMEM (SP + 18432)            // 73728

__global__ void __launch_bounds__(256)
attn_tc(const float* __restrict__ amask, const float* __restrict__ tl)
{
    extern __shared__ __align__(16) char sm[];
    const uint32_t sb = smem_u32(sm);
    const int tid = threadIdx.x, lane = tid & 31, w = tid >> 5;
    const int n0 = blockIdx.x * 128, h = blockIdx.y, b = blockIdx.z;
    const int bh = b * H_ + h;

    // Q -> smem (128 rows)
    #pragma unroll
    for (int it = 0; it < 4; it++) {
        int idx = tid + it * 256;
        int r = idx >> 3, c = (idx & 7) * 8;
        *(float4*)(sm + SQ + (r * DS + c) * 2) =
            *(const float4*)(g_Qh + ((size_t)bh * N_ + n0 + r) * 64 + c);
    }

    int mlist[8];
    int nact = 0;
    const int tr = n0 >> 6;          // covers flag rows tr, tr+1
    #pragma unroll
    for (int t = 0; t < 8; t++)
        if (g_tflag[tr * 8 + t] | g_tflag[(tr + 1) * 8 + t]) mlist[nact++] = t * 64;

    auto load_kv = [&](int m0, int st) {
        const uint32_t base = sb + SKV0 + st * KVST;
        #pragma unroll
        for (int it = 0; it < 2; it++) {
            int idx = tid + it * 256;
            int r = idx >> 3, c = (idx & 7) * 8;
            uint32_t doff = (uint32_t)(r * DS + c) * 2;
            size_t src = ((size_t)bh * N_ + m0 + r) * 64 + c;
            cpa16(base + doff,        g_Kh + src);
            cpa16(base + 9216 + doff, g_Vh + src);
        }
        cpa_commit();
    };

    float o[8][4] = {};

    if (nact > 0) load_kv(mlist[0], 0);

    for (int i = 0; i < nact; i++) {
        if (i + 1 < nact) { load_kv(mlist[i + 1], (i + 1) & 1); cpa_wait1(); }
        else              { cpa_wait0(); }
        __syncthreads();

        const int m0 = mlist[i];
        const uint32_t kb = sb + SKV0 + (i & 1) * KVST;
        const int g2 = lane >> 3;

        // S = Q K^T
        float s[8][4] = {};
        #pragma unroll
        for (int ks = 0; ks < 4; ks++) {
            uint32_t q[4];
            int arow = w * 16 + (lane & 15);
            uint32_t aoff = (uint32_t)(arow * DS + ks * 16 + (lane >> 4) * 8) * 2;
            ldsm_x4(q, sb + SQ + aoff);
            #pragma unroll
            for (int t = 0; t < 4; t++) {
                uint32_t kk[4];
                int brow = t * 16 + (g2 >> 1) * 8 + (lane & 7);
                int bcol = ks * 16 + (g2 & 1) * 8;
                ldsm_x4(kk, kb + (uint32_t)(brow * DS + bcol) * 2);
                mma_f16(s[2 * t + 0], q, &kk[0]);
                mma_f16(s[2 * t + 1], q, &kk[2]);
            }
        }

        // epilogue: rel from fp16 table; P unscaled by 1/N (folded into O)
        #pragma unroll
        for (int half = 0; half < 2; half++) {
            int r = w * 16 + (lane >> 2) + half * 8;
            int n = n0 + r;
            float tlnv = tl[b * N_ + n];
            const __half* relrow = g_relh + ((size_t)(b * N_ + n)) * N_;
            #pragma unroll
            for (int ni = 0; ni < 8; ni++) {
                int c = ni * 8 + (lane & 3) * 2;
                int m = m0 + c;
                float2 am = *(const float2*)(amask + (size_t)n * N_ + m);
                float2 rl = __half22float2(*(const __half2*)(relrow + m));
                float x0 = s[ni][half * 2 + 0] + rl.x;
                float x1 = s[ni][half * 2 + 1] + rl.y;
                x0 = __fdividef(x0, 1.0f + __expf(-x0));
                x1 = __fdividef(x1, 1.0f + __expf(-x1));
                x0 *= am.x * tl[b * N_ + m]     * tlnv;
                x1 *= am.y * tl[b * N_ + m + 1] * tlnv;
                __half2 hp = __floats2half2_rn(x0, x1);
                *(uint32_t*)(sm + SP + (r * DS + c) * 2) = *(uint32_t*)&hp;
            }
        }
        __syncwarp();

        // O += P V; V via ldmatrix.trans x4
        #pragma unroll
        for (int ks = 0; ks < 4; ks++) {
            uint32_t p[4];
            int arow = w * 16 + (lane & 15);
            uint32_t aoff = (uint32_t)(arow * DS + ks * 16 + (lane >> 4) * 8) * 2;
            ldsm_x4(p, sb + SP + aoff);
            #pragma unroll
            for (int t = 0; t < 4; t++) {
                uint32_t v[4];
                int vrow = ks * 16 + (lane & 15);
                int vcol = (2 * t + (lane >> 4)) * 8;
                ldsm_x4_t(v, kb + 9216 + (uint32_t)(vrow * DS + vcol) * 2);
                mma_f16(o[2 * t + 0], p, &v[0]);
                mma_f16(o[2 * t + 1], p, &v[2]);
            }
        }
        __syncthreads();
    }

    #pragma unroll
    for (int half = 0; half < 2; half++) {
        int r = w * 16 + (lane >> 2) + half * 8;
        int n = n0 + r;
        #pragma unroll
        for (int ni = 0; ni < 8; ni++) {
            int c = ni * 8 + (lane & 3) * 2;
            __half2 hp = __floats2half2_rn(o[ni][half * 2] * (1.0f / N_),
                                           o[ni][half * 2 + 1] * (1.0f / N_));
            *(__half2*)(g_attnh + ((size_t)(b * N_ + n)) * 512 + h * 64 + c) = hp;
        }
    }
}

// ---------------- launch -------------------------------------------------------
extern "C" void kernel_launch(void* const* d_in, const int* in_sizes, int n_in,
                              void* d_out, int out_size)
{
    const float* x      = (const float*)d_in[0];
    const float* tlmask = (const float*)d_in[1];
    const float* amask  = (const float*)d_in[2];
    const float* uvqk   = (const float*)d_in[3];
    const float* out_w  = (const float*)d_in[4];
    const float* out_b  = (const float*)d_in[5];
    const float* tw     = (const float*)d_in[6];
    const float* pw     = (const float*)d_in[7];
    const int*   tsraw  = (const int*)d_in[8];
    float*       out    = (float*)d_out;

    const int rows = B_ * N_;   // 16384

    ts_fix_kernel<<<(B_ * NP1 + 255) / 256, 256>>>(tsraw);
    tileflag_kernel<<<64, 256>>>(amask);
    relprep_kernel<<<B_ * N_ * N_ / 1024, 256>>>(tw, pw);

    __half *wh, *w2h;
    cudaGetSymbolAddress((void**)&wh,  g_Wh);
    cudaGetSymbolAddress((void**)&w2h, g_W2h);
    wprep_kernel<<<dim3(G_ / 32, F_ / 32), dim3(32, 8)>>>(uvqk, wh, G_);
    wprep_kernel<<<dim3(512 / 32, F_ / 32), dim3(32, 8)>>>(out_w, w2h, 512);

    ln1_kernel<<<rows, 256>>>(x, tlmask);

    __half *ah, *o2h;
    cudaGetSymbolAddress((void**)&ah,  g_Ah);
    cudaGetSymbolAddress((void**)&o2h, g_O2h);

    cudaFuncSetAttribute(gemm_mma<1>, cudaFuncAttributeMaxDynamicSharedMemorySize, GEMM_SMEM);
    cudaFuncSetAttribute(gemm_mma<2>, cudaFuncAttributeMaxDynamicSharedMemorySize, GEMM_SMEM);
    cudaFuncSetAttribute(attn_tc, cudaFuncAttributeMaxDynamicSharedMemorySize, ATT_SMEM);

    dim3 g1(G_ / 128, rows / 128);        // (16, 128)
    gemm_mma<1><<<g1, 256, GEMM_SMEM>>>(ah, wh, tlmask, nullptr, nullptr, nullptr);

    dim3 ga(N_ / 128, H_, B_);            // (4, 8, 32)
    attn_tc<<<ga, 256, ATT_SMEM>>>(amask, tlmask);

    ln2_kernel<<<rows, 256>>>(tlmask);

    dim3 g2(512 / 128, rows / 128);       // (4, 128)
    gemm_mma<2><<<g2, 256, GEMM_SMEM>>>(o2h, w2h, nullptr, out_b, x, out);
}

// round 13
// speedup vs baseline: 6.8050x; 1.0413x over previous
#include <cuda_runtime.h>
#include <cuda_fp16.h>
#include <math.h>
#include <stdint.h>

#define B_  32
#define N_  512
#define F_  512
#define H_  8
#define NB_ 128
#define G_  2048
#define NP1 513

// ---------------- scratch ------------------------------------------------------
__device__ __align__(16) __half g_uh[(size_t)B_ * N_ * 512];      // u (gated path)
__device__ __align__(16) __half g_attnh[(size_t)B_ * N_ * 512];
__device__ __align__(16) __half2 g_combo[(size_t)B_ * N_ * N_];   // (rel, mult) per (b,n,m)
__device__ int   g_ts32[B_ * NP1];
__device__ int   g_tflag[64];
__device__ __align__(16) __half g_Ah[(size_t)B_ * N_ * F_];
__device__ __align__(16) __half g_Wh[(size_t)G_ * F_];            // [n][k]
__device__ __align__(16) __half g_O2h[(size_t)B_ * N_ * 512];
__device__ __align__(16) __half g_W2h[(size_t)512 * 512];         // [n][k]
// head-major qkv, layout [b*H+h][n][64]
__device__ __align__(16) __half g_Qh[(size_t)B_ * H_ * N_ * 64];
__device__ __align__(16) __half g_Kh[(size_t)B_ * H_ * N_ * 64];
__device__ __align__(16) __half g_Vh[(size_t)B_ * H_ * N_ * 64];

// ---------------- helpers ------------------------------------------------------
__device__ __forceinline__ uint32_t smem_u32(const void* p) {
    uint32_t a;
    asm("{ .reg .u64 t; cvta.to.shared.u64 t, %1; cvt.u32.u64 %0, t; }" : "=r"(a) : "l"(p));
    return a;
}
__device__ __forceinline__ void cpa16(uint32_t dst, const void* src) {
    asm volatile("cp.async.cg.shared.global [%0], [%1], 16;" :: "r"(dst), "l"(src));
}
__device__ __forceinline__ void cpa_commit() { asm volatile("cp.async.commit_group;" ::: "memory"); }
__device__ __forceinline__ void cpa_wait1()  { asm volatile("cp.async.wait_group 1;" ::: "memory"); }
__device__ __forceinline__ void cpa_wait0()  { asm volatile("cp.async.wait_group 0;" ::: "memory"); }
__device__ __forceinline__ void ldsm_x4(uint32_t* r, uint32_t a) {
    asm volatile("ldmatrix.sync.aligned.m8n8.x4.shared.b16 {%0,%1,%2,%3}, [%4];"
        : "=r"(r[0]), "=r"(r[1]), "=r"(r[2]), "=r"(r[3]) : "r"(a));
}
__device__ __forceinline__ void ldsm_x4_t(uint32_t* r, uint32_t a) {
    asm volatile("ldmatrix.sync.aligned.m8n8.x4.trans.shared.b16 {%0,%1,%2,%3}, [%4];"
        : "=r"(r[0]), "=r"(r[1]), "=r"(r[2]), "=r"(r[3]) : "r"(a));
}
__device__ __forceinline__ void mma_f16(float* d, const uint32_t* a, const uint32_t* b) {
    asm volatile("mma.sync.aligned.m16n8k16.row.col.f32.f16.f16.f32 "
        "{%0,%1,%2,%3}, {%4,%5,%6,%7}, {%8,%9}, {%0,%1,%2,%3};"
        : "+f"(d[0]), "+f"(d[1]), "+f"(d[2]), "+f"(d[3])
        : "r"(a[0]), "r"(a[1]), "r"(a[2]), "r"(a[3]), "r"(b[0]), "r"(b[1]));
}

// ---------------- timestamp canonicalization ----------------------------------
__global__ void ts_fix_kernel(const int* __restrict__ tsraw)
{
    __shared__ int is64;
    if (threadIdx.x == 0) {
        int z = 0;
        #pragma unroll
        for (int i = 1; i < 16; i += 2) z |= tsraw[i];
        is64 = (z == 0) ? 1 : 0;
    }
    __syncthreads();
    int i = blockIdx.x * blockDim.x + threadIdx.x;
    if (i < B_ * NP1) g_ts32[i] = is64 ? tsraw[2 * i] : tsraw[i];
}

// ---------------- per-tile mask flags ------------------------------------------
__global__ void tileflag_kernel(const float* __restrict__ amask)
{
    int t = blockIdx.x;
    int ti = t >> 3, tj = t & 7;
    int any = 0;
    for (int k = threadIdx.x; k < 1024; k += 256) {
        int r = k >> 4, c = (k & 15) * 4;
        float4 v = *(const float4*)(amask + (size_t)(ti * 64 + r) * N_ + tj * 64 + c);
        any |= (v.x != 0.f) | (v.y != 0.f) | (v.z != 0.f) | (v.w != 0.f);
    }
    any = __syncthreads_or(any);
    if (threadIdx.x == 0) g_tflag[t] = any;
}

// ---------------- fused rel+mult table (shared across heads) -------------------
// combo[b][n][m] = ( tw[buck]+pw[N-1+m-n] , amask[n][m]*tl[b,m]*tl[b,n] ) as half2
__global__ void relprep_kernel(const float* __restrict__ tw,
                               const float* __restrict__ pw,
                               const float* __restrict__ amask,
                               const float* __restrict__ tl)
{
    int idx = blockIdx.x * 256 + threadIdx.x;          // quad index
    int b = idx >> 16;                                 // N*N/4 = 2^16 quads per batch
    int q = idx & 0xFFFF;
    int n = q >> 7;                                    // 128 quads per row
    int mq = (q & 127) * 4;
    int tn = g_ts32[b * NP1 + n + 1];
    float tlnv = tl[b * N_ + n];
    float4 am = *(const float4*)(amask + (size_t)n * N_ + mq);
    const float* amp = &am.x;
    uint4 pk;
    uint32_t* pp = &pk.x;
    #pragma unroll
    for (int j = 0; j < 4; j++) {
        int m = mq + j;
        int dt = tn - g_ts32[b * NP1 + m];
        float ad = fmaxf(fabsf((float)dt), 1.0f);
        int bk = min(max((int)(__logf(ad) * (1.0f / 0.301f)), 0), NB_);
        float rel = tw[bk] + pw[N_ - 1 + m - n];
        float mult = amp[j] * tl[b * N_ + m] * tlnv;
        __half2 h = __floats2half2_rn(rel, mult);
        pp[j] = *(uint32_t*)&h;
    }
    *(uint4*)(g_combo + ((size_t)(b * N_ + n)) * N_ + mq) = pk;
}

// ---------------- W transpose + fp16 -------------------------------------------
__global__ void wprep_kernel(const float* __restrict__ W,
                             __half* __restrict__ hp, int ncols)
{
    __shared__ float t[32][33];
    int n0 = blockIdx.x * 32, k0 = blockIdx.y * 32;
    int tx = threadIdx.x, ty = threadIdx.y;   // 32 x 8
    #pragma unroll
    for (int j = 0; j < 4; j++)
        t[ty + j * 8][tx] = W[(size_t)(k0 + ty + j * 8) * ncols + n0 + tx];
    __syncthreads();
    #pragma unroll
    for (int j = 0; j < 4; j++) {
        int row = ty + j * 8;
        hp[(size_t)(n0 + row) * F_ + k0 + tx] = __float2half_rn(t[tx][row]);
    }
}

// ---------------- ln1: LayerNorm -> fp16 ---------------------------------------
__global__ void ln1_kernel(const float* __restrict__ x,
                           const float* __restrict__ tl)
{
    int row = blockIdx.x;
    int tid = threadIdx.x;
    const float* xr = x + (size_t)row * F_;
    float v0 = xr[tid], v1 = xr[tid + 256];
    float s = v0 + v1, sq = v0 * v0 + v1 * v1;
    #pragma unroll
    for (int o = 16; o; o >>= 1) {
        s  += __shfl_down_sync(0xffffffffu, s,  o);
        sq += __shfl_down_sync(0xffffffffu, sq, o);
    }
    __shared__ float red[16];
    __shared__ float mean_s, rstd_s;
    int w = tid >> 5, l = tid & 31;
    if (l == 0) { red[w] = s; red[w + 8] = sq; }
    __syncthreads();
    if (tid == 0) {
        float ts = 0.f, tq = 0.f;
        #pragma unroll
        for (int i = 0; i < 8; i++) { ts += red[i]; tq += red[i + 8]; }
        float m = ts * (1.0f / F_);
        float var = tq * (1.0f / F_) - m * m;
        mean_s = m;
        rstd_s = rsqrtf(var + 1e-6f);
    }
    __syncthreads();
    float t = tl[row];
    float m = mean_s, rs = rstd_s;
    size_t o0 = (size_t)row * F_ + tid;
    g_Ah[o0]       = __float2half_rn((v0 - m) * rs * t);
    g_Ah[o0 + 256] = __float2half_rn((v1 - m) * rs * t);
}

// ---------------- ln2: o_input = u*LN(attn)*tl -> fp16 -------------------------
__global__ void ln2_kernel(const float* __restrict__ tl)
{
    int row = blockIdx.x;
    int tid = threadIdx.x;
    const __half* ar = g_attnh + (size_t)row * 512;
    float v0 = __half2float(ar[tid]);
    float v1 = __half2float(ar[tid + 256]);
    float s = v0 + v1, sq = v0 * v0 + v1 * v1;
    #pragma unroll
    for (int o = 16; o; o >>= 1) {
        s  += __shfl_down_sync(0xffffffffu, s,  o);
        sq += __shfl_down_sync(0xffffffffu, sq, o);
    }
    __shared__ float red[16];
    __shared__ float mean_s, rstd_s;
    int w = tid >> 5, l = tid & 31;
    if (l == 0) { red[w] = s; red[w + 8] = sq; }
    __syncthreads();
    if (tid == 0) {
        float ts = 0.f, tq = 0.f;
        #pragma unroll
        for (int i = 0; i < 8; i++) { ts += red[i]; tq += red[i + 8]; }
        float m = ts * (1.0f / 512.0f);
        float var = tq * (1.0f / 512.0f) - m * m;
        mean_s = m;
        rstd_s = rsqrtf(var + 1e-6f);
    }
    __syncthreads();
    float t = tl[row];
    float m = mean_s, rs = rstd_s;
    float u0 = __half2float(g_uh[(size_t)row * 512 + tid]);
    float u1 = __half2float(g_uh[(size_t)row * 512 + tid + 256]);
    size_t off = (size_t)row * 512 + tid;
    g_O2h[off]       = __float2half_rn(u0 * (v0 - m) * rs * t);
    g_O2h[off + 256] = __float2half_rn(u1 * (v1 - m) * rs * t);
}

// ---------------- GEMM via mma.sync fp16, cp.async 2-stage ---------------------
// per stage 20480 B: A +0, B +10240
#define GST 20480
#define GEMM_SMEM (2 * GST)

template <int MODE>
__global__ void __launch_bounds__(256)
gemm_mma(const __half* __restrict__ Ah, const __half* __restrict__ Bh,
         const float* __restrict__ tl, const float* __restrict__ bias,
         const float* __restrict__ xres, float* __restrict__ Cout)
{
    constexpr int LDS = 40;
    extern __shared__ __align__(16) char dsm[];
    const uint32_t sb = smem_u32(dsm);

    const int tid = threadIdx.x, lane = tid & 31, wid = tid >> 5;
    const int wr = wid & 3, wc = wid >> 2;
    const int m0 = blockIdx.y * 128, n0 = blockIdx.x * 128;

    float d[2][8][4] = {};

    auto load_stage = [&](int kc, int st) {
        const int k0 = kc * 32;
        const uint32_t base = sb + st * GST;
        #pragma unroll
        for (int it = 0; it < 2; it++) {
            int idx = tid + it * 256;
            int r = idx >> 2, c = (idx & 3) * 8;
            uint32_t doff = (uint32_t)(r * LDS + c) * 2;
            cpa16(base + doff,         Ah + (size_t)(m0 + r) * F_ + k0 + c);
            cpa16(base + 10240 + doff, Bh + (size_t)(n0 + r) * F_ + k0 + c);
        }
        cpa_commit();
    };

    load_stage(0, 0);

    for (int kc = 0; kc < 16; kc++) {
        if (kc < 15) { load_stage(kc + 1, (kc + 1) & 1); cpa_wait1(); }
        else         { cpa_wait0(); }
        __syncthreads();

        const uint32_t base = sb + (kc & 1) * GST;
        #pragma unroll
        for (int ks = 0; ks < 2; ks++) {
            uint32_t a[2][4], bb[4][4];
            const int g2 = lane >> 3;     // 0..3
            #pragma unroll
            for (int mi = 0; mi < 2; mi++) {
                int row = wr * 32 + mi * 16 + (lane & 15);
                uint32_t off = (uint32_t)(row * LDS + ks * 16 + (lane >> 4) * 8) * 2;
                ldsm_x4(a[mi], base + off);
            }
            #pragma unroll
            for (int nj = 0; nj < 4; nj++) {
                int row = wc * 64 + nj * 16 + (g2 >> 1) * 8 + (lane & 7);
                int col = ks * 16 + (g2 & 1) * 8;
                ldsm_x4(bb[nj], base + 10240 + (uint32_t)(row * LDS + col) * 2);
            }
            #pragma unroll
            for (int mi = 0; mi < 2; mi++)
                #pragma unroll
                for (int nj = 0; nj < 4; nj++) {
                    mma_f16(d[mi][2 * nj + 0], a[mi], &bb[nj][0]);
                    mma_f16(d[mi][2 * nj + 1], a[mi], &bb[nj][2]);
                }
        }
        __syncthreads();
    }

    #pragma unroll
    for (int mi = 0; mi < 2; mi++) {
        int rbase = m0 + wr * 32 + mi * 16 + (lane >> 2);
        #pragma unroll
        for (int half = 0; half < 2; half++) {
            int row = rbase + half * 8;
            float tlv = (MODE == 1) ? tl[row] : 0.0f;
            #pragma unroll
            for (int ni = 0; ni < 8; ni++) {
                int col = n0 + wc * 64 + ni * 8 + (lane & 3) * 2;
                float v0 = d[mi][ni][half * 2 + 0];
                float v1 = d[mi][ni][half * 2 + 1];
                if (MODE == 1) {
                    v0 = __fdividef(v0, 1.0f + __expf(-v0)) * tlv;
                    v1 = __fdividef(v1, 1.0f + __expf(-v1)) * tlv;
                    __half2 hp = __floats2half2_rn(v0, v1);
                    if (col < 512) {
                        *(__half2*)(g_uh + (size_t)row * 512 + col) = hp;
                    } else {
                        int hh = (col >> 6) & 7;
                        int dd = col & 63;
                        size_t off = (((size_t)(row >> 9) * H_ + hh) * N_ + (row & 511)) * 64 + dd;
                        if (col < 1024)      *(__half2*)(g_Vh + off) = hp;
                        else if (col < 1536) *(__half2*)(g_Qh + off) = hp;
                        else                 *(__half2*)(g_Kh + off) = hp;
                    }
                } else {
                    v0 += bias[col]     + xres[(size_t)row * 512 + col];
                    v1 += bias[col + 1] + xres[(size_t)row * 512 + col + 1];
                    *(float2*)(Cout + (size_t)row * 512 + col) = make_float2(v0, v1);
                }
            }
        }
    }
}

// ---------------- tensor-core attention: 128 q-rows, fp16, 2-stage KV ----------
#define DS    72
#define SQ    0
#define SKV0  18432         // per stage: K +0, V +9216; stage size 18432
#define KVST  18432
#define SP    (SKV0 + 2 * KVST)          // 55296
#define ATT_SMEM (SP + 18432)            // 73728

__global__ void __launch_bounds__(256)
attn_tc()
{
    extern __shared__ __align__(16) char sm[];
    const uint32_t sb = smem_u32(sm);
    const int tid = threadIdx.x, lane = tid & 31, w = tid >> 5;
    const int n0 = blockIdx.x * 128, h = blockIdx.y, b = blockIdx.z;
    const int bh = b * H_ + h;

    // Q -> smem (128 rows)
    #pragma unroll
    for (int it = 0; it < 4; it++) {
        int idx = tid + it * 256;
        int r = idx >> 3, c = (idx & 7) * 8;
        *(float4*)(sm + SQ + (r * DS + c) * 2) =
            *(const float4*)(g_Qh + ((size_t)bh * N_ + n0 + r) * 64 + c);
    }

    int mlist[8];
    int nact = 0;
    const int tr = n0 >> 6;          // covers flag rows tr, tr+1
    #pragma unroll
    for (int t = 0; t < 8; t++)
        if (g_tflag[tr * 8 + t] | g_tflag[(tr + 1) * 8 + t]) mlist[nact++] = t * 64;

    auto load_kv = [&](int m0, int st) {
        const uint32_t base = sb + SKV0 + st * KVST;
        #pragma unroll
        for (int it = 0; it < 2; it++) {
            int idx = tid + it * 256;
            int r = idx >> 3, c = (idx & 7) * 8;
            uint32_t doff = (uint32_t)(r * DS + c) * 2;
            size_t src = ((size_t)bh * N_ + m0 + r) * 64 + c;
            cpa16(base + doff,        g_Kh + src);
            cpa16(base + 9216 + doff, g_Vh + src);
        }
        cpa_commit();
    };

    float o[8][4] = {};

    if (nact > 0) load_kv(mlist[0], 0);

    for (int i = 0; i < nact; i++) {
        if (i + 1 < nact) { load_kv(mlist[i + 1], (i + 1) & 1); cpa_wait1(); }
        else              { cpa_wait0(); }
        __syncthreads();

        const int m0 = mlist[i];
        const uint32_t kb = sb + SKV0 + (i & 1) * KVST;
        const int g2 = lane >> 3;

        // S = Q K^T
        float s[8][4] = {};
        #pragma unroll
        for (int ks = 0; ks < 4; ks++) {
            uint32_t q[4];
            int arow = w * 16 + (lane & 15);
            uint32_t aoff = (uint32_t)(arow * DS + ks * 16 + (lane >> 4) * 8) * 2;
            ldsm_x4(q, sb + SQ + aoff);
            #pragma unroll
            for (int t = 0; t < 4; t++) {
                uint32_t kk[4];
                int brow = t * 16 + (g2 >> 1) * 8 + (lane & 7);
                int bcol = ks * 16 + (g2 & 1) * 8;
                ldsm_x4(kk, kb + (uint32_t)(brow * DS + bcol) * 2);
                mma_f16(s[2 * t + 0], q, &kk[0]);
                mma_f16(s[2 * t + 1], q, &kk[2]);
            }
        }

        // epilogue: fused (rel, mult) table; P unscaled by 1/N (folded into O)
        #pragma unroll
        for (int half = 0; half < 2; half++) {
            int r = w * 16 + (lane >> 2) + half * 8;
            int n = n0 + r;
            const __half2* crow = g_combo + ((size_t)(b * N_ + n)) * N_;
            #pragma unroll
            for (int ni = 0; ni < 8; ni++) {
                int c = ni * 8 + (lane & 3) * 2;
                int m = m0 + c;
                uint2 pk = *(const uint2*)(crow + m);
                float2 f0 = __half22float2(*(__half2*)&pk.x);
                float2 f1 = __half22float2(*(__half2*)&pk.y);
                float x0 = s[ni][half * 2 + 0] + f0.x;
                float x1 = s[ni][half * 2 + 1] + f1.x;
                x0 = __fdividef(x0, 1.0f + __expf(-x0)) * f0.y;
                x1 = __fdividef(x1, 1.0f + __expf(-x1)) * f1.y;
                __half2 hp = __floats2half2_rn(x0, x1);
                *(uint32_t*)(sm + SP + (r * DS + c) * 2) = *(uint32_t*)&hp;
            }
        }
        __syncwarp();

        // O += P V; V via ldmatrix.trans x4
        #pragma unroll
        for (int ks = 0; ks < 4; ks++) {
            uint32_t p[4];
            int arow = w * 16 + (lane & 15);
            uint32_t aoff = (uint32_t)(arow * DS + ks * 16 + (lane >> 4) * 8) * 2;
            ldsm_x4(p, sb + SP + aoff);
            #pragma unroll
            for (int t = 0; t < 4; t++) {
                uint32_t v[4];
                int vrow = ks * 16 + (lane & 15);
                int vcol = (2 * t + (lane >> 4)) * 8;
                ldsm_x4_t(v, kb + 9216 + (uint32_t)(vrow * DS + vcol) * 2);
                mma_f16(o[2 * t + 0], p, &v[0]);
                mma_f16(o[2 * t + 1], p, &v[2]);
            }
        }
        __syncthreads();
    }

    #pragma unroll
    for (int half = 0; half < 2; half++) {
        int r = w * 16 + (lane >> 2) + half * 8;
        int n = n0 + r;
        #pragma unroll
        for (int ni = 0; ni < 8; ni++) {
            int c = ni * 8 + (lane & 3) * 2;
            __half2 hp = __floats2half2_rn(o[ni][half * 2] * (1.0f / N_),
                                           o[ni][half * 2 + 1] * (1.0f / N_));
            *(__half2*)(g_attnh + ((size_t)(b * N_ + n)) * 512 + h * 64 + c) = hp;
        }
    }
}

// ---------------- launch -------------------------------------------------------
// Order chosen so launch #6 (0-based 5) is gemm_mma<1>: ncu -s 5 -c 1 profiles it.
extern "C" void kernel_launch(void* const* d_in, const int* in_sizes, int n_in,
                              void* d_out, int out_size)
{
    const float* x      = (const float*)d_in[0];
    const float* tlmask = (const float*)d_in[1];
    const float* amask  = (const float*)d_in[2];
    const float* uvqk   = (const float*)d_in[3];
    const float* out_w  = (const float*)d_in[4];
    const float* out_b  = (const float*)d_in[5];
    const float* tw     = (const float*)d_in[6];
    const float* pw     = (const float*)d_in[7];
    const int*   tsraw  = (const int*)d_in[8];
    float*       out    = (float*)d_out;

    const int rows = B_ * N_;   // 16384

    __half *wh, *w2h, *ah, *o2h;
    cudaGetSymbolAddress((void**)&wh,  g_Wh);
    cudaGetSymbolAddress((void**)&w2h, g_W2h);
    cudaGetSymbolAddress((void**)&ah,  g_Ah);
    cudaGetSymbolAddress((void**)&o2h, g_O2h);

    cudaFuncSetAttribute(gemm_mma<1>, cudaFuncAttributeMaxDynamicSharedMemorySize, GEMM_SMEM);
    cudaFuncSetAttribute(gemm_mma<2>, cudaFuncAttributeMaxDynamicSharedMemorySize, GEMM_SMEM);
    cudaFuncSetAttribute(attn_tc, cudaFuncAttributeMaxDynamicSharedMemorySize, ATT_SMEM);

    ts_fix_kernel<<<(B_ * NP1 + 255) / 256, 256>>>(tsraw);                      // 0
    tileflag_kernel<<<64, 256>>>(amask);                                        // 1
    wprep_kernel<<<dim3(G_ / 32, F_ / 32), dim3(32, 8)>>>(uvqk, wh, G_);        // 2
    wprep_kernel<<<dim3(512 / 32, F_ / 32), dim3(32, 8)>>>(out_w, w2h, 512);    // 3
    ln1_kernel<<<rows, 256>>>(x, tlmask);                                       // 4

    dim3 g1(G_ / 128, rows / 128);                                              // 5 (profiled)
    gemm_mma<1><<<g1, 256, GEMM_SMEM>>>(ah, wh, tlmask, nullptr, nullptr, nullptr);

    relprep_kernel<<<B_ * N_ * N_ / 1024, 256>>>(tw, pw, amask, tlmask);        // 6

    dim3 ga(N_ / 128, H_, B_);                                                  // 7
    attn_tc<<<ga, 256, ATT_SMEM>>>();

    ln2_kernel<<<rows, 256>>>(tlmask);                                          // 8

    dim3 g2(512 / 128, rows / 128);                                             // 9
    gemm_mma<2><<<g2, 256, GEMM_SMEM>>>(o2h, w2h, nullptr, out_b, x, out);
}

// round 14
// speedup vs baseline: 7.0301x; 1.0331x over previous
#include <cuda_runtime.h>
#include <cuda_fp16.h>
#include <math.h>
#include <stdint.h>

#define B_  32
#define N_  512
#define F_  512
#define H_  8
#define NB_ 128
#define G_  2048
#define NP1 513

// ---------------- scratch ------------------------------------------------------
__device__ __align__(16) __half g_uh[(size_t)B_ * N_ * 512];      // u (gated path)
__device__ __align__(16) __half g_attnh[(size_t)B_ * N_ * 512];
__device__ __align__(16) __half2 g_combo[(size_t)B_ * N_ * N_];   // (rel, mult) per (b,n,m)
__device__ int   g_ts32[B_ * NP1];
__device__ int   g_tflag[64];
__device__ __align__(16) __half g_Ah[(size_t)B_ * N_ * F_];
__device__ __align__(16) __half g_Wh[(size_t)G_ * F_];            // [n][k]
__device__ __align__(16) __half g_O2h[(size_t)B_ * N_ * 512];
__device__ __align__(16) __half g_W2h[(size_t)512 * 512];         // [n][k]
// head-major qkv, layout [b*H+h][n][64]
__device__ __align__(16) __half g_Qh[(size_t)B_ * H_ * N_ * 64];
__device__ __align__(16) __half g_Kh[(size_t)B_ * H_ * N_ * 64];
__device__ __align__(16) __half g_Vh[(size_t)B_ * H_ * N_ * 64];

// ---------------- helpers ------------------------------------------------------
__device__ __forceinline__ uint32_t smem_u32(const void* p) {
    uint32_t a;
    asm("{ .reg .u64 t; cvta.to.shared.u64 t, %1; cvt.u32.u64 %0, t; }" : "=r"(a) : "l"(p));
    return a;
}
__device__ __forceinline__ void cpa16(uint32_t dst, const void* src) {
    asm volatile("cp.async.cg.shared.global [%0], [%1], 16;" :: "r"(dst), "l"(src));
}
__device__ __forceinline__ void cpa_commit() { asm volatile("cp.async.commit_group;" ::: "memory"); }
__device__ __forceinline__ void cpa_wait1()  { asm volatile("cp.async.wait_group 1;" ::: "memory"); }
__device__ __forceinline__ void cpa_wait0()  { asm volatile("cp.async.wait_group 0;" ::: "memory"); }
__device__ __forceinline__ void ldsm_x4(uint32_t* r, uint32_t a) {
    asm volatile("ldmatrix.sync.aligned.m8n8.x4.shared.b16 {%0,%1,%2,%3}, [%4];"
        : "=r"(r[0]), "=r"(r[1]), "=r"(r[2]), "=r"(r[3]) : "r"(a));
}
__device__ __forceinline__ void ldsm_x4_t(uint32_t* r, uint32_t a) {
    asm volatile("ldmatrix.sync.aligned.m8n8.x4.trans.shared.b16 {%0,%1,%2,%3}, [%4];"
        : "=r"(r[0]), "=r"(r[1]), "=r"(r[2]), "=r"(r[3]) : "r"(a));
}
__device__ __forceinline__ void mma_f16(float* d, const uint32_t* a, const uint32_t* b) {
    asm volatile("mma.sync.aligned.m16n8k16.row.col.f32.f16.f16.f32 "
        "{%0,%1,%2,%3}, {%4,%5,%6,%7}, {%8,%9}, {%0,%1,%2,%3};"
        : "+f"(d[0]), "+f"(d[1]), "+f"(d[2]), "+f"(d[3])
        : "r"(a[0]), "r"(a[1]), "r"(a[2]), "r"(a[3]), "r"(b[0]), "r"(b[1]));
}

// ---------------- timestamp canonicalization ----------------------------------
__global__ void ts_fix_kernel(const int* __restrict__ tsraw)
{
    __shared__ int is64;
    if (threadIdx.x == 0) {
        int z = 0;
        #pragma unroll
        for (int i = 1; i < 16; i += 2) z |= tsraw[i];
        is64 = (z == 0) ? 1 : 0;
    }
    __syncthreads();
    int i = blockIdx.x * blockDim.x + threadIdx.x;
    if (i < B_ * NP1) g_ts32[i] = is64 ? tsraw[2 * i] : tsraw[i];
}

// ---------------- per-tile mask flags ------------------------------------------
__global__ void tileflag_kernel(const float* __restrict__ amask)
{
    int t = blockIdx.x;
    int ti = t >> 3, tj = t & 7;
    int any = 0;
    for (int k = threadIdx.x; k < 1024; k += 256) {
        int r = k >> 4, c = (k & 15) * 4;
        float4 v = *(const float4*)(amask + (size_t)(ti * 64 + r) * N_ + tj * 64 + c);
        any |= (v.x != 0.f) | (v.y != 0.f) | (v.z != 0.f) | (v.w != 0.f);
    }
    any = __syncthreads_or(any);
    if (threadIdx.x == 0) g_tflag[t] = any;
}

// ---------------- fused rel+mult table (shared across heads) -------------------
__global__ void relprep_kernel(const float* __restrict__ tw,
                               const float* __restrict__ pw,
                               const float* __restrict__ amask,
                               const float* __restrict__ tl)
{
    int idx = blockIdx.x * 256 + threadIdx.x;          // quad index
    int b = idx >> 16;                                 // N*N/4 = 2^16 quads per batch
    int q = idx & 0xFFFF;
    int n = q >> 7;
    int mq = (q & 127) * 4;
    int tn = g_ts32[b * NP1 + n + 1];
    float tlnv = tl[b * N_ + n];
    float4 am = *(const float4*)(amask + (size_t)n * N_ + mq);
    const float* amp = &am.x;
    uint4 pk;
    uint32_t* pp = &pk.x;
    #pragma unroll
    for (int j = 0; j < 4; j++) {
        int m = mq + j;
        int dt = tn - g_ts32[b * NP1 + m];
        float ad = fmaxf(fabsf((float)dt), 1.0f);
        int bk = min(max((int)(__logf(ad) * (1.0f / 0.301f)), 0), NB_);
        float rel = tw[bk] + pw[N_ - 1 + m - n];
        float mult = amp[j] * tl[b * N_ + m] * tlnv;
        __half2 h = __floats2half2_rn(rel, mult);
        pp[j] = *(uint32_t*)&h;
    }
    *(uint4*)(g_combo + ((size_t)(b * N_ + n)) * N_ + mq) = pk;
}

// ---------------- W transpose + fp16 -------------------------------------------
__global__ void wprep_kernel(const float* __restrict__ W,
                             __half* __restrict__ hp, int ncols)
{
    __shared__ float t[32][33];
    int n0 = blockIdx.x * 32, k0 = blockIdx.y * 32;
    int tx = threadIdx.x, ty = threadIdx.y;   // 32 x 8
    #pragma unroll
    for (int j = 0; j < 4; j++)
        t[ty + j * 8][tx] = W[(size_t)(k0 + ty + j * 8) * ncols + n0 + tx];
    __syncthreads();
    #pragma unroll
    for (int j = 0; j < 4; j++) {
        int row = ty + j * 8;
        hp[(size_t)(n0 + row) * F_ + k0 + tx] = __float2half_rn(t[tx][row]);
    }
}

// ---------------- ln1: LayerNorm -> fp16 ---------------------------------------
__global__ void ln1_kernel(const float* __restrict__ x,
                           const float* __restrict__ tl)
{
    int row = blockIdx.x;
    int tid = threadIdx.x;
    const float* xr = x + (size_t)row * F_;
    float v0 = xr[tid], v1 = xr[tid + 256];
    float s = v0 + v1, sq = v0 * v0 + v1 * v1;
    #pragma unroll
    for (int o = 16; o; o >>= 1) {
        s  += __shfl_down_sync(0xffffffffu, s,  o);
        sq += __shfl_down_sync(0xffffffffu, sq, o);
    }
    __shared__ float red[16];
    __shared__ float mean_s, rstd_s;
    int w = tid >> 5, l = tid & 31;
    if (l == 0) { red[w] = s; red[w + 8] = sq; }
    __syncthreads();
    if (tid == 0) {
        float ts = 0.f, tq = 0.f;
        #pragma unroll
        for (int i = 0; i < 8; i++) { ts += red[i]; tq += red[i + 8]; }
        float m = ts * (1.0f / F_);
        float var = tq * (1.0f / F_) - m * m;
        mean_s = m;
        rstd_s = rsqrtf(var + 1e-6f);
    }
    __syncthreads();
    float t = tl[row];
    float m = mean_s, rs = rstd_s;
    size_t o0 = (size_t)row * F_ + tid;
    g_Ah[o0]       = __float2half_rn((v0 - m) * rs * t);
    g_Ah[o0 + 256] = __float2half_rn((v1 - m) * rs * t);
}

// ---------------- ln2: o_input = u*LN(attn)*tl -> fp16 -------------------------
__global__ void ln2_kernel(const float* __restrict__ tl)
{
    int row = blockIdx.x;
    int tid = threadIdx.x;
    const __half* ar = g_attnh + (size_t)row * 512;
    float v0 = __half2float(ar[tid]);
    float v1 = __half2float(ar[tid + 256]);
    float s = v0 + v1, sq = v0 * v0 + v1 * v1;
    #pragma unroll
    for (int o = 16; o; o >>= 1) {
        s  += __shfl_down_sync(0xffffffffu, s,  o);
        sq += __shfl_down_sync(0xffffffffu, sq, o);
    }
    __shared__ float red[16];
    __shared__ float mean_s, rstd_s;
    int w = tid >> 5, l = tid & 31;
    if (l == 0) { red[w] = s; red[w + 8] = sq; }
    __syncthreads();
    if (tid == 0) {
        float ts = 0.f, tq = 0.f;
        #pragma unroll
        for (int i = 0; i < 8; i++) { ts += red[i]; tq += red[i + 8]; }
        float m = ts * (1.0f / 512.0f);
        float var = tq * (1.0f / 512.0f) - m * m;
        mean_s = m;
        rstd_s = rsqrtf(var + 1e-6f);
    }
    __syncthreads();
    float t = tl[row];
    float m = mean_s, rs = rstd_s;
    float u0 = __half2float(g_uh[(size_t)row * 512 + tid]);
    float u1 = __half2float(g_uh[(size_t)row * 512 + tid + 256]);
    size_t off = (size_t)row * 512 + tid;
    g_O2h[off]       = __float2half_rn(u0 * (v0 - m) * rs * t);
    g_O2h[off + 256] = __float2half_rn(u1 * (v1 - m) * rs * t);
}

// ---------------- GEMM via mma.sync fp16, cp.async 3-stage, 1 sync/iter --------
// per stage 20480 B: A +0, B +10240
#define GST 20480
#define GEMM_SMEM (3 * GST)

template <int MODE>
__global__ void __launch_bounds__(256)
gemm_mma(const __half* __restrict__ Ah, const __half* __restrict__ Bh,
         const float* __restrict__ tl, const float* __restrict__ bias,
         const float* __restrict__ xres, float* __restrict__ Cout)
{
    constexpr int LDS = 40;
    extern __shared__ __align__(16) char dsm[];
    const uint32_t sb = smem_u32(dsm);

    const int tid = threadIdx.x, lane = tid & 31, wid = tid >> 5;
    const int wr = wid & 3, wc = wid >> 2;
    const int m0 = blockIdx.y * 128, n0 = blockIdx.x * 128;

    float d[2][8][4] = {};

    auto load_stage = [&](int kc, int st) {
        const int k0 = kc * 32;
        const uint32_t base = sb + st * GST;
        #pragma unroll
        for (int it = 0; it < 2; it++) {
            int idx = tid + it * 256;
            int r = idx >> 2, c = (idx & 3) * 8;
            uint32_t doff = (uint32_t)(r * LDS + c) * 2;
            cpa16(base + doff,         Ah + (size_t)(m0 + r) * F_ + k0 + c);
            cpa16(base + 10240 + doff, Bh + (size_t)(n0 + r) * F_ + k0 + c);
        }
        cpa_commit();
    };

    load_stage(0, 0);
    load_stage(1, 1);

    for (int kc = 0; kc < 16; kc++) {
        if (kc + 1 < 16) cpa_wait1(); else cpa_wait0();
        __syncthreads();                 // also releases buffer (kc+2)%3 = (kc-1)%3
        if (kc + 2 < 16) load_stage(kc + 2, (kc + 2) % 3);

        const uint32_t base = sb + (kc % 3) * GST;
        #pragma unroll
        for (int ks = 0; ks < 2; ks++) {
            uint32_t a[2][4], bb[4][4];
            const int g2 = lane >> 3;     // 0..3
            #pragma unroll
            for (int mi = 0; mi < 2; mi++) {
                int row = wr * 32 + mi * 16 + (lane & 15);
                uint32_t off = (uint32_t)(row * LDS + ks * 16 + (lane >> 4) * 8) * 2;
                ldsm_x4(a[mi], base + off);
            }
            #pragma unroll
            for (int nj = 0; nj < 4; nj++) {
                int row = wc * 64 + nj * 16 + (g2 >> 1) * 8 + (lane & 7);
                int col = ks * 16 + (g2 & 1) * 8;
                ldsm_x4(bb[nj], base + 10240 + (uint32_t)(row * LDS + col) * 2);
            }
            #pragma unroll
            for (int mi = 0; mi < 2; mi++)
                #pragma unroll
                for (int nj = 0; nj < 4; nj++) {
                    mma_f16(d[mi][2 * nj + 0], a[mi], &bb[nj][0]);
                    mma_f16(d[mi][2 * nj + 1], a[mi], &bb[nj][2]);
                }
        }
    }

    #pragma unroll
    for (int mi = 0; mi < 2; mi++) {
        int rbase = m0 + wr * 32 + mi * 16 + (lane >> 2);
        #pragma unroll
        for (int half = 0; half < 2; half++) {
            int row = rbase + half * 8;
            float tlv = (MODE == 1) ? tl[row] : 0.0f;
            #pragma unroll
            for (int ni = 0; ni < 8; ni++) {
                int col = n0 + wc * 64 + ni * 8 + (lane & 3) * 2;
                float v0 = d[mi][ni][half * 2 + 0];
                float v1 = d[mi][ni][half * 2 + 1];
                if (MODE == 1) {
                    v0 = __fdividef(v0, 1.0f + __expf(-v0)) * tlv;
                    v1 = __fdividef(v1, 1.0f + __expf(-v1)) * tlv;
                    __half2 hp = __floats2half2_rn(v0, v1);
                    if (col < 512) {
                        *(__half2*)(g_uh + (size_t)row * 512 + col) = hp;
                    } else {
                        int hh = (col >> 6) & 7;
                        int dd = col & 63;
                        size_t off = (((size_t)(row >> 9) * H_ + hh) * N_ + (row & 511)) * 64 + dd;
                        if (col < 1024)      *(__half2*)(g_Vh + off) = hp;
                        else if (col < 1536) *(__half2*)(g_Qh + off) = hp;
                        else                 *(__half2*)(g_Kh + off) = hp;
                    }
                } else {
                    v0 += bias[col]     + xres[(size_t)row * 512 + col];
                    v1 += bias[col + 1] + xres[(size_t)row * 512 + col + 1];
                    *(float2*)(Cout + (size_t)row * 512 + col) = make_float2(v0, v1);
                }
            }
        }
    }
}

// ---------------- tensor-core attention: 128 q-rows, 3-stage KV, 1 sync/iter ---
#define DS    72
#define SQ    0
#define SKV0  18432         // per stage: K +0, V +9216; stage size 18432
#define KVST  18432
#define SP    (SKV0 + 3 * KVST)          // 73728
#define ATT_SMEM (SP + 18432)            // 92160

__global__ void __launch_bounds__(256)
attn_tc()
{
    extern __shared__ __align__(16) char sm[];
    const uint32_t sb = smem_u32(sm);
    const int tid = threadIdx.x, lane = tid & 31, w = tid >> 5;
    const int n0 = blockIdx.x * 128, h = blockIdx.y, b = blockIdx.z;
    const int bh = b * H_ + h;

    // Q -> smem (128 rows)
    #pragma unroll
    for (int it = 0; it < 4; it++) {
        int idx = tid + it * 256;
        int r = idx >> 3, c = (idx & 7) * 8;
        *(float4*)(sm + SQ + (r * DS + c) * 2) =
            *(const float4*)(g_Qh + ((size_t)bh * N_ + n0 + r) * 64 + c);
    }

    int mlist[8];
    int nact = 0;
    const int tr = n0 >> 6;
    #pragma unroll
    for (int t = 0; t < 8; t++)
        if (g_tflag[tr * 8 + t] | g_tflag[(tr + 1) * 8 + t]) mlist[nact++] = t * 64;

    auto load_kv = [&](int m0, int st) {
        const uint32_t base = sb + SKV0 + st * KVST;
        #pragma unroll
        for (int it = 0; it < 2; it++) {
            int idx = tid + it * 256;
            int r = idx >> 3, c = (idx & 7) * 8;
            uint32_t doff = (uint32_t)(r * DS + c) * 2;
            size_t src = ((size_t)bh * N_ + m0 + r) * 64 + c;
            cpa16(base + doff,        g_Kh + src);
            cpa16(base + 9216 + doff, g_Vh + src);
        }
        cpa_commit();
    };

    if (nact > 0) load_kv(mlist[0], 0);
    if (nact > 1) load_kv(mlist[1], 1);

    __syncthreads();                       // Q visible to all warps

    // hoist Q fragments (reused across all tiles)
    uint32_t qf[4][4];
    {
        int arow = w * 16 + (lane & 15);
        #pragma unroll
        for (int ks = 0; ks < 4; ks++) {
            uint32_t aoff = (uint32_t)(arow * DS + ks * 16 + (lane >> 4) * 8) * 2;
            ldsm_x4(qf[ks], sb + SQ + aoff);
        }
    }

    float o[8][4] = {};

    for (int i = 0; i < nact; i++) {
        if (i + 1 < nact) cpa_wait1(); else cpa_wait0();
        __syncthreads();                   // releases KV buffer (i+2)%3 = (i-1)%3
        if (i + 2 < nact) load_kv(mlist[i + 2], (i + 2) % 3);

        const int m0 = mlist[i];
        const uint32_t kb = sb + SKV0 + (i % 3) * KVST;
        const int g2 = lane >> 3;

        // S = Q K^T
        float s[8][4] = {};
        #pragma unroll
        for (int ks = 0; ks < 4; ks++) {
            #pragma unroll
            for (int t = 0; t < 4; t++) {
                uint32_t kk[4];
                int brow = t * 16 + (g2 >> 1) * 8 + (lane & 7);
                int bcol = ks * 16 + (g2 & 1) * 8;
                ldsm_x4(kk, kb + (uint32_t)(brow * DS + bcol) * 2);
                mma_f16(s[2 * t + 0], qf[ks], &kk[0]);
                mma_f16(s[2 * t + 1], qf[ks], &kk[2]);
            }
        }

        // epilogue: fused (rel, mult) table; P unscaled by 1/N (folded into O)
        #pragma unroll
        for (int half = 0; half < 2; half++) {
            int r = w * 16 + (lane >> 2) + half * 8;
            int n = n0 + r;
            const __half2* crow = g_combo + ((size_t)(b * N_ + n)) * N_;
            #pragma unroll
            for (int ni = 0; ni < 8; ni++) {
                int c = ni * 8 + (lane & 3) * 2;
                int m = m0 + c;
                uint2 pk = *(const uint2*)(crow + m);
                float2 f0 = __half22float2(*(__half2*)&pk.x);
                float2 f1 = __half22float2(*(__half2*)&pk.y);
                float x0 = s[ni][half * 2 + 0] + f0.x;
                float x1 = s[ni][half * 2 + 1] + f1.x;
                x0 = __fdividef(x0, 1.0f + __expf(-x0)) * f0.y;
                x1 = __fdividef(x1, 1.0f + __expf(-x1)) * f1.y;
                __half2 hp = __floats2half2_rn(x0, x1);
                *(uint32_t*)(sm + SP + (r * DS + c) * 2) = *(uint32_t*)&hp;
            }
        }
        __syncwarp();                      // P rows are warp-private

        // O += P V; V via ldmatrix.trans x4
        #pragma unroll
        for (int ks = 0; ks < 4; ks++) {
            uint32_t p[4];
            int arow = w * 16 + (lane & 15);
            uint32_t aoff = (uint32_t)(arow * DS + ks * 16 + (lane >> 4) * 8) * 2;
            ldsm_x4(p, sb + SP + aoff);
            #pragma unroll
            for (int t = 0; t < 4; t++) {
                uint32_t v[4];
                int vrow = ks * 16 + (lane & 15);
                int vcol = (2 * t + (lane >> 4)) * 8;
                ldsm_x4_t(v, kb + 9216 + (uint32_t)(vrow * DS + vcol) * 2);
                mma_f16(o[2 * t + 0], p, &v[0]);
                mma_f16(o[2 * t + 1], p, &v[2]);
            }
        }
    }

    #pragma unroll
    for (int half = 0; half < 2; half++) {
        int r = w * 16 + (lane >> 2) + half * 8;
        int n = n0 + r;
        #pragma unroll
        for (int ni = 0; ni < 8; ni++) {
            int c = ni * 8 + (lane & 3) * 2;
            __half2 hp = __floats2half2_rn(o[ni][half * 2] * (1.0f / N_),
                                           o[ni][half * 2 + 1] * (1.0f / N_));
            *(__half2*)(g_attnh + ((size_t)(b * N_ + n)) * 512 + h * 64 + c) = hp;
        }
    }
}

// ---------------- launch -------------------------------------------------------
extern "C" void kernel_launch(void* const* d_in, const int* in_sizes, int n_in,
                              void* d_out, int out_size)
{
    const float* x      = (const float*)d_in[0];
    const float* tlmask = (const float*)d_in[1];
    const float* amask  = (const float*)d_in[2];
    const float* uvqk   = (const float*)d_in[3];
    const float* out_w  = (const float*)d_in[4];
    const float* out_b  = (const float*)d_in[5];
    const float* tw     = (const float*)d_in[6];
    const float* pw     = (const float*)d_in[7];
    const int*   tsraw  = (const int*)d_in[8];
    float*       out    = (float*)d_out;

    const int rows = B_ * N_;   // 16384

    __half *wh, *w2h, *ah, *o2h;
    cudaGetSymbolAddress((void**)&wh,  g_Wh);
    cudaGetSymbolAddress((void**)&w2h, g_W2h);
    cudaGetSymbolAddress((void**)&ah,  g_Ah);
    cudaGetSymbolAddress((void**)&o2h, g_O2h);

    cudaFuncSetAttribute(gemm_mma<1>, cudaFuncAttributeMaxDynamicSharedMemorySize, GEMM_SMEM);
    cudaFuncSetAttribute(gemm_mma<2>, cudaFuncAttributeMaxDynamicSharedMemorySize, GEMM_SMEM);
    cudaFuncSetAttribute(attn_tc, cudaFuncAttributeMaxDynamicSharedMemorySize, ATT_SMEM);

    ts_fix_kernel<<<(B_ * NP1 + 255) / 256, 256>>>(tsraw);
    tileflag_kernel<<<64, 256>>>(amask);
    wprep_kernel<<<dim3(G_ / 32, F_ / 32), dim3(32, 8)>>>(uvqk, wh, G_);
    wprep_kernel<<<dim3(512 / 32, F_ / 32), dim3(32, 8)>>>(out_w, w2h, 512);
    ln1_kernel<<<rows, 256>>>(x, tlmask);

    dim3 g1(G_ / 128, rows / 128);
    gemm_mma<1><<<g1, 256, GEMM_SMEM>>>(ah, wh, tlmask, nullptr, nullptr, nullptr);

    relprep_kernel<<<B_ * N_ * N_ / 1024, 256>>>(tw, pw, amask, tlmask);

    dim3 ga(N_ / 128, H_, B_);
    attn_tc<<<ga, 256, ATT_SMEM>>>();

    ln2_kernel<<<rows, 256>>>(tlmask);

    dim3 g2(512 / 128, rows / 128);
    gemm_mma<2><<<g2, 256, GEMM_SMEM>>>(o2h, w2h, nullptr, out_b, x, out);
}

// round 15
// speedup vs baseline: 7.1968x; 1.0237x over previous
#include <cuda_runtime.h>
#include <cuda_fp16.h>
#include <math.h>
#include <stdint.h>

#define B_  32
#define N_  512
#define F_  512
#define H_  8
#define NB_ 128
#define G_  2048
#define NP1 513

// ---------------- scratch ------------------------------------------------------
__device__ __align__(16) __half g_uh[(size_t)B_ * N_ * 512];      // u (gated path)
__device__ __align__(16) __half g_attnh[(size_t)B_ * N_ * 512];
__device__ __align__(16) __half2 g_combo[(size_t)B_ * N_ * N_];   // (rel, mult) per (b,n,m)
__device__ int   g_ts32[B_ * NP1];
__device__ int   g_tflag[64];
__device__ __align__(16) __half g_Ah[(size_t)B_ * N_ * F_];
__device__ __align__(16) __half g_Wh[(size_t)G_ * F_];            // [n][k]
__device__ __align__(16) __half g_O2h[(size_t)B_ * N_ * 512];
__device__ __align__(16) __half g_W2h[(size_t)512 * 512];         // [n][k]
// head-major qkv, layout [b*H+h][n][64]
__device__ __align__(16) __half g_Qh[(size_t)B_ * H_ * N_ * 64];
__device__ __align__(16) __half g_Kh[(size_t)B_ * H_ * N_ * 64];
__device__ __align__(16) __half g_Vh[(size_t)B_ * H_ * N_ * 64];

// ---------------- helpers ------------------------------------------------------
__device__ __forceinline__ uint32_t smem_u32(const void* p) {
    uint32_t a;
    asm("{ .reg .u64 t; cvta.to.shared.u64 t, %1; cvt.u32.u64 %0, t; }" : "=r"(a) : "l"(p));
    return a;
}
__device__ __forceinline__ void cpa16(uint32_t dst, const void* src) {
    asm volatile("cp.async.cg.shared.global [%0], [%1], 16;" :: "r"(dst), "l"(src));
}
__device__ __forceinline__ void cpa_commit() { asm volatile("cp.async.commit_group;" ::: "memory"); }
__device__ __forceinline__ void cpa_wait1()  { asm volatile("cp.async.wait_group 1;" ::: "memory"); }
__device__ __forceinline__ void cpa_wait0()  { asm volatile("cp.async.wait_group 0;" ::: "memory"); }
__device__ __forceinline__ void ldsm_x4(uint32_t* r, uint32_t a) {
    asm volatile("ldmatrix.sync.aligned.m8n8.x4.shared.b16 {%0,%1,%2,%3}, [%4];"
        : "=r"(r[0]), "=r"(r[1]), "=r"(r[2]), "=r"(r[3]) : "r"(a));
}
__device__ __forceinline__ void ldsm_x4_t(uint32_t* r, uint32_t a) {
    asm volatile("ldmatrix.sync.aligned.m8n8.x4.trans.shared.b16 {%0,%1,%2,%3}, [%4];"
        : "=r"(r[0]), "=r"(r[1]), "=r"(r[2]), "=r"(r[3]) : "r"(a));
}
__device__ __forceinline__ void mma_f16(float* d, const uint32_t* a, const uint32_t* b) {
    asm volatile("mma.sync.aligned.m16n8k16.row.col.f32.f16.f16.f32 "
        "{%0,%1,%2,%3}, {%4,%5,%6,%7}, {%8,%9}, {%0,%1,%2,%3};"
        : "+f"(d[0]), "+f"(d[1]), "+f"(d[2]), "+f"(d[3])
        : "r"(a[0]), "r"(a[1]), "r"(a[2]), "r"(a[3]), "r"(b[0]), "r"(b[1]));
}
// silu via tanh.approx: sigmoid(x) = 0.5*tanh(x/2)+0.5  (1 MUFU vs 2)
__device__ __forceinline__ float fast_silu(float x) {
    float t;
    asm("tanh.approx.f32 %0, %1;" : "=f"(t) : "f"(x * 0.5f));
    return x * fmaf(t, 0.5f, 0.5f);
}

// ---------------- timestamp canonicalization ----------------------------------
__global__ void ts_fix_kernel(const int* __restrict__ tsraw)
{
    __shared__ int is64;
    if (threadIdx.x == 0) {
        int z = 0;
        #pragma unroll
        for (int i = 1; i < 16; i += 2) z |= tsraw[i];
        is64 = (z == 0) ? 1 : 0;
    }
    __syncthreads();
    int i = blockIdx.x * blockDim.x + threadIdx.x;
    if (i < B_ * NP1) g_ts32[i] = is64 ? tsraw[2 * i] : tsraw[i];
}

// ---------------- per-tile mask flags ------------------------------------------
__global__ void tileflag_kernel(const float* __restrict__ amask)
{
    int t = blockIdx.x;
    int ti = t >> 3, tj = t & 7;
    int any = 0;
    for (int k = threadIdx.x; k < 1024; k += 256) {
        int r = k >> 4, c = (k & 15) * 4;
        float4 v = *(const float4*)(amask + (size_t)(ti * 64 + r) * N_ + tj * 64 + c);
        any |= (v.x != 0.f) | (v.y != 0.f) | (v.z != 0.f) | (v.w != 0.f);
    }
    any = __syncthreads_or(any);
    if (threadIdx.x == 0) g_tflag[t] = any;
}

// ---------------- fused rel+mult table (shared across heads) -------------------
__global__ void relprep_kernel(const float* __restrict__ tw,
                               const float* __restrict__ pw,
                               const float* __restrict__ amask,
                               const float* __restrict__ tl)
{
    int idx = blockIdx.x * 256 + threadIdx.x;          // quad index
    int b = idx >> 16;                                 // N*N/4 = 2^16 quads per batch
    int q = idx & 0xFFFF;
    int n = q >> 7;
    int mq = (q & 127) * 4;
    int tn = g_ts32[b * NP1 + n + 1];
    float tlnv = tl[b * N_ + n];
    float4 am = *(const float4*)(amask + (size_t)n * N_ + mq);
    const float* amp = &am.x;
    uint4 pk;
    uint32_t* pp = &pk.x;
    #pragma unroll
    for (int j = 0; j < 4; j++) {
        int m = mq + j;
        int dt = tn - g_ts32[b * NP1 + m];
        float ad = fmaxf(fabsf((float)dt), 1.0f);
        int bk = min(max((int)(__logf(ad) * (1.0f / 0.301f)), 0), NB_);
        float rel = tw[bk] + pw[N_ - 1 + m - n];
        float mult = amp[j] * tl[b * N_ + m] * tlnv;
        __half2 h = __floats2half2_rn(rel, mult);
        pp[j] = *(uint32_t*)&h;
    }
    *(uint4*)(g_combo + ((size_t)(b * N_ + n)) * N_ + mq) = pk;
}

// ---------------- W transpose + fp16 -------------------------------------------
__global__ void wprep_kernel(const float* __restrict__ W,
                             __half* __restrict__ hp, int ncols)
{
    __shared__ float t[32][33];
    int n0 = blockIdx.x * 32, k0 = blockIdx.y * 32;
    int tx = threadIdx.x, ty = threadIdx.y;   // 32 x 8
    #pragma unroll
    for (int j = 0; j < 4; j++)
        t[ty + j * 8][tx] = W[(size_t)(k0 + ty + j * 8) * ncols + n0 + tx];
    __syncthreads();
    #pragma unroll
    for (int j = 0; j < 4; j++) {
        int row = ty + j * 8;
        hp[(size_t)(n0 + row) * F_ + k0 + tx] = __float2half_rn(t[tx][row]);
    }
}

// ---------------- ln1: LayerNorm -> fp16 ---------------------------------------
__global__ void ln1_kernel(const float* __restrict__ x,
                           const float* __restrict__ tl)
{
    int row = blockIdx.x;
    int tid = threadIdx.x;
    const float* xr = x + (size_t)row * F_;
    float v0 = xr[tid], v1 = xr[tid + 256];
    float s = v0 + v1, sq = v0 * v0 + v1 * v1;
    #pragma unroll
    for (int o = 16; o; o >>= 1) {
        s  += __shfl_down_sync(0xffffffffu, s,  o);
        sq += __shfl_down_sync(0xffffffffu, sq, o);
    }
    __shared__ float red[16];
    __shared__ float mean_s, rstd_s;
    int w = tid >> 5, l = tid & 31;
    if (l == 0) { red[w] = s; red[w + 8] = sq; }
    __syncthreads();
    if (tid == 0) {
        float ts = 0.f, tq = 0.f;
        #pragma unroll
        for (int i = 0; i < 8; i++) { ts += red[i]; tq += red[i + 8]; }
        float m = ts * (1.0f / F_);
        float var = tq * (1.0f / F_) - m * m;
        mean_s = m;
        rstd_s = rsqrtf(var + 1e-6f);
    }
    __syncthreads();
    float t = tl[row];
    float m = mean_s, rs = rstd_s;
    size_t o0 = (size_t)row * F_ + tid;
    g_Ah[o0]       = __float2half_rn((v0 - m) * rs * t);
    g_Ah[o0 + 256] = __float2half_rn((v1 - m) * rs * t);
}

// ---------------- ln2: o_input = u*LN(attn)*tl -> fp16 -------------------------
__global__ void ln2_kernel(const float* __restrict__ tl)
{
    int row = blockIdx.x;
    int tid = threadIdx.x;
    const __half* ar = g_attnh + (size_t)row * 512;
    float v0 = __half2float(ar[tid]);
    float v1 = __half2float(ar[tid + 256]);
    float s = v0 + v1, sq = v0 * v0 + v1 * v1;
    #pragma unroll
    for (int o = 16; o; o >>= 1) {
        s  += __shfl_down_sync(0xffffffffu, s,  o);
        sq += __shfl_down_sync(0xffffffffu, sq, o);
    }
    __shared__ float red[16];
    __shared__ float mean_s, rstd_s;
    int w = tid >> 5, l = tid & 31;
    if (l == 0) { red[w] = s; red[w + 8] = sq; }
    __syncthreads();
    if (tid == 0) {
        float ts = 0.f, tq = 0.f;
        #pragma unroll
        for (int i = 0; i < 8; i++) { ts += red[i]; tq += red[i + 8]; }
        float m = ts * (1.0f / 512.0f);
        float var = tq * (1.0f / 512.0f) - m * m;
        mean_s = m;
        rstd_s = rsqrtf(var + 1e-6f);
    }
    __syncthreads();
    float t = tl[row];
    float m = mean_s, rs = rstd_s;
    float u0 = __half2float(g_uh[(size_t)row * 512 + tid]);
    float u1 = __half2float(g_uh[(size_t)row * 512 + tid + 256]);
    size_t off = (size_t)row * 512 + tid;
    g_O2h[off]       = __float2half_rn(u0 * (v0 - m) * rs * t);
    g_O2h[off + 256] = __float2half_rn(u1 * (v1 - m) * rs * t);
}

// ---------------- GEMM via mma.sync fp16, cp.async 3-stage, 1 sync/iter --------
// per stage 20480 B: A +0, B +10240
#define GST 20480
#define GEMM_SMEM (3 * GST)

template <int MODE>
__global__ void __launch_bounds__(256)
gemm_mma(const __half* __restrict__ Ah, const __half* __restrict__ Bh,
         const float* __restrict__ tl, const float* __restrict__ bias,
         const float* __restrict__ xres, float* __restrict__ Cout)
{
    constexpr int LDS = 40;
    extern __shared__ __align__(16) char dsm[];
    const uint32_t sb = smem_u32(dsm);

    const int tid = threadIdx.x, lane = tid & 31, wid = tid >> 5;
    const int wr = wid & 3, wc = wid >> 2;
    const int m0 = blockIdx.y * 128, n0 = blockIdx.x * 128;

    float d[2][8][4] = {};

    auto load_stage = [&](int kc, int st) {
        const int k0 = kc * 32;
        const uint32_t base = sb + st * GST;
        #pragma unroll
        for (int it = 0; it < 2; it++) {
            int idx = tid + it * 256;
            int r = idx >> 2, c = (idx & 3) * 8;
            uint32_t doff = (uint32_t)(r * LDS + c) * 2;
            cpa16(base + doff,         Ah + (size_t)(m0 + r) * F_ + k0 + c);
            cpa16(base + 10240 + doff, Bh + (size_t)(n0 + r) * F_ + k0 + c);
        }
        cpa_commit();
    };

    load_stage(0, 0);
    load_stage(1, 1);

    for (int kc = 0; kc < 16; kc++) {
        if (kc + 1 < 16) cpa_wait1(); else cpa_wait0();
        __syncthreads();                 // also releases buffer (kc+2)%3 = (kc-1)%3
        if (kc + 2 < 16) load_stage(kc + 2, (kc + 2) % 3);

        const uint32_t base = sb + (kc % 3) * GST;
        #pragma unroll
        for (int ks = 0; ks < 2; ks++) {
            uint32_t a[2][4], bb[4][4];
            const int g2 = lane >> 3;     // 0..3
            #pragma unroll
            for (int mi = 0; mi < 2; mi++) {
                int row = wr * 32 + mi * 16 + (lane & 15);
                uint32_t off = (uint32_t)(row * LDS + ks * 16 + (lane >> 4) * 8) * 2;
                ldsm_x4(a[mi], base + off);
            }
            #pragma unroll
            for (int nj = 0; nj < 4; nj++) {
                int row = wc * 64 + nj * 16 + (g2 >> 1) * 8 + (lane & 7);
                int col = ks * 16 + (g2 & 1) * 8;
                ldsm_x4(bb[nj], base + 10240 + (uint32_t)(row * LDS + col) * 2);
            }
            #pragma unroll
            for (int mi = 0; mi < 2; mi++)
                #pragma unroll
                for (int nj = 0; nj < 4; nj++) {
                    mma_f16(d[mi][2 * nj + 0], a[mi], &bb[nj][0]);
                    mma_f16(d[mi][2 * nj + 1], a[mi], &bb[nj][2]);
                }
        }
    }

    #pragma unroll
    for (int mi = 0; mi < 2; mi++) {
        int rbase = m0 + wr * 32 + mi * 16 + (lane >> 2);
        #pragma unroll
        for (int half = 0; half < 2; half++) {
            int row = rbase + half * 8;
            float tlv = (MODE == 1) ? tl[row] : 0.0f;
            #pragma unroll
            for (int ni = 0; ni < 8; ni++) {
                int col = n0 + wc * 64 + ni * 8 + (lane & 3) * 2;
                float v0 = d[mi][ni][half * 2 + 0];
                float v1 = d[mi][ni][half * 2 + 1];
                if (MODE == 1) {
                    v0 = fast_silu(v0) * tlv;
                    v1 = fast_silu(v1) * tlv;
                    __half2 hp = __floats2half2_rn(v0, v1);
                    if (col < 512) {
                        *(__half2*)(g_uh + (size_t)row * 512 + col) = hp;
                    } else {
                        int hh = (col >> 6) & 7;
                        int dd = col & 63;
                        size_t off = (((size_t)(row >> 9) * H_ + hh) * N_ + (row & 511)) * 64 + dd;
                        if (col < 1024)      *(__half2*)(g_Vh + off) = hp;
                        else if (col < 1536) *(__half2*)(g_Qh + off) = hp;
                        else                 *(__half2*)(g_Kh + off) = hp;
                    }
                } else {
                    v0 += bias[col]     + xres[(size_t)row * 512 + col];
                    v1 += bias[col + 1] + xres[(size_t)row * 512 + col + 1];
                    *(float2*)(Cout + (size_t)row * 512 + col) = make_float2(v0, v1);
                }
            }
        }
    }
}

// ---------------- tensor-core attention: 128 q-rows, 3-stage KV, 1 sync/iter ---
#define DS    72
#define SQ    0
#define SKV0  18432         // per stage: K +0, V +9216; stage size 18432
#define KVST  18432
#define SP    (SKV0 + 3 * KVST)          // 73728
#define ATT_SMEM (SP + 18432)            // 92160

__global__ void __launch_bounds__(256)
attn_tc()
{
    extern __shared__ __align__(16) char sm[];
    const uint32_t sb = smem_u32(sm);
    const int tid = threadIdx.x, lane = tid & 31, w = tid >> 5;
    const int n0 = blockIdx.x * 128, h = blockIdx.y, b = blockIdx.z;
    const int bh = b * H_ + h;

    // Q -> smem (128 rows)
    #pragma unroll
    for (int it = 0; it < 4; it++) {
        int idx = tid + it * 256;
        int r = idx >> 3, c = (idx & 7) * 8;
        *(float4*)(sm + SQ + (r * DS + c) * 2) =
            *(const float4*)(g_Qh + ((size_t)bh * N_ + n0 + r) * 64 + c);
    }

    int mlist[8];
    int nact = 0;
    const int tr = n0 >> 6;
    #pragma unroll
    for (int t = 0; t < 8; t++)
        if (g_tflag[tr * 8 + t] | g_tflag[(tr + 1) * 8 + t]) mlist[nact++] = t * 64;

    auto load_kv = [&](int m0, int st) {
        const uint32_t base = sb + SKV0 + st * KVST;
        #pragma unroll
        for (int it = 0; it < 2; it++) {
            int idx = tid + it * 256;
            int r = idx >> 3, c = (idx & 7) * 8;
            uint32_t doff = (uint32_t)(r * DS + c) * 2;
            size_t src = ((size_t)bh * N_ + m0 + r) * 64 + c;
            cpa16(base + doff,        g_Kh + src);
            cpa16(base + 9216 + doff, g_Vh + src);
        }
        cpa_commit();
    };

    if (nact > 0) load_kv(mlist[0], 0);
    if (nact > 1) load_kv(mlist[1], 1);

    __syncthreads();                       // Q visible to all warps

    // hoist Q fragments (reused across all tiles)
    uint32_t qf[4][4];
    {
        int arow = w * 16 + (lane & 15);
        #pragma unroll
        for (int ks = 0; ks < 4; ks++) {
            uint32_t aoff = (uint32_t)(arow * DS + ks * 16 + (lane >> 4) * 8) * 2;
            ldsm_x4(qf[ks], sb + SQ + aoff);
        }
    }

    float o[8][4] = {};

    for (int i = 0; i < nact; i++) {
        if (i + 1 < nact) cpa_wait1(); else cpa_wait0();
        __syncthreads();                   // releases KV buffer (i+2)%3 = (i-1)%3
        if (i + 2 < nact) load_kv(mlist[i + 2], (i + 2) % 3);

        const int m0 = mlist[i];
        const uint32_t kb = sb + SKV0 + (i % 3) * KVST;
        const int g2 = lane >> 3;

        // S = Q K^T
        float s[8][4] = {};
        #pragma unroll
        for (int ks = 0; ks < 4; ks++) {
            #pragma unroll
            for (int t = 0; t < 4; t++) {
                uint32_t kk[4];
                int brow = t * 16 + (g2 >> 1) * 8 + (lane & 7);
                int bcol = ks * 16 + (g2 & 1) * 8;
                ldsm_x4(kk, kb + (uint32_t)(brow * DS + bcol) * 2);
                mma_f16(s[2 * t + 0], qf[ks], &kk[0]);
                mma_f16(s[2 * t + 1], qf[ks], &kk[2]);
            }
        }

        // epilogue: fused (rel, mult) table; P unscaled by 1/N (folded into O)
        #pragma unroll
        for (int half = 0; half < 2; half++) {
            int r = w * 16 + (lane >> 2) + half * 8;
            int n = n0 + r;
            const __half2* crow = g_combo + ((size_t)(b * N_ + n)) * N_;
            #pragma unroll
            for (int ni = 0; ni < 8; ni++) {
                int c = ni * 8 + (lane & 3) * 2;
                int m = m0 + c;
                uint2 pk = *(const uint2*)(crow + m);
                float2 f0 = __half22float2(*(__half2*)&pk.x);
                float2 f1 = __half22float2(*(__half2*)&pk.y);
                float x0 = fast_silu(s[ni][half * 2 + 0] + f0.x) * f0.y;
                float x1 = fast_silu(s[ni][half * 2 + 1] + f1.x) * f1.y;
                __half2 hp = __floats2half2_rn(x0, x1);
                *(uint32_t*)(sm + SP + (r * DS + c) * 2) = *(uint32_t*)&hp;
            }
        }
        __syncwarp();                      // P rows are warp-private

        // O += P V; V via ldmatrix.trans x4
        #pragma unroll
        for (int ks = 0; ks < 4; ks++) {
            uint32_t p[4];
            int arow = w * 16 + (lane & 15);
            uint32_t aoff = (uint32_t)(arow * DS + ks * 16 + (lane >> 4) * 8) * 2;
            ldsm_x4(p, sb + SP + aoff);
            #pragma unroll
            for (int t = 0; t < 4; t++) {
                uint32_t v[4];
                int vrow = ks * 16 + (lane & 15);
                int vcol = (2 * t + (lane >> 4)) * 8;
                ldsm_x4_t(v, kb + 9216 + (uint32_t)(vrow * DS + vcol) * 2);
                mma_f16(o[2 * t + 0], p, &v[0]);
                mma_f16(o[2 * t + 1], p, &v[2]);
            }
        }
    }

    #pragma unroll
    for (int half = 0; half < 2; half++) {
        int r = w * 16 + (lane >> 2) + half * 8;
        int n = n0 + r;
        #pragma unroll
        for (int ni = 0; ni < 8; ni++) {
            int c = ni * 8 + (lane & 3) * 2;
            __half2 hp = __floats2half2_rn(o[ni][half * 2] * (1.0f / N_),
                                           o[ni][half * 2 + 1] * (1.0f / N_));
            *(__half2*)(g_attnh + ((size_t)(b * N_ + n)) * 512 + h * 64 + c) = hp;
        }
    }
}

// ---------------- launch -------------------------------------------------------
extern "C" void kernel_launch(void* const* d_in, const int* in_sizes, int n_in,
                              void* d_out, int out_size)
{
    const float* x      = (const float*)d_in[0];
    const float* tlmask = (const float*)d_in[1];
    const float* amask  = (const float*)d_in[2];
    const float* uvqk   = (const float*)d_in[3];
    const float* out_w  = (const float*)d_in[4];
    const float* out_b  = (const float*)d_in[5];
    const float* tw     = (const float*)d_in[6];
    const float* pw     = (const float*)d_in[7];
    const int*   tsraw  = (const int*)d_in[8];
    float*       out    = (float*)d_out;

    const int rows = B_ * N_;   // 16384

    __half *wh, *w2h, *ah, *o2h;
    cudaGetSymbolAddress((void**)&wh,  g_Wh);
    cudaGetSymbolAddress((void**)&w2h, g_W2h);
    cudaGetSymbolAddress((void**)&ah,  g_Ah);
    cudaGetSymbolAddress((void**)&o2h, g_O2h);

    cudaFuncSetAttribute(gemm_mma<1>, cudaFuncAttributeMaxDynamicSharedMemorySize, GEMM_SMEM);
    cudaFuncSetAttribute(gemm_mma<2>, cudaFuncAttributeMaxDynamicSharedMemorySize, GEMM_SMEM);
    cudaFuncSetAttribute(attn_tc, cudaFuncAttributeMaxDynamicSharedMemorySize, ATT_SMEM);

    ts_fix_kernel<<<(B_ * NP1 + 255) / 256, 256>>>(tsraw);
    tileflag_kernel<<<64, 256>>>(amask);
    wprep_kernel<<<dim3(G_ / 32, F_ / 32), dim3(32, 8)>>>(uvqk, wh, G_);
    wprep_kernel<<<dim3(512 / 32, F_ / 32), dim3(32, 8)>>>(out_w, w2h, 512);
    ln1_kernel<<<rows, 256>>>(x, tlmask);

    dim3 g1(G_ / 128, rows / 128);
    gemm_mma<1><<<g1, 256, GEMM_SMEM>>>(ah, wh, tlmask, nullptr, nullptr, nullptr);

    relprep_kernel<<<B_ * N_ * N_ / 1024, 256>>>(tw, pw, amask, tlmask);

    dim3 ga(N_ / 128, H_, B_);
    attn_tc<<<ga, 256, ATT_SMEM>>>();

    ln2_kernel<<<rows, 256>>>(tlmask);

    dim3 g2(512 / 128, rows / 128);
    gemm_mma<2><<<g2, 256, GEMM_SMEM>>>(o2h, w2h, nullptr, out_b, x, out);
}